// round 4
// baseline (speedup 1.0000x reference)
#include <cuda_runtime.h>

#define S 64
#define NB 8
#define C 256
#define CR 64
#define P 4096   // S*S per plane

typedef unsigned long long u64;

__device__ __forceinline__ void ffma2(u64& d, u64 a, u64 b) {
    asm("fma.rn.f32x2 %0, %1, %2, %0;" : "+l"(d) : "l"(a), "l"(b));
}
__device__ __forceinline__ float2 unpack2(u64 v) {
    float2 f;
    asm("mov.b64 {%0, %1}, %2;" : "=f"(f.x), "=f"(f.y) : "l"(v));
    return f;
}

// ---- scratch (device globals; no runtime allocation allowed) ----
__device__ float g_red[NB * CR * P];     // 8 MB
__device__ float g_u  [NB * C  * P];     // 32 MB
__device__ float g_lam[NB * C  * P];     // 32 MB
__device__ float g_Rv [NB * P];          // 128 KB
__device__ float g_A  [NB * C  * P];     // 32 MB
__device__ float g_Bt [NB * C  * P];     // 32 MB
__device__ float g_Wfold[256 * 512];     // 512 KB

// ============================================================
// Fold merge weights: Wfold[o,k] = wm[o,k] + wm[o,k+512], k<512
// ============================================================
__global__ void k_fold(const float* __restrict__ wm) {
    int i = blockIdx.x * 256 + threadIdx.x;   // 131072 elems
    int o = i >> 9, k = i & 511;
    g_Wfold[i] = wm[o * 1024 + k] + wm[o * 1024 + k + 512];
}

// ============================================================
// K1: reduced[b,m,p] = sum_k w_red[m,k]*x[b,k,p] + b_red[m]
// M=64, K=256, N=4096/batch. Tile 64x128, BK=32, 256 thr, 4x8 micro (FFMA2).
// ============================================================
__global__ __launch_bounds__(256) void k_red(const float* __restrict__ x,
                                             const float* __restrict__ w,
                                             const float* __restrict__ bias) {
    __shared__ __align__(16) float2 As2[32][64];   // [k][m] duplicated {v,v}
    __shared__ __align__(16) float  Bs [32][128];  // [k][p]
    int b  = blockIdx.z;
    int p0 = blockIdx.x * 128;
    int tid = threadIdx.x;
    int mb = (tid >> 4) * 4;
    int nb = (tid & 15) * 8;
    u64 acc[4][4];
#pragma unroll
    for (int i = 0; i < 4; i++)
#pragma unroll
        for (int j = 0; j < 4; j++) acc[i][j] = 0ull;

    const float* xb = x + (size_t)b * C * P;
    for (int k0 = 0; k0 < 256; k0 += 32) {
#pragma unroll
        for (int l = 0; l < 2; l++) {               // 64 rows x 32 k
            int fid = tid + l * 256;
            int row = fid >> 3, kq = fid & 7;
            float4 v = *(const float4*)(w + row * 256 + k0 + kq * 4);
            As2[kq * 4 + 0][row] = make_float2(v.x, v.x);
            As2[kq * 4 + 1][row] = make_float2(v.y, v.y);
            As2[kq * 4 + 2][row] = make_float2(v.z, v.z);
            As2[kq * 4 + 3][row] = make_float2(v.w, v.w);
        }
#pragma unroll
        for (int l = 0; l < 4; l++) {               // 32 k x 128 p
            int fid = tid + l * 256;
            int kk = fid >> 5, pq = fid & 31;
            *(float4*)&Bs[kk][pq * 4] =
                *(const float4*)(xb + (size_t)(k0 + kk) * P + p0 + pq * 4);
        }
        __syncthreads();
#pragma unroll
        for (int kk = 0; kk < 32; kk++) {
            u64 aa[4];
#pragma unroll
            for (int i = 0; i < 4; i++) aa[i] = *(const u64*)&As2[kk][mb + i];
            const u64* bp = (const u64*)&Bs[kk][nb];
            u64 bb[4] = {bp[0], bp[1], bp[2], bp[3]};
#pragma unroll
            for (int i = 0; i < 4; i++)
#pragma unroll
                for (int j = 0; j < 4; j++) ffma2(acc[i][j], aa[i], bb[j]);
        }
        __syncthreads();
    }
#pragma unroll
    for (int i = 0; i < 4; i++) {
        int m = mb + i;
        float bs = bias[m];
        float* dst = g_red + ((size_t)b * CR + m) * P + p0 + nb;
        float2 f0 = unpack2(acc[i][0]), f1 = unpack2(acc[i][1]);
        float2 f2 = unpack2(acc[i][2]), f3 = unpack2(acc[i][3]);
        float4 o0 = {f0.x + bs, f0.y + bs, f1.x + bs, f1.y + bs};
        float4 o1 = {f2.x + bs, f2.y + bs, f3.x + bs, f3.y + bs};
        *(float4*)(dst)     = o0;
        *(float4*)(dst + 4) = o1;
    }
}

// ============================================================
// K2: u (rows 0..255) and lam (rows 256..511) from reduced.
// M=512, K=64, N=4096/batch. Tile 128x128, BK=16, 8x8 micro (FFMA2).
// ============================================================
__global__ __launch_bounds__(256) void k_ul(const float* __restrict__ wu,
                                            const float* __restrict__ bu,
                                            const float* __restrict__ wl,
                                            const float* __restrict__ bl) {
    __shared__ __align__(16) float2 As2[16][128];  // [k][m] duplicated
    __shared__ __align__(16) float  Bs [16][128];  // [k][p]
    int b  = blockIdx.z;
    int m0 = blockIdx.y * 128;
    int p0 = blockIdx.x * 128;
    int tid = threadIdx.x;
    int mb = (tid >> 4) * 8;
    int nb = (tid & 15) * 8;
    u64 acc[8][4];
#pragma unroll
    for (int i = 0; i < 8; i++)
#pragma unroll
        for (int j = 0; j < 4; j++) acc[i][j] = 0ull;

    const float* red = g_red + (size_t)b * CR * P;
    for (int k0 = 0; k0 < 64; k0 += 16) {
#pragma unroll
        for (int l = 0; l < 2; l++) {               // 128 rows x 16 k
            int fid = tid + l * 256;
            int row = fid >> 2, kq = fid & 3;
            int mg = m0 + row;
            const float* wrow = (mg < 256) ? (wu + mg * 64) : (wl + (mg - 256) * 64);
            float4 v = *(const float4*)(wrow + k0 + kq * 4);
            As2[kq * 4 + 0][row] = make_float2(v.x, v.x);
            As2[kq * 4 + 1][row] = make_float2(v.y, v.y);
            As2[kq * 4 + 2][row] = make_float2(v.z, v.z);
            As2[kq * 4 + 3][row] = make_float2(v.w, v.w);
        }
#pragma unroll
        for (int l = 0; l < 2; l++) {               // 16 k x 128 p
            int fid = tid + l * 256;
            int kk = fid >> 5, pq = fid & 31;
            *(float4*)&Bs[kk][pq * 4] =
                *(const float4*)(red + (size_t)(k0 + kk) * P + p0 + pq * 4);
        }
        __syncthreads();
#pragma unroll
        for (int kk = 0; kk < 16; kk++) {
            u64 aa[8];
#pragma unroll
            for (int i = 0; i < 8; i++) aa[i] = *(const u64*)&As2[kk][mb + i];
            const u64* bp = (const u64*)&Bs[kk][nb];
            u64 bb[4] = {bp[0], bp[1], bp[2], bp[3]};
#pragma unroll
            for (int i = 0; i < 8; i++)
#pragma unroll
                for (int j = 0; j < 4; j++) ffma2(acc[i][j], aa[i], bb[j]);
        }
        __syncthreads();
    }
#pragma unroll
    for (int i = 0; i < 8; i++) {
        int mg = m0 + mb + i;
        float bs;
        float* dst;
        if (mg < 256) { bs = bu[mg];       dst = g_u   + ((size_t)b * C + mg)       * P; }
        else          { bs = bl[mg - 256]; dst = g_lam + ((size_t)b * C + mg - 256) * P; }
        dst += p0 + nb;
        float2 f0 = unpack2(acc[i][0]), f1 = unpack2(acc[i][1]);
        float2 f2 = unpack2(acc[i][2]), f3 = unpack2(acc[i][3]);
        float4 o0 = {f0.x + bs, f0.y + bs, f1.x + bs, f1.y + bs};
        float4 o1 = {f2.x + bs, f2.y + bs, f3.x + bs, f3.y + bs};
        *(float4*)(dst)     = o0;
        *(float4*)(dst + 4) = o1;
    }
}

// ============================================================
// K3: pre (3ch) from reduced, sigmoid, normalize, band-validity sum.
// Rv[b,h,w] = (s1 + (w>=1)s0 + (w<=S-2)s2) / max(s0+s1+s2, 1e-6)
// 128-thread CTAs x 256 for latency hiding.
// ============================================================
__global__ __launch_bounds__(128) void k_rv(const float* __restrict__ wwt,
                                            const float* __restrict__ bwt) {
    __shared__ float ws[192];
    __shared__ float bs[3];
    int tid = threadIdx.x;
    for (int i = tid; i < 192; i += 128) ws[i] = wwt[i];
    if (tid < 3) bs[tid] = bwt[tid];
    __syncthreads();
    int gid = blockIdx.x * 128 + tid;       // 32768 pixels
    int b = gid >> 12, p = gid & 4095, w = p & 63;
    const float* red = g_red + (size_t)b * CR * P + p;
    float a0 = bs[0], a1 = bs[1], a2 = bs[2];
#pragma unroll 16
    for (int c = 0; c < 64; c++) {
        float r = __ldg(red + (size_t)c * P);
        a0 += ws[c]       * r;
        a1 += ws[64 + c]  * r;
        a2 += ws[128 + c] * r;
    }
    float s0 = 1.f / (1.f + expf(-a0));
    float s1 = 1.f / (1.f + expf(-a1));
    float s2 = 1.f / (1.f + expf(-a2));
    float den = fmaxf(s0 + s1 + s2, 1e-6f);
    float rv = s1;
    if (w >= 1)     rv += s0;
    if (w <= S - 2) rv += s2;
    g_Rv[gid] = rv / den;
}

// ============================================================
// K4: fused dual linear-recurrence scan along w (warp-parallel).
// One block per (b,c) plane. 16 warps, each scans 4 rows (h).
//   A: h_w = h*Rv[b,h,w] + lam[b,c,w,h]*x       ; out A = h*u[b,c,h,w]
//   B: h_w = h*Rv[b,h,w] + lam[b,c,63-w,63-h]*x ; out B = h*u[b,c,63-h,w]
// ============================================================
__global__ __launch_bounds__(512) void k_scan(const float* __restrict__ x) {
    __shared__ float ls[64 * 65];
    int b = blockIdx.y, c = blockIdx.x;
    size_t base = ((size_t)b * C + c) * P;
    const float* xp = x + base;
    const float* up = g_u + base;
    const float* lp = g_lam + base;
    const float* rv = g_Rv + (size_t)b * P;
    float* Ap = g_A + base;
    float* Bp = g_Bt + base;
    int tid = threadIdx.x;

#pragma unroll
    for (int l = 0; l < 2; l++) {           // 1024 float4s of lam plane
        int fid = tid + l * 512;
        int row = fid >> 4, q = fid & 15;
        float4 v = *(const float4*)(lp + row * 64 + q * 4);
        ls[row * 65 + q * 4 + 0] = v.x;
        ls[row * 65 + q * 4 + 1] = v.y;
        ls[row * 65 + q * 4 + 2] = v.z;
        ls[row * 65 + q * 4 + 3] = v.w;
    }
    __syncthreads();

    int wid = tid >> 5, lane = tid & 31;
#pragma unroll
    for (int r = 0; r < 4; r++) {
        int h = wid + r * 16;
        int hb = 63 - h;
        int w0 = lane * 2, w1 = w0 + 1;
        float2 av = *(const float2*)(rv + h * 64 + w0);
        float a0 = av.x, a1 = av.y;
        float2 xv = *(const float2*)(xp + h * 64 + w0);
        float bA0 = ls[w0 * 65 + h] * xv.x;
        float bA1 = ls[w1 * 65 + h] * xv.y;
        float bB0 = ls[(63 - w0) * 65 + hb] * xv.x;
        float bB1 = ls[(63 - w1) * 65 + hb] * xv.y;
        float ca  = a0 * a1;
        float cbA = a1 * bA0 + bA1;
        float cbB = a1 * bB0 + bB1;
#pragma unroll
        for (int d = 1; d < 32; d <<= 1) {
            float pa  = __shfl_up_sync(0xffffffffu, ca,  d);
            float pbA = __shfl_up_sync(0xffffffffu, cbA, d);
            float pbB = __shfl_up_sync(0xffffffffu, cbB, d);
            if (lane >= d) {
                cbA = ca * pbA + cbA;
                cbB = ca * pbB + cbB;
                ca  = ca * pa;
            }
        }
        float eA = __shfl_up_sync(0xffffffffu, cbA, 1);
        float eB = __shfl_up_sync(0xffffffffu, cbB, 1);
        if (lane == 0) { eA = 0.f; eB = 0.f; }
        float hA0 = a0 * eA + bA0;
        float hA1 = a1 * hA0 + bA1;
        float hB0 = a0 * eB + bB0;
        float hB1 = a1 * hB0 + bB1;
        float2 uv  = *(const float2*)(up + h  * 64 + w0);
        float2 uvb = *(const float2*)(up + hb * 64 + w0);
        float2 oA = {hA0 * uv.x,  hA1 * uv.y};
        float2 oB = {hB0 * uvb.x, hB1 * uvb.y};
        *(float2*)(Ap + h * 64 + w0) = oA;
        *(float2*)(Bp + h * 64 + w0) = oB;
    }
}

// ============================================================
// K5: out[b,o,p] = sum_{k<512} Wfold[o,k]*Kmat[b,k,p] + b_merge[o]
// M=256, K=512, N=4096/batch. Tile 128x128, BK=16, 8x8 micro (FFMA2).
// ============================================================
__global__ __launch_bounds__(256) void k_merge(float* __restrict__ out,
                                               const float* __restrict__ bm) {
    __shared__ __align__(16) float2 As2[16][128];  // [k][m] duplicated
    __shared__ __align__(16) float  Bs [16][128];  // [k][p]
    int b  = blockIdx.z;
    int m0 = blockIdx.y * 128;
    int p0 = blockIdx.x * 128;
    int tid = threadIdx.x;
    int mb = (tid >> 4) * 8;
    int nb = (tid & 15) * 8;
    u64 acc[8][4];
#pragma unroll
    for (int i = 0; i < 8; i++)
#pragma unroll
        for (int j = 0; j < 4; j++) acc[i][j] = 0ull;

    const float* Ab = g_A  + (size_t)b * C * P;
    const float* Bb = g_Bt + (size_t)b * C * P;
    for (int k0 = 0; k0 < 512; k0 += 16) {
#pragma unroll
        for (int l = 0; l < 2; l++) {               // 128 rows x 16 k
            int fid = tid + l * 256;
            int row = fid >> 2, kq = fid & 3;
            float4 v = *(const float4*)(g_Wfold + (size_t)(m0 + row) * 512 + k0 + kq * 4);
            As2[kq * 4 + 0][row] = make_float2(v.x, v.x);
            As2[kq * 4 + 1][row] = make_float2(v.y, v.y);
            As2[kq * 4 + 2][row] = make_float2(v.z, v.z);
            As2[kq * 4 + 3][row] = make_float2(v.w, v.w);
        }
#pragma unroll
        for (int l = 0; l < 2; l++) {               // 16 k x 128 p
            int fid = tid + l * 256;
            int kk = fid >> 5, pq = fid & 31;
            int kg = k0 + kk;
            const float* src = (kg < 256) ? (Ab + (size_t)kg * P)
                                          : (Bb + (size_t)(kg - 256) * P);
            *(float4*)&Bs[kk][pq * 4] = *(const float4*)(src + p0 + pq * 4);
        }
        __syncthreads();
#pragma unroll
        for (int kk = 0; kk < 16; kk++) {
            u64 aa[8];
#pragma unroll
            for (int i = 0; i < 8; i++) aa[i] = *(const u64*)&As2[kk][mb + i];
            const u64* bp = (const u64*)&Bs[kk][nb];
            u64 bb[4] = {bp[0], bp[1], bp[2], bp[3]};
#pragma unroll
            for (int i = 0; i < 8; i++)
#pragma unroll
                for (int j = 0; j < 4; j++) ffma2(acc[i][j], aa[i], bb[j]);
        }
        __syncthreads();
    }
#pragma unroll
    for (int i = 0; i < 8; i++) {
        int o = m0 + mb + i;
        float bs = bm[o];
        float* dst = out + ((size_t)b * C + o) * P + p0 + nb;
        float2 f0 = unpack2(acc[i][0]), f1 = unpack2(acc[i][1]);
        float2 f2 = unpack2(acc[i][2]), f3 = unpack2(acc[i][3]);
        float4 o0 = {f0.x + bs, f0.y + bs, f1.x + bs, f1.y + bs};
        float4 o1 = {f2.x + bs, f2.y + bs, f3.x + bs, f3.y + bs};
        *(float4*)(dst)     = o0;
        *(float4*)(dst + 4) = o1;
    }
}

// ============================================================
extern "C" void kernel_launch(void* const* d_in, const int* in_sizes, int n_in,
                              void* d_out, int out_size) {
    const float* x       = (const float*)d_in[0];
    const float* w_red   = (const float*)d_in[1];
    const float* b_red   = (const float*)d_in[2];
    const float* w_u     = (const float*)d_in[3];
    const float* b_u     = (const float*)d_in[4];
    const float* w_lam   = (const float*)d_in[5];
    const float* b_lam   = (const float*)d_in[6];
    const float* w_wt    = (const float*)d_in[7];
    const float* b_wt    = (const float*)d_in[8];
    const float* w_merge = (const float*)d_in[9];
    const float* b_merge = (const float*)d_in[10];
    float* out = (float*)d_out;

    k_fold<<<512, 256>>>(w_merge);
    k_red <<<dim3(32, 1, NB), 256>>>(x, w_red, b_red);
    k_ul  <<<dim3(32, 4, NB), 256>>>(w_u, b_u, w_lam, b_lam);
    k_rv  <<<256, 128>>>(w_wt, b_wt);
    k_scan<<<dim3(256, NB), 512>>>(x);
    k_merge<<<dim3(32, 2, NB), 256>>>(out, b_merge);
}

// round 5
// speedup vs baseline: 1.7680x; 1.7680x over previous
#include <cuda_runtime.h>
#include <cuda_bf16.h>

#define S 64
#define NB 8
#define C 256
#define CR 64
#define P 4096   // S*S per plane

typedef unsigned int u32;

// ---- scratch (device globals; no runtime allocation allowed) ----
__device__ float g_red[NB * CR * P];                 // 8 MB fp32 (for k_rv)
__device__ __nv_bfloat16 g_red_hi[NB * CR * P];      // 4 MB
__device__ __nv_bfloat16 g_red_lo[NB * CR * P];      // 4 MB
__device__ float g_u  [NB * C * P];                  // 32 MB
__device__ float g_lam[NB * C * P];                  // 32 MB
__device__ float g_Rv [NB * P];                      // 128 KB
__device__ __nv_bfloat16 g_Khi[NB * 512 * P];        // 32 MB (planes 0..255 = A, 256..511 = B)
__device__ __nv_bfloat16 g_Klo[NB * 512 * P];        // 32 MB
__device__ __nv_bfloat16 g_Wf [256 * 1536];          // merge A': [Whi | Wlo | Whi]
__device__ __nv_bfloat16 g_Wul[512 * 192];           // ul    A': [Whi | Wlo | Whi]

// ---- helpers ----
__device__ __forceinline__ u32 sptr(const void* p) {
    return (u32)__cvta_generic_to_shared(p);
}
__device__ __forceinline__ void ldm_x4(u32* r, u32 addr) {
    asm volatile("ldmatrix.sync.aligned.m8n8.x4.shared.b16 {%0,%1,%2,%3}, [%4];"
                 : "=r"(r[0]), "=r"(r[1]), "=r"(r[2]), "=r"(r[3]) : "r"(addr));
}
__device__ __forceinline__ void ldm_x4_t(u32* r, u32 addr) {
    asm volatile("ldmatrix.sync.aligned.m8n8.x4.trans.shared.b16 {%0,%1,%2,%3}, [%4];"
                 : "=r"(r[0]), "=r"(r[1]), "=r"(r[2]), "=r"(r[3]) : "r"(addr));
}
__device__ __forceinline__ void mma16816(float* d, const u32* a, u32 b0, u32 b1) {
    asm volatile("mma.sync.aligned.m16n8k16.row.col.f32.bf16.bf16.f32 "
                 "{%0,%1,%2,%3}, {%4,%5,%6,%7}, {%8,%9}, {%0,%1,%2,%3};"
                 : "+f"(d[0]), "+f"(d[1]), "+f"(d[2]), "+f"(d[3])
                 : "r"(a[0]), "r"(a[1]), "r"(a[2]), "r"(a[3]), "r"(b0), "r"(b1));
}
__device__ __forceinline__ void split_bf(float v, __nv_bfloat16& hi, __nv_bfloat16& lo) {
    hi = __float2bfloat16(v);
    lo = __float2bfloat16(v - __bfloat162float(hi));
}

// ============================================================
// Prep: fold merge weights + bf16-split both weight matrices.
//  g_Wf [256][1536] = [ hi(wm[:, :512]+wm[:, 512:]) | lo(...) | hi(...) ]
//  g_Wul[512][192]  = rows: [wu; wl] split the same way (K=64)
// ============================================================
__global__ void k_prep(const float* __restrict__ wm,
                       const float* __restrict__ wu,
                       const float* __restrict__ wl) {
    int i = blockIdx.x * 256 + threadIdx.x;   // 131072 + 32768
    if (i < 131072) {
        int o = i >> 9, k = i & 511;
        float v = wm[o * 1024 + k] + wm[o * 1024 + k + 512];
        __nv_bfloat16 hi, lo; split_bf(v, hi, lo);
        g_Wf[o * 1536 + k]        = hi;
        g_Wf[o * 1536 + 512 + k]  = lo;
        g_Wf[o * 1536 + 1024 + k] = hi;
    } else if (i < 163840) {
        int j = i - 131072;
        int m = j >> 6, k = j & 63;
        float v = (m < 256) ? wu[m * 64 + k] : wl[(m - 256) * 64 + k];
        __nv_bfloat16 hi, lo; split_bf(v, hi, lo);
        g_Wul[m * 192 + k]       = hi;
        g_Wul[m * 192 + 64 + k]  = lo;
        g_Wul[m * 192 + 128 + k] = hi;
    }
}

// ============================================================
// K1: reduced[b,m,p] = sum_k w_red[m,k]*x[b,k,p] + b_red[m]  (scalar fp32)
// Also emits bf16 hi/lo copies for the tensor-core u/lam GEMM.
// ============================================================
__global__ __launch_bounds__(256) void k_red(const float* __restrict__ x,
                                             const float* __restrict__ w,
                                             const float* __restrict__ bias) {
    __shared__ float As[32][64];    // [k][m]
    __shared__ float Bs[32][128];   // [k][p]
    int b  = blockIdx.z;
    int p0 = blockIdx.x * 128;
    int tid = threadIdx.x;
    int mb = (tid >> 4) * 4;
    int nb = (tid & 15) * 8;
    float acc[4][8];
#pragma unroll
    for (int i = 0; i < 4; i++)
#pragma unroll
        for (int j = 0; j < 8; j++) acc[i][j] = 0.f;

    const float* xb = x + (size_t)b * C * P;
    for (int k0 = 0; k0 < 256; k0 += 32) {
#pragma unroll
        for (int l = 0; l < 2; l++) {
            int fid = tid + l * 256;
            int row = fid >> 3, kq = fid & 7;
            float4 v = *(const float4*)(w + row * 256 + k0 + kq * 4);
            As[kq * 4 + 0][row] = v.x; As[kq * 4 + 1][row] = v.y;
            As[kq * 4 + 2][row] = v.z; As[kq * 4 + 3][row] = v.w;
        }
#pragma unroll
        for (int l = 0; l < 4; l++) {
            int fid = tid + l * 256;
            int kk = fid >> 5, pq = fid & 31;
            *(float4*)&Bs[kk][pq * 4] =
                *(const float4*)(xb + (size_t)(k0 + kk) * P + p0 + pq * 4);
        }
        __syncthreads();
#pragma unroll
        for (int kk = 0; kk < 32; kk++) {
            float4 a  = *(float4*)&As[kk][mb];
            float4 b0 = *(float4*)&Bs[kk][nb];
            float4 b1 = *(float4*)&Bs[kk][nb + 4];
            float av[4] = {a.x, a.y, a.z, a.w};
            float bv[8] = {b0.x, b0.y, b0.z, b0.w, b1.x, b1.y, b1.z, b1.w};
#pragma unroll
            for (int i = 0; i < 4; i++)
#pragma unroll
                for (int j = 0; j < 8; j++) acc[i][j] += av[i] * bv[j];
        }
        __syncthreads();
    }
#pragma unroll
    for (int i = 0; i < 4; i++) {
        int m = mb + i;
        float bs = bias[m];
        size_t off = ((size_t)b * CR + m) * P + p0 + nb;
        float v[8];
#pragma unroll
        for (int j = 0; j < 8; j++) v[j] = acc[i][j] + bs;
        *(float4*)(g_red + off)     = make_float4(v[0], v[1], v[2], v[3]);
        *(float4*)(g_red + off + 4) = make_float4(v[4], v[5], v[6], v[7]);
#pragma unroll
        for (int j = 0; j < 8; j += 2) {
            __nv_bfloat16 h0, l0, h1, l1;
            split_bf(v[j], h0, l0); split_bf(v[j + 1], h1, l1);
            __nv_bfloat162 hh; hh.x = h0; hh.y = h1;
            __nv_bfloat162 ll; ll.x = l0; ll.y = l1;
            *(__nv_bfloat162*)(g_red_hi + off + j) = hh;
            *(__nv_bfloat162*)(g_red_lo + off + j) = ll;
        }
    }
}

// ============================================================
// K2 (tensor): u (m<256) and lam (m>=256) via bf16-split MMA.
// D[512, 32768] = Wul'[512, 192] @ Red'[192, 32768]
// CTA tile 128x128, BK=32, 8 warps @ 64x32.
// ============================================================
__global__ __launch_bounds__(256) void k_ul_mma(const float* __restrict__ bu,
                                                const float* __restrict__ bl) {
    __shared__ __align__(16) __nv_bfloat16 As[128 * 40];   // stride 40
    __shared__ __align__(16) __nv_bfloat16 Bs[32 * 136];   // stride 136
    int b  = blockIdx.z;
    int m0 = blockIdx.y * 128;
    int p0 = blockIdx.x * 128;
    int tid = threadIdx.x;
    int wid = tid >> 5, lane = tid & 31;
    int wm = wid >> 2, wn = wid & 3;       // 2 x 4 warps -> 64 x 32 each
    float acc[4][4][4];
#pragma unroll
    for (int i = 0; i < 4; i++)
#pragma unroll
        for (int j = 0; j < 4; j++)
#pragma unroll
            for (int q = 0; q < 4; q++) acc[i][j][q] = 0.f;

    for (int k0 = 0; k0 < 192; k0 += 32) {
        int region = k0 >> 6;              // 0:hi 1:lo(A)/hi(B) 2:hi(A)/lo(B)
        const __nv_bfloat16* arr = (region == 2) ? g_red_lo : g_red_hi;
        const __nv_bfloat16* bsrc = arr + ((size_t)b * CR + (k0 & 63)) * P + p0;
#pragma unroll
        for (int l = 0; l < 2; l++) {      // A: 128 rows x 32 k
            int cid = tid + l * 256;
            int row = cid >> 2, q = cid & 3;
            uint4 v = *(const uint4*)(g_Wul + (size_t)(m0 + row) * 192 + k0 + q * 8);
            *(uint4*)&As[row * 40 + q * 8] = v;
        }
#pragma unroll
        for (int l = 0; l < 2; l++) {      // B: 32 k x 128 p
            int cid = tid + l * 256;
            int kk = cid >> 4, q = cid & 15;
            uint4 v = *(const uint4*)(bsrc + (size_t)kk * P + q * 8);
            *(uint4*)&Bs[kk * 136 + q * 8] = v;
        }
        __syncthreads();
#pragma unroll
        for (int ks = 0; ks < 2; ks++) {
            int kk = ks * 16;
            u32 a[4][4], bf[2][4];
#pragma unroll
            for (int mf = 0; mf < 4; mf++)
                ldm_x4(a[mf], sptr(&As[(wm * 64 + mf * 16 + (lane & 15)) * 40
                                        + kk + (lane >> 4) * 8]));
#pragma unroll
            for (int nh = 0; nh < 2; nh++)
                ldm_x4_t(bf[nh], sptr(&Bs[(kk + (lane & 15)) * 136
                                          + wn * 32 + nh * 16 + (lane >> 4) * 8]));
#pragma unroll
            for (int mf = 0; mf < 4; mf++)
#pragma unroll
                for (int nf = 0; nf < 4; nf++)
                    mma16816(acc[mf][nf], a[mf], bf[nf >> 1][(nf & 1) * 2],
                             bf[nf >> 1][(nf & 1) * 2 + 1]);
        }
        __syncthreads();
    }
    // epilogue: whole CTA is either u (m0<256) or lam
    float* outb; const float* biasArr; int mofs;
    if (m0 < 256) { outb = g_u   + (size_t)b * C * P; biasArr = bu; mofs = m0; }
    else          { outb = g_lam + (size_t)b * C * P; biasArr = bl; mofs = m0 - 256; }
    int g = lane >> 2, tg = lane & 3;
#pragma unroll
    for (int mf = 0; mf < 4; mf++) {
        int m1 = mofs + wm * 64 + mf * 16 + g;
#pragma unroll
        for (int nf = 0; nf < 4; nf++) {
            int p = p0 + wn * 32 + nf * 8 + tg * 2;
            float bs1 = biasArr[m1], bs2 = biasArr[m1 + 8];
            float2 o0 = {acc[mf][nf][0] + bs1, acc[mf][nf][1] + bs1};
            float2 o1 = {acc[mf][nf][2] + bs2, acc[mf][nf][3] + bs2};
            *(float2*)(outb + (size_t)m1 * P + p)       = o0;
            *(float2*)(outb + (size_t)(m1 + 8) * P + p) = o1;
        }
    }
}

// ============================================================
// K3: Rv from reduced (fp32), sigmoid+normalize+band-validity.
// ============================================================
__global__ __launch_bounds__(128) void k_rv(const float* __restrict__ wwt,
                                            const float* __restrict__ bwt) {
    __shared__ float ws[192];
    __shared__ float bs[3];
    int tid = threadIdx.x;
    for (int i = tid; i < 192; i += 128) ws[i] = wwt[i];
    if (tid < 3) bs[tid] = bwt[tid];
    __syncthreads();
    int gid = blockIdx.x * 128 + tid;       // 32768 pixels
    int b = gid >> 12, p = gid & 4095, w = p & 63;
    const float* red = g_red + (size_t)b * CR * P + p;
    float a0 = bs[0], a1 = bs[1], a2 = bs[2];
#pragma unroll 16
    for (int c = 0; c < 64; c++) {
        float r = __ldg(red + (size_t)c * P);
        a0 += ws[c]       * r;
        a1 += ws[64 + c]  * r;
        a2 += ws[128 + c] * r;
    }
    float s0 = 1.f / (1.f + expf(-a0));
    float s1 = 1.f / (1.f + expf(-a1));
    float s2 = 1.f / (1.f + expf(-a2));
    float den = fmaxf(s0 + s1 + s2, 1e-6f);
    float rv = s1;
    if (w >= 1)     rv += s0;
    if (w <= S - 2) rv += s2;
    g_Rv[gid] = rv / den;
}

// ============================================================
// K4: fused dual scan along w; outputs bf16 hi/lo planes of
// Kmat rows: plane c = A-direction, plane 256+c = B-direction.
// ============================================================
__global__ __launch_bounds__(512) void k_scan(const float* __restrict__ x) {
    __shared__ float ls[64 * 65];
    int b = blockIdx.y, c = blockIdx.x;
    size_t base = ((size_t)b * C + c) * P;
    const float* xp = x + base;
    const float* up = g_u + base;
    const float* lp = g_lam + base;
    const float* rv = g_Rv + (size_t)b * P;
    __nv_bfloat16* AhiP = g_Khi + ((size_t)b * 512 + c) * P;
    __nv_bfloat16* AloP = g_Klo + ((size_t)b * 512 + c) * P;
    __nv_bfloat16* BhiP = g_Khi + ((size_t)b * 512 + 256 + c) * P;
    __nv_bfloat16* BloP = g_Klo + ((size_t)b * 512 + 256 + c) * P;
    int tid = threadIdx.x;

#pragma unroll
    for (int l = 0; l < 2; l++) {
        int fid = tid + l * 512;
        int row = fid >> 4, q = fid & 15;
        float4 v = *(const float4*)(lp + row * 64 + q * 4);
        ls[row * 65 + q * 4 + 0] = v.x;
        ls[row * 65 + q * 4 + 1] = v.y;
        ls[row * 65 + q * 4 + 2] = v.z;
        ls[row * 65 + q * 4 + 3] = v.w;
    }
    __syncthreads();

    int wid = tid >> 5, lane = tid & 31;
#pragma unroll
    for (int r = 0; r < 4; r++) {
        int h = wid + r * 16;
        int hb = 63 - h;
        int w0 = lane * 2, w1 = w0 + 1;
        float2 av = *(const float2*)(rv + h * 64 + w0);
        float a0 = av.x, a1 = av.y;
        float2 xv = *(const float2*)(xp + h * 64 + w0);
        float bA0 = ls[w0 * 65 + h] * xv.x;
        float bA1 = ls[w1 * 65 + h] * xv.y;
        float bB0 = ls[(63 - w0) * 65 + hb] * xv.x;
        float bB1 = ls[(63 - w1) * 65 + hb] * xv.y;
        float ca  = a0 * a1;
        float cbA = a1 * bA0 + bA1;
        float cbB = a1 * bB0 + bB1;
#pragma unroll
        for (int d = 1; d < 32; d <<= 1) {
            float pa  = __shfl_up_sync(0xffffffffu, ca,  d);
            float pbA = __shfl_up_sync(0xffffffffu, cbA, d);
            float pbB = __shfl_up_sync(0xffffffffu, cbB, d);
            if (lane >= d) {
                cbA = ca * pbA + cbA;
                cbB = ca * pbB + cbB;
                ca  = ca * pa;
            }
        }
        float eA = __shfl_up_sync(0xffffffffu, cbA, 1);
        float eB = __shfl_up_sync(0xffffffffu, cbB, 1);
        if (lane == 0) { eA = 0.f; eB = 0.f; }
        float hA0 = a0 * eA + bA0;
        float hA1 = a1 * hA0 + bA1;
        float hB0 = a0 * eB + bB0;
        float hB1 = a1 * hB0 + bB1;
        float2 uv  = *(const float2*)(up + h  * 64 + w0);
        float2 uvb = *(const float2*)(up + hb * 64 + w0);
        float oA0 = hA0 * uv.x,  oA1 = hA1 * uv.y;
        float oB0 = hB0 * uvb.x, oB1 = hB1 * uvb.y;
        __nv_bfloat16 h0, l0, h1, l1;
        __nv_bfloat162 hh, ll;
        split_bf(oA0, h0, l0); split_bf(oA1, h1, l1);
        hh.x = h0; hh.y = h1; ll.x = l0; ll.y = l1;
        *(__nv_bfloat162*)(AhiP + h * 64 + w0) = hh;
        *(__nv_bfloat162*)(AloP + h * 64 + w0) = ll;
        split_bf(oB0, h0, l0); split_bf(oB1, h1, l1);
        hh.x = h0; hh.y = h1; ll.x = l0; ll.y = l1;
        *(__nv_bfloat162*)(BhiP + h * 64 + w0) = hh;
        *(__nv_bfloat162*)(BloP + h * 64 + w0) = ll;
    }
}

// ============================================================
// K5 (tensor): out[256, 32768] = Wf'[256, 1536] @ Kmat'[1536, 32768] + bias
// CTA tile 128x128, BK=32, 8 warps @ 64x32, bf16-split accumulation.
// ============================================================
__global__ __launch_bounds__(256) void k_merge_mma(float* __restrict__ out,
                                                   const float* __restrict__ bm) {
    __shared__ __align__(16) __nv_bfloat16 As[128 * 40];
    __shared__ __align__(16) __nv_bfloat16 Bs[32 * 136];
    int b  = blockIdx.z;
    int m0 = blockIdx.y * 128;
    int p0 = blockIdx.x * 128;
    int tid = threadIdx.x;
    int wid = tid >> 5, lane = tid & 31;
    int wm = wid >> 2, wn = wid & 3;
    float acc[4][4][4];
#pragma unroll
    for (int i = 0; i < 4; i++)
#pragma unroll
        for (int j = 0; j < 4; j++)
#pragma unroll
            for (int q = 0; q < 4; q++) acc[i][j][q] = 0.f;

    for (int k0 = 0; k0 < 1536; k0 += 32) {
        const __nv_bfloat16* arr = (k0 < 1024) ? g_Khi : g_Klo;
        const __nv_bfloat16* bsrc = arr + ((size_t)b * 512 + (k0 & 511)) * P + p0;
#pragma unroll
        for (int l = 0; l < 2; l++) {
            int cid = tid + l * 256;
            int row = cid >> 2, q = cid & 3;
            uint4 v = *(const uint4*)(g_Wf + (size_t)(m0 + row) * 1536 + k0 + q * 8);
            *(uint4*)&As[row * 40 + q * 8] = v;
        }
#pragma unroll
        for (int l = 0; l < 2; l++) {
            int cid = tid + l * 256;
            int kk = cid >> 4, q = cid & 15;
            uint4 v = *(const uint4*)(bsrc + (size_t)kk * P + q * 8);
            *(uint4*)&Bs[kk * 136 + q * 8] = v;
        }
        __syncthreads();
#pragma unroll
        for (int ks = 0; ks < 2; ks++) {
            int kk = ks * 16;
            u32 a[4][4], bf[2][4];
#pragma unroll
            for (int mf = 0; mf < 4; mf++)
                ldm_x4(a[mf], sptr(&As[(wm * 64 + mf * 16 + (lane & 15)) * 40
                                        + kk + (lane >> 4) * 8]));
#pragma unroll
            for (int nh = 0; nh < 2; nh++)
                ldm_x4_t(bf[nh], sptr(&Bs[(kk + (lane & 15)) * 136
                                          + wn * 32 + nh * 16 + (lane >> 4) * 8]));
#pragma unroll
            for (int mf = 0; mf < 4; mf++)
#pragma unroll
                for (int nf = 0; nf < 4; nf++)
                    mma16816(acc[mf][nf], a[mf], bf[nf >> 1][(nf & 1) * 2],
                             bf[nf >> 1][(nf & 1) * 2 + 1]);
        }
        __syncthreads();
    }
    int g = lane >> 2, tg = lane & 3;
#pragma unroll
    for (int mf = 0; mf < 4; mf++) {
        int m1 = m0 + wm * 64 + mf * 16 + g;
#pragma unroll
        for (int nf = 0; nf < 4; nf++) {
            int p = p0 + wn * 32 + nf * 8 + tg * 2;
            float bs1 = bm[m1], bs2 = bm[m1 + 8];
            float2 o0 = {acc[mf][nf][0] + bs1, acc[mf][nf][1] + bs1};
            float2 o1 = {acc[mf][nf][2] + bs2, acc[mf][nf][3] + bs2};
            *(float2*)(out + ((size_t)b * C + m1) * P + p)       = o0;
            *(float2*)(out + ((size_t)b * C + m1 + 8) * P + p)   = o1;
        }
    }
}

// ============================================================
extern "C" void kernel_launch(void* const* d_in, const int* in_sizes, int n_in,
                              void* d_out, int out_size) {
    const float* x       = (const float*)d_in[0];
    const float* w_red   = (const float*)d_in[1];
    const float* b_red   = (const float*)d_in[2];
    const float* w_u     = (const float*)d_in[3];
    const float* b_u     = (const float*)d_in[4];
    const float* w_lam   = (const float*)d_in[5];
    const float* b_lam   = (const float*)d_in[6];
    const float* w_wt    = (const float*)d_in[7];
    const float* b_wt    = (const float*)d_in[8];
    const float* w_merge = (const float*)d_in[9];
    const float* b_merge = (const float*)d_in[10];
    float* out = (float*)d_out;

    k_prep<<<640, 256>>>(w_merge, w_u, w_lam);
    k_red <<<dim3(32, 1, NB), 256>>>(x, w_red, b_red);
    k_ul_mma<<<dim3(32, 4, NB), 256>>>(b_u, b_lam);
    k_rv  <<<256, 128>>>(w_wt, b_wt);
    k_scan<<<dim3(256, NB), 512>>>(x);
    k_merge_mma<<<dim3(32, 2, NB), 256>>>(out, b_merge);
}

// round 6
// speedup vs baseline: 2.4556x; 1.3889x over previous
#include <cuda_runtime.h>
#include <cuda_bf16.h>

#define S 64
#define NB 8
#define C 256
#define CR 64
#define P 4096   // S*S per plane

typedef unsigned int u32;

// ---- scratch (device globals; no runtime allocation allowed) ----
__device__ __nv_bfloat16 g_red_hi[NB * CR * P];      // 4 MB
__device__ __nv_bfloat16 g_red_lo[NB * CR * P];      // 4 MB
__device__ float g_u  [NB * C * P];                  // 32 MB
__device__ float g_lam[NB * C * P];                  // 32 MB
__device__ float g_Rv [NB * P];                      // 128 KB
__device__ __nv_bfloat16 g_Khi[NB * 512 * P];        // 32 MB (0..255 = A dir, 256..511 = B dir)
__device__ __nv_bfloat16 g_Klo[NB * 512 * P];        // 32 MB
__device__ __nv_bfloat16 g_Wf  [256 * 1024];         // merge W: row = [hi(512) | lo(512)]
__device__ __nv_bfloat16 g_Wul [512 * 128];          // u/lam W: row = [hi(64) | lo(64)]
__device__ __nv_bfloat16 g_Wred[64 * 512];           // red  W: row = [hi(256) | lo(256)]

// ---- helpers ----
__device__ __forceinline__ u32 sptr(const void* p) {
    return (u32)__cvta_generic_to_shared(p);
}
__device__ __forceinline__ void ldm_x4(u32* r, u32 addr) {
    asm volatile("ldmatrix.sync.aligned.m8n8.x4.shared.b16 {%0,%1,%2,%3}, [%4];"
                 : "=r"(r[0]), "=r"(r[1]), "=r"(r[2]), "=r"(r[3]) : "r"(addr));
}
__device__ __forceinline__ void ldm_x4_t(u32* r, u32 addr) {
    asm volatile("ldmatrix.sync.aligned.m8n8.x4.trans.shared.b16 {%0,%1,%2,%3}, [%4];"
                 : "=r"(r[0]), "=r"(r[1]), "=r"(r[2]), "=r"(r[3]) : "r"(addr));
}
__device__ __forceinline__ void mma16816(float* d, const u32* a, u32 b0, u32 b1) {
    asm volatile("mma.sync.aligned.m16n8k16.row.col.f32.bf16.bf16.f32 "
                 "{%0,%1,%2,%3}, {%4,%5,%6,%7}, {%8,%9}, {%0,%1,%2,%3};"
                 : "+f"(d[0]), "+f"(d[1]), "+f"(d[2]), "+f"(d[3])
                 : "r"(a[0]), "r"(a[1]), "r"(a[2]), "r"(a[3]), "r"(b0), "r"(b1));
}
__device__ __forceinline__ void split_bf(float v, __nv_bfloat16& hi, __nv_bfloat16& lo) {
    hi = __float2bfloat16(v);
    lo = __float2bfloat16(v - __bfloat162float(hi));
}

// ============================================================
// Prep: fold merge weights; bf16-split all three weight matrices.
// ============================================================
__global__ void k_prep(const float* __restrict__ wm,
                       const float* __restrict__ wu,
                       const float* __restrict__ wl,
                       const float* __restrict__ wr) {
    int i = blockIdx.x * 256 + threadIdx.x;   // 131072 + 32768 + 16384 = 180224
    if (i < 131072) {
        int o = i >> 9, k = i & 511;
        float v = wm[o * 1024 + k] + wm[o * 1024 + k + 512];
        __nv_bfloat16 hi, lo; split_bf(v, hi, lo);
        g_Wf[o * 1024 + k]       = hi;
        g_Wf[o * 1024 + 512 + k] = lo;
    } else if (i < 163840) {
        int j = i - 131072;
        int m = j >> 6, k = j & 63;
        float v = (m < 256) ? wu[m * 64 + k] : wl[(m - 256) * 64 + k];
        __nv_bfloat16 hi, lo; split_bf(v, hi, lo);
        g_Wul[m * 128 + k]      = hi;
        g_Wul[m * 128 + 64 + k] = lo;
    } else if (i < 180224) {
        int j = i - 163840;
        int m = j >> 8, k = j & 255;
        float v = wr[m * 256 + k];
        __nv_bfloat16 hi, lo; split_bf(v, hi, lo);
        g_Wred[m * 512 + k]       = hi;
        g_Wred[m * 512 + 256 + k] = lo;
    }
}

// ============================================================
// K1 (tensor): reduced = w_red @ x + b_red, bf16-split in-kernel
// (x fp32 tile split to hi/lo during smem stage; 3 term-MMAs/chunk).
// CTA 64x128 (full M), 8 warps (4x2), warp tile 16x64.
// Fused epilogue: emits g_red_hi/lo AND Rv (sigmoid tri-band rowsum).
// ============================================================
__global__ __launch_bounds__(256) void k_red_mma(const float* __restrict__ x,
                                                 const float* __restrict__ bred,
                                                 const float* __restrict__ wwt,
                                                 const float* __restrict__ bwt) {
    // arena: main loop tiles (27648B) / fp32 red transpose (33792B)
    __shared__ __align__(16) char arena[33792];
    __nv_bfloat16* As_hi = (__nv_bfloat16*)(arena);          // 64x40 = 5120B
    __nv_bfloat16* As_lo = (__nv_bfloat16*)(arena + 5120);
    __nv_bfloat16* Bs_hi = (__nv_bfloat16*)(arena + 10240);  // 32x136 = 8704B
    __nv_bfloat16* Bs_lo = (__nv_bfloat16*)(arena + 18944);
    float* redT = (float*)arena;                             // 64x132 fp32
    __shared__ float ws[192];
    __shared__ float bs3[3];

    int b  = blockIdx.z;
    int p0 = blockIdx.x * 128;
    int tid = threadIdx.x;
    int wid = tid >> 5, lane = tid & 31;
    int wm = wid & 3;       // 4 m-slots x 16 rows
    int wn = wid >> 2;      // 2 n-slots x 64 cols
    for (int i = tid; i < 192; i += 256) ws[i] = wwt[i];
    if (tid < 3) bs3[tid] = bwt[tid];

    float acc[8][4];
#pragma unroll
    for (int i = 0; i < 8; i++)
#pragma unroll
        for (int q = 0; q < 4; q++) acc[i][q] = 0.f;

    const float* xb = x + (size_t)b * C * P;
    for (int k0 = 0; k0 < 256; k0 += 32) {
        {   // A chunk: 64 rows x 32 k, hi & lo
            int row = tid >> 2, q = tid & 3;
            *(uint4*)&As_hi[row * 40 + q * 8] =
                *(const uint4*)(g_Wred + row * 512 + k0 + q * 8);
            *(uint4*)&As_lo[row * 40 + q * 8] =
                *(const uint4*)(g_Wred + row * 512 + 256 + k0 + q * 8);
        }
#pragma unroll
        for (int l = 0; l < 4; l++) {   // x chunk 32k x 128p, split fp32->hi/lo
            int cid = tid + l * 256;
            int kk = cid >> 5, pq = cid & 31;
            float4 v = *(const float4*)(xb + (size_t)(k0 + kk) * P + p0 + pq * 4);
            __nv_bfloat162 h0, h1, l0, l1;
            h0.x = __float2bfloat16(v.x); h0.y = __float2bfloat16(v.y);
            h1.x = __float2bfloat16(v.z); h1.y = __float2bfloat16(v.w);
            l0.x = __float2bfloat16(v.x - __bfloat162float(h0.x));
            l0.y = __float2bfloat16(v.y - __bfloat162float(h0.y));
            l1.x = __float2bfloat16(v.z - __bfloat162float(h1.x));
            l1.y = __float2bfloat16(v.w - __bfloat162float(h1.y));
            *(__nv_bfloat162*)&Bs_hi[kk * 136 + pq * 4]     = h0;
            *(__nv_bfloat162*)&Bs_hi[kk * 136 + pq * 4 + 2] = h1;
            *(__nv_bfloat162*)&Bs_lo[kk * 136 + pq * 4]     = l0;
            *(__nv_bfloat162*)&Bs_lo[kk * 136 + pq * 4 + 2] = l1;
        }
        __syncthreads();
#pragma unroll
        for (int ks = 0; ks < 2; ks++) {
            int kk = ks * 16;
            u32 ah[4], al[4], bh[4][4], bl[4][4];
            ldm_x4(ah, sptr(&As_hi[(wm * 16 + (lane & 15)) * 40 + kk + (lane >> 4) * 8]));
            ldm_x4(al, sptr(&As_lo[(wm * 16 + (lane & 15)) * 40 + kk + (lane >> 4) * 8]));
#pragma unroll
            for (int nh = 0; nh < 4; nh++) {
                ldm_x4_t(bh[nh], sptr(&Bs_hi[(kk + (lane & 15)) * 136
                                             + wn * 64 + nh * 16 + (lane >> 4) * 8]));
                ldm_x4_t(bl[nh], sptr(&Bs_lo[(kk + (lane & 15)) * 136
                                             + wn * 64 + nh * 16 + (lane >> 4) * 8]));
            }
#pragma unroll
            for (int nf = 0; nf < 8; nf++) {
                u32 b0h = bh[nf >> 1][(nf & 1) * 2], b1h = bh[nf >> 1][(nf & 1) * 2 + 1];
                u32 b0l = bl[nf >> 1][(nf & 1) * 2], b1l = bl[nf >> 1][(nf & 1) * 2 + 1];
                mma16816(acc[nf], ah, b0h, b1h);
                mma16816(acc[nf], al, b0h, b1h);
                mma16816(acc[nf], ah, b0l, b1l);
            }
        }
        __syncthreads();
    }

    // ---- epilogue: bias, write bf16 hi/lo, stage fp32 tile for Rv ----
    int g = lane >> 2, tg = lane & 3;
    int m1 = wm * 16 + g;
    float bsA = __ldg(bred + m1), bsB = __ldg(bred + m1 + 8);
#pragma unroll
    for (int nf = 0; nf < 8; nf++) {
        int p = wn * 64 + nf * 8 + tg * 2;
        float v0 = acc[nf][0] + bsA, v1 = acc[nf][1] + bsA;
        float v2 = acc[nf][2] + bsB, v3 = acc[nf][3] + bsB;
        *(float2*)&redT[m1 * 132 + p]       = make_float2(v0, v1);
        *(float2*)&redT[(m1 + 8) * 132 + p] = make_float2(v2, v3);
        size_t off0 = ((size_t)b * CR + m1) * P + p0 + p;
        size_t off1 = ((size_t)b * CR + m1 + 8) * P + p0 + p;
        __nv_bfloat16 h0, l0, h1, l1;
        __nv_bfloat162 hh, ll;
        split_bf(v0, h0, l0); split_bf(v1, h1, l1);
        hh.x = h0; hh.y = h1; ll.x = l0; ll.y = l1;
        *(__nv_bfloat162*)(g_red_hi + off0) = hh;
        *(__nv_bfloat162*)(g_red_lo + off0) = ll;
        split_bf(v2, h0, l0); split_bf(v3, h1, l1);
        hh.x = h0; hh.y = h1; ll.x = l0; ll.y = l1;
        *(__nv_bfloat162*)(g_red_hi + off1) = hh;
        *(__nv_bfloat162*)(g_red_lo + off1) = ll;
    }
    __syncthreads();

    // ---- fused Rv: 128 threads, one pixel each ----
    if (tid < 128) {
        int w = tid & 63;                 // p0 multiple of 128
        float a0 = bs3[0], a1 = bs3[1], a2 = bs3[2];
#pragma unroll 16
        for (int m = 0; m < 64; m++) {
            float r = redT[m * 132 + tid];
            a0 += ws[m]       * r;
            a1 += ws[64 + m]  * r;
            a2 += ws[128 + m] * r;
        }
        float s0 = 1.f / (1.f + expf(-a0));
        float s1 = 1.f / (1.f + expf(-a1));
        float s2 = 1.f / (1.f + expf(-a2));
        float den = fmaxf(s0 + s1 + s2, 1e-6f);
        float rv = s1;
        if (w >= 1)     rv += s0;
        if (w <= S - 2) rv += s2;
        g_Rv[(size_t)b * P + p0 + tid] = rv / den;
    }
}

// ============================================================
// Shared MMA body for K2/K5: CTA 128x128, 8 warps (2x4), warp 64x32.
// Per 32-k chunk: Bhi+Blo loaded once, 3 term-MMAs.
// ============================================================

// K2 (tensor): u (m<256) and lam (m>=256). K=64.
__global__ __launch_bounds__(256) void k_ul_mma(const float* __restrict__ bu,
                                                const float* __restrict__ bl) {
    __shared__ __align__(16) __nv_bfloat16 As_hi[128 * 40];
    __shared__ __align__(16) __nv_bfloat16 As_lo[128 * 40];
    __shared__ __align__(16) __nv_bfloat16 Bs_hi[32 * 136];
    __shared__ __align__(16) __nv_bfloat16 Bs_lo[32 * 136];
    int b  = blockIdx.z;
    int m0 = blockIdx.y * 128;
    int p0 = blockIdx.x * 128;
    int tid = threadIdx.x;
    int wid = tid >> 5, lane = tid & 31;
    int wm = wid >> 2, wn = wid & 3;
    float acc[4][4][4];
#pragma unroll
    for (int i = 0; i < 4; i++)
#pragma unroll
        for (int j = 0; j < 4; j++)
#pragma unroll
            for (int q = 0; q < 4; q++) acc[i][j][q] = 0.f;

    for (int k0 = 0; k0 < 64; k0 += 32) {
#pragma unroll
        for (int l = 0; l < 2; l++) {   // A: 128 rows x 32 k
            int cid = tid + l * 256;
            int row = cid >> 2, q = cid & 3;
            *(uint4*)&As_hi[row * 40 + q * 8] =
                *(const uint4*)(g_Wul + (size_t)(m0 + row) * 128 + k0 + q * 8);
            *(uint4*)&As_lo[row * 40 + q * 8] =
                *(const uint4*)(g_Wul + (size_t)(m0 + row) * 128 + 64 + k0 + q * 8);
        }
#pragma unroll
        for (int l = 0; l < 2; l++) {   // B: 32 k x 128 p
            int cid = tid + l * 256;
            int kk = cid >> 4, q = cid & 15;
            size_t off = ((size_t)b * CR + k0 + kk) * P + p0 + q * 8;
            *(uint4*)&Bs_hi[kk * 136 + q * 8] = *(const uint4*)(g_red_hi + off);
            *(uint4*)&Bs_lo[kk * 136 + q * 8] = *(const uint4*)(g_red_lo + off);
        }
        __syncthreads();
#pragma unroll
        for (int ks = 0; ks < 2; ks++) {
            int kk = ks * 16;
            u32 ah[4][4], al[4][4], bh[2][4], bl2[2][4];
#pragma unroll
            for (int mf = 0; mf < 4; mf++) {
                ldm_x4(ah[mf], sptr(&As_hi[(wm * 64 + mf * 16 + (lane & 15)) * 40
                                           + kk + (lane >> 4) * 8]));
                ldm_x4(al[mf], sptr(&As_lo[(wm * 64 + mf * 16 + (lane & 15)) * 40
                                           + kk + (lane >> 4) * 8]));
            }
#pragma unroll
            for (int nh = 0; nh < 2; nh++) {
                ldm_x4_t(bh[nh], sptr(&Bs_hi[(kk + (lane & 15)) * 136
                                             + wn * 32 + nh * 16 + (lane >> 4) * 8]));
                ldm_x4_t(bl2[nh], sptr(&Bs_lo[(kk + (lane & 15)) * 136
                                              + wn * 32 + nh * 16 + (lane >> 4) * 8]));
            }
#pragma unroll
            for (int mf = 0; mf < 4; mf++)
#pragma unroll
                for (int nf = 0; nf < 4; nf++) {
                    u32 b0h = bh[nf >> 1][(nf & 1) * 2], b1h = bh[nf >> 1][(nf & 1) * 2 + 1];
                    u32 b0l = bl2[nf >> 1][(nf & 1) * 2], b1l = bl2[nf >> 1][(nf & 1) * 2 + 1];
                    mma16816(acc[mf][nf], ah[mf], b0h, b1h);
                    mma16816(acc[mf][nf], al[mf], b0h, b1h);
                    mma16816(acc[mf][nf], ah[mf], b0l, b1l);
                }
        }
        __syncthreads();
    }
    float* outb; const float* biasArr; int mofs;
    if (m0 < 256) { outb = g_u   + (size_t)b * C * P; biasArr = bu; mofs = m0; }
    else          { outb = g_lam + (size_t)b * C * P; biasArr = bl; mofs = m0 - 256; }
    int g = lane >> 2, tg = lane & 3;
#pragma unroll
    for (int mf = 0; mf < 4; mf++) {
        int m1 = mofs + wm * 64 + mf * 16 + g;
#pragma unroll
        for (int nf = 0; nf < 4; nf++) {
            int p = p0 + wn * 32 + nf * 8 + tg * 2;
            float bs1 = biasArr[m1], bs2 = biasArr[m1 + 8];
            *(float2*)(outb + (size_t)m1 * P + p) =
                make_float2(acc[mf][nf][0] + bs1, acc[mf][nf][1] + bs1);
            *(float2*)(outb + (size_t)(m1 + 8) * P + p) =
                make_float2(acc[mf][nf][2] + bs2, acc[mf][nf][3] + bs2);
        }
    }
}

// ============================================================
// K4: fused dual scan along w; outputs bf16 hi/lo Kmat planes.
// ============================================================
__global__ __launch_bounds__(512) void k_scan(const float* __restrict__ x) {
    __shared__ float ls[64 * 65];
    int b = blockIdx.y, c = blockIdx.x;
    size_t base = ((size_t)b * C + c) * P;
    const float* xp = x + base;
    const float* up = g_u + base;
    const float* lp = g_lam + base;
    const float* rv = g_Rv + (size_t)b * P;
    __nv_bfloat16* AhiP = g_Khi + ((size_t)b * 512 + c) * P;
    __nv_bfloat16* AloP = g_Klo + ((size_t)b * 512 + c) * P;
    __nv_bfloat16* BhiP = g_Khi + ((size_t)b * 512 + 256 + c) * P;
    __nv_bfloat16* BloP = g_Klo + ((size_t)b * 512 + 256 + c) * P;
    int tid = threadIdx.x;

#pragma unroll
    for (int l = 0; l < 2; l++) {
        int fid = tid + l * 512;
        int row = fid >> 4, q = fid & 15;
        float4 v = *(const float4*)(lp + row * 64 + q * 4);
        ls[row * 65 + q * 4 + 0] = v.x;
        ls[row * 65 + q * 4 + 1] = v.y;
        ls[row * 65 + q * 4 + 2] = v.z;
        ls[row * 65 + q * 4 + 3] = v.w;
    }
    __syncthreads();

    int wid = tid >> 5, lane = tid & 31;
#pragma unroll
    for (int r = 0; r < 4; r++) {
        int h = wid + r * 16;
        int hb = 63 - h;
        int w0 = lane * 2, w1 = w0 + 1;
        float2 av = *(const float2*)(rv + h * 64 + w0);
        float a0 = av.x, a1 = av.y;
        float2 xv = *(const float2*)(xp + h * 64 + w0);
        float bA0 = ls[w0 * 65 + h] * xv.x;
        float bA1 = ls[w1 * 65 + h] * xv.y;
        float bB0 = ls[(63 - w0) * 65 + hb] * xv.x;
        float bB1 = ls[(63 - w1) * 65 + hb] * xv.y;
        float ca  = a0 * a1;
        float cbA = a1 * bA0 + bA1;
        float cbB = a1 * bB0 + bB1;
#pragma unroll
        for (int d = 1; d < 32; d <<= 1) {
            float pa  = __shfl_up_sync(0xffffffffu, ca,  d);
            float pbA = __shfl_up_sync(0xffffffffu, cbA, d);
            float pbB = __shfl_up_sync(0xffffffffu, cbB, d);
            if (lane >= d) {
                cbA = ca * pbA + cbA;
                cbB = ca * pbB + cbB;
                ca  = ca * pa;
            }
        }
        float eA = __shfl_up_sync(0xffffffffu, cbA, 1);
        float eB = __shfl_up_sync(0xffffffffu, cbB, 1);
        if (lane == 0) { eA = 0.f; eB = 0.f; }
        float hA0 = a0 * eA + bA0;
        float hA1 = a1 * hA0 + bA1;
        float hB0 = a0 * eB + bB0;
        float hB1 = a1 * hB0 + bB1;
        float2 uv  = *(const float2*)(up + h  * 64 + w0);
        float2 uvb = *(const float2*)(up + hb * 64 + w0);
        float oA0 = hA0 * uv.x,  oA1 = hA1 * uv.y;
        float oB0 = hB0 * uvb.x, oB1 = hB1 * uvb.y;
        __nv_bfloat16 h0, l0, h1, l1;
        __nv_bfloat162 hh, ll;
        split_bf(oA0, h0, l0); split_bf(oA1, h1, l1);
        hh.x = h0; hh.y = h1; ll.x = l0; ll.y = l1;
        *(__nv_bfloat162*)(AhiP + h * 64 + w0) = hh;
        *(__nv_bfloat162*)(AloP + h * 64 + w0) = ll;
        split_bf(oB0, h0, l0); split_bf(oB1, h1, l1);
        hh.x = h0; hh.y = h1; ll.x = l0; ll.y = l1;
        *(__nv_bfloat162*)(BhiP + h * 64 + w0) = hh;
        *(__nv_bfloat162*)(BloP + h * 64 + w0) = ll;
    }
}

// ============================================================
// K5 (tensor): out = Wf @ Kmat + bias. K=512, per-chunk 3-term.
// ============================================================
__global__ __launch_bounds__(256) void k_merge_mma(float* __restrict__ out,
                                                   const float* __restrict__ bm) {
    __shared__ __align__(16) __nv_bfloat16 As_hi[128 * 40];
    __shared__ __align__(16) __nv_bfloat16 As_lo[128 * 40];
    __shared__ __align__(16) __nv_bfloat16 Bs_hi[32 * 136];
    __shared__ __align__(16) __nv_bfloat16 Bs_lo[32 * 136];
    int b  = blockIdx.z;
    int m0 = blockIdx.y * 128;
    int p0 = blockIdx.x * 128;
    int tid = threadIdx.x;
    int wid = tid >> 5, lane = tid & 31;
    int wm = wid >> 2, wn = wid & 3;
    float acc[4][4][4];
#pragma unroll
    for (int i = 0; i < 4; i++)
#pragma unroll
        for (int j = 0; j < 4; j++)
#pragma unroll
            for (int q = 0; q < 4; q++) acc[i][j][q] = 0.f;

    for (int k0 = 0; k0 < 512; k0 += 32) {
#pragma unroll
        for (int l = 0; l < 2; l++) {
            int cid = tid + l * 256;
            int row = cid >> 2, q = cid & 3;
            *(uint4*)&As_hi[row * 40 + q * 8] =
                *(const uint4*)(g_Wf + (size_t)(m0 + row) * 1024 + k0 + q * 8);
            *(uint4*)&As_lo[row * 40 + q * 8] =
                *(const uint4*)(g_Wf + (size_t)(m0 + row) * 1024 + 512 + k0 + q * 8);
        }
#pragma unroll
        for (int l = 0; l < 2; l++) {
            int cid = tid + l * 256;
            int kk = cid >> 4, q = cid & 15;
            size_t off = ((size_t)b * 512 + k0 + kk) * P + p0 + q * 8;
            *(uint4*)&Bs_hi[kk * 136 + q * 8] = *(const uint4*)(g_Khi + off);
            *(uint4*)&Bs_lo[kk * 136 + q * 8] = *(const uint4*)(g_Klo + off);
        }
        __syncthreads();
#pragma unroll
        for (int ks = 0; ks < 2; ks++) {
            int kk = ks * 16;
            u32 ah[4][4], al[4][4], bh[2][4], bl2[2][4];
#pragma unroll
            for (int mf = 0; mf < 4; mf++) {
                ldm_x4(ah[mf], sptr(&As_hi[(wm * 64 + mf * 16 + (lane & 15)) * 40
                                           + kk + (lane >> 4) * 8]));
                ldm_x4(al[mf], sptr(&As_lo[(wm * 64 + mf * 16 + (lane & 15)) * 40
                                           + kk + (lane >> 4) * 8]));
            }
#pragma unroll
            for (int nh = 0; nh < 2; nh++) {
                ldm_x4_t(bh[nh], sptr(&Bs_hi[(kk + (lane & 15)) * 136
                                             + wn * 32 + nh * 16 + (lane >> 4) * 8]));
                ldm_x4_t(bl2[nh], sptr(&Bs_lo[(kk + (lane & 15)) * 136
                                              + wn * 32 + nh * 16 + (lane >> 4) * 8]));
            }
#pragma unroll
            for (int mf = 0; mf < 4; mf++)
#pragma unroll
                for (int nf = 0; nf < 4; nf++) {
                    u32 b0h = bh[nf >> 1][(nf & 1) * 2], b1h = bh[nf >> 1][(nf & 1) * 2 + 1];
                    u32 b0l = bl2[nf >> 1][(nf & 1) * 2], b1l = bl2[nf >> 1][(nf & 1) * 2 + 1];
                    mma16816(acc[mf][nf], ah[mf], b0h, b1h);
                    mma16816(acc[mf][nf], al[mf], b0h, b1h);
                    mma16816(acc[mf][nf], ah[mf], b0l, b1l);
                }
        }
        __syncthreads();
    }
    int g = lane >> 2, tg = lane & 3;
#pragma unroll
    for (int mf = 0; mf < 4; mf++) {
        int m1 = m0 + wm * 64 + mf * 16 + g;
#pragma unroll
        for (int nf = 0; nf < 4; nf++) {
            int p = p0 + wn * 32 + nf * 8 + tg * 2;
            float bs1 = bm[m1], bs2 = bm[m1 + 8];
            *(float2*)(out + ((size_t)b * C + m1) * P + p) =
                make_float2(acc[mf][nf][0] + bs1, acc[mf][nf][1] + bs1);
            *(float2*)(out + ((size_t)b * C + m1 + 8) * P + p) =
                make_float2(acc[mf][nf][2] + bs2, acc[mf][nf][3] + bs2);
        }
    }
}

// ============================================================
extern "C" void kernel_launch(void* const* d_in, const int* in_sizes, int n_in,
                              void* d_out, int out_size) {
    const float* x       = (const float*)d_in[0];
    const float* w_red   = (const float*)d_in[1];
    const float* b_red   = (const float*)d_in[2];
    const float* w_u     = (const float*)d_in[3];
    const float* b_u     = (const float*)d_in[4];
    const float* w_lam   = (const float*)d_in[5];
    const float* b_lam   = (const float*)d_in[6];
    const float* w_wt    = (const float*)d_in[7];
    const float* b_wt    = (const float*)d_in[8];
    const float* w_merge = (const float*)d_in[9];
    const float* b_merge = (const float*)d_in[10];
    float* out = (float*)d_out;

    k_prep<<<704, 256>>>(w_merge, w_u, w_lam, w_red);
    k_red_mma<<<dim3(32, 1, NB), 256>>>(x, b_red, w_wt, b_wt);
    k_ul_mma<<<dim3(32, 4, NB), 256>>>(b_u, b_lam);
    k_scan<<<dim3(256, NB), 512>>>(x);
    k_merge_mma<<<dim3(32, 2, NB), 256>>>(out, b_merge);
}

// round 7
// speedup vs baseline: 2.4906x; 1.0143x over previous
#include <cuda_runtime.h>
#include <cuda_bf16.h>

#define S 64
#define NB 8
#define C 256
#define CR 64
#define P 4096   // S*S per plane

typedef unsigned int u32;

// ---- scratch (device globals; no runtime allocation allowed) ----
__device__ __nv_bfloat16 g_red_hi[NB * CR * P];      // 4 MB
__device__ __nv_bfloat16 g_red_lo[NB * CR * P];      // 4 MB
__device__ float g_u  [NB * C * P];                  // 32 MB
__device__ float g_lam[NB * C * P];                  // 32 MB
__device__ float g_Rv [NB * P];                      // 128 KB
__device__ __nv_bfloat16 g_Khi[NB * 512 * P];        // 32 MB (0..255 = A dir, 256..511 = B dir)
__device__ __nv_bfloat16 g_Klo[NB * 512 * P];        // 32 MB
__device__ __nv_bfloat16 g_Wf  [256 * 1024];         // merge W: row = [hi(512) | lo(512)]
__device__ __nv_bfloat16 g_Wul [512 * 128];          // u/lam W: row = [hi(64) | lo(64)]
__device__ __nv_bfloat16 g_Wred[64 * 512];           // red  W: row = [hi(256) | lo(256)]

// ---- helpers ----
__device__ __forceinline__ u32 sptr(const void* p) {
    return (u32)__cvta_generic_to_shared(p);
}
__device__ __forceinline__ void ldm_x4(u32* r, u32 addr) {
    asm volatile("ldmatrix.sync.aligned.m8n8.x4.shared.b16 {%0,%1,%2,%3}, [%4];"
                 : "=r"(r[0]), "=r"(r[1]), "=r"(r[2]), "=r"(r[3]) : "r"(addr));
}
__device__ __forceinline__ void ldm_x4_t(u32* r, u32 addr) {
    asm volatile("ldmatrix.sync.aligned.m8n8.x4.trans.shared.b16 {%0,%1,%2,%3}, [%4];"
                 : "=r"(r[0]), "=r"(r[1]), "=r"(r[2]), "=r"(r[3]) : "r"(addr));
}
__device__ __forceinline__ void mma16816(float* d, const u32* a, u32 b0, u32 b1) {
    asm volatile("mma.sync.aligned.m16n8k16.row.col.f32.bf16.bf16.f32 "
                 "{%0,%1,%2,%3}, {%4,%5,%6,%7}, {%8,%9}, {%0,%1,%2,%3};"
                 : "+f"(d[0]), "+f"(d[1]), "+f"(d[2]), "+f"(d[3])
                 : "r"(a[0]), "r"(a[1]), "r"(a[2]), "r"(a[3]), "r"(b0), "r"(b1));
}
__device__ __forceinline__ void split_bf(float v, __nv_bfloat16& hi, __nv_bfloat16& lo) {
    hi = __float2bfloat16(v);
    lo = __float2bfloat16(v - __bfloat162float(hi));
}
__device__ __forceinline__ void cp16(u32 dst, const void* src) {
    asm volatile("cp.async.cg.shared.global [%0], [%1], 16;" :: "r"(dst), "l"(src));
}

// ============================================================
// Prep: fold merge weights; bf16-split all three weight matrices.
// ============================================================
__global__ void k_prep(const float* __restrict__ wm,
                       const float* __restrict__ wu,
                       const float* __restrict__ wl,
                       const float* __restrict__ wr) {
    int i = blockIdx.x * 256 + threadIdx.x;   // 131072 + 32768 + 16384 = 180224
    if (i < 131072) {
        int o = i >> 9, k = i & 511;
        float v = wm[o * 1024 + k] + wm[o * 1024 + k + 512];
        __nv_bfloat16 hi, lo; split_bf(v, hi, lo);
        g_Wf[o * 1024 + k]       = hi;
        g_Wf[o * 1024 + 512 + k] = lo;
    } else if (i < 163840) {
        int j = i - 131072;
        int m = j >> 6, k = j & 63;
        float v = (m < 256) ? wu[m * 64 + k] : wl[(m - 256) * 64 + k];
        __nv_bfloat16 hi, lo; split_bf(v, hi, lo);
        g_Wul[m * 128 + k]      = hi;
        g_Wul[m * 128 + 64 + k] = lo;
    } else if (i < 180224) {
        int j = i - 163840;
        int m = j >> 8, k = j & 255;
        float v = wr[m * 256 + k];
        __nv_bfloat16 hi, lo; split_bf(v, hi, lo);
        g_Wred[m * 512 + k]       = hi;
        g_Wred[m * 512 + 256 + k] = lo;
    }
}

// ============================================================
// K1 (tensor): reduced = w_red @ x + b_red, bf16-split in-kernel.
// Fused epilogue: emits g_red_hi/lo AND Rv.
// ============================================================
__global__ __launch_bounds__(256) void k_red_mma(const float* __restrict__ x,
                                                 const float* __restrict__ bred,
                                                 const float* __restrict__ wwt,
                                                 const float* __restrict__ bwt) {
    __shared__ __align__(16) char arena[33792];
    __nv_bfloat16* As_hi = (__nv_bfloat16*)(arena);          // 64x40
    __nv_bfloat16* As_lo = (__nv_bfloat16*)(arena + 5120);
    __nv_bfloat16* Bs_hi = (__nv_bfloat16*)(arena + 10240);  // 32x136
    __nv_bfloat16* Bs_lo = (__nv_bfloat16*)(arena + 18944);
    float* redT = (float*)arena;                             // 64x132 fp32
    __shared__ float ws[192];
    __shared__ float bs3[3];

    int b  = blockIdx.z;
    int p0 = blockIdx.x * 128;
    int tid = threadIdx.x;
    int wid = tid >> 5, lane = tid & 31;
    int wm = wid & 3;
    int wn = wid >> 2;
    for (int i = tid; i < 192; i += 256) ws[i] = wwt[i];
    if (tid < 3) bs3[tid] = bwt[tid];

    float acc[8][4];
#pragma unroll
    for (int i = 0; i < 8; i++)
#pragma unroll
        for (int q = 0; q < 4; q++) acc[i][q] = 0.f;

    const float* xb = x + (size_t)b * C * P;
    for (int k0 = 0; k0 < 256; k0 += 32) {
        {
            int row = tid >> 2, q = tid & 3;
            *(uint4*)&As_hi[row * 40 + q * 8] =
                *(const uint4*)(g_Wred + row * 512 + k0 + q * 8);
            *(uint4*)&As_lo[row * 40 + q * 8] =
                *(const uint4*)(g_Wred + row * 512 + 256 + k0 + q * 8);
        }
#pragma unroll
        for (int l = 0; l < 4; l++) {
            int cid = tid + l * 256;
            int kk = cid >> 5, pq = cid & 31;
            float4 v = *(const float4*)(xb + (size_t)(k0 + kk) * P + p0 + pq * 4);
            __nv_bfloat162 h0, h1, l0, l1;
            h0.x = __float2bfloat16(v.x); h0.y = __float2bfloat16(v.y);
            h1.x = __float2bfloat16(v.z); h1.y = __float2bfloat16(v.w);
            l0.x = __float2bfloat16(v.x - __bfloat162float(h0.x));
            l0.y = __float2bfloat16(v.y - __bfloat162float(h0.y));
            l1.x = __float2bfloat16(v.z - __bfloat162float(h1.x));
            l1.y = __float2bfloat16(v.w - __bfloat162float(h1.y));
            *(__nv_bfloat162*)&Bs_hi[kk * 136 + pq * 4]     = h0;
            *(__nv_bfloat162*)&Bs_hi[kk * 136 + pq * 4 + 2] = h1;
            *(__nv_bfloat162*)&Bs_lo[kk * 136 + pq * 4]     = l0;
            *(__nv_bfloat162*)&Bs_lo[kk * 136 + pq * 4 + 2] = l1;
        }
        __syncthreads();
#pragma unroll
        for (int ks = 0; ks < 2; ks++) {
            int kk = ks * 16;
            u32 ah[4], al[4], bh[4][4], bl[4][4];
            ldm_x4(ah, sptr(&As_hi[(wm * 16 + (lane & 15)) * 40 + kk + (lane >> 4) * 8]));
            ldm_x4(al, sptr(&As_lo[(wm * 16 + (lane & 15)) * 40 + kk + (lane >> 4) * 8]));
#pragma unroll
            for (int nh = 0; nh < 4; nh++) {
                ldm_x4_t(bh[nh], sptr(&Bs_hi[(kk + (lane & 15)) * 136
                                             + wn * 64 + nh * 16 + (lane >> 4) * 8]));
                ldm_x4_t(bl[nh], sptr(&Bs_lo[(kk + (lane & 15)) * 136
                                             + wn * 64 + nh * 16 + (lane >> 4) * 8]));
            }
#pragma unroll
            for (int nf = 0; nf < 8; nf++) {
                u32 b0h = bh[nf >> 1][(nf & 1) * 2], b1h = bh[nf >> 1][(nf & 1) * 2 + 1];
                u32 b0l = bl[nf >> 1][(nf & 1) * 2], b1l = bl[nf >> 1][(nf & 1) * 2 + 1];
                mma16816(acc[nf], ah, b0h, b1h);
                mma16816(acc[nf], al, b0h, b1h);
                mma16816(acc[nf], ah, b0l, b1l);
            }
        }
        __syncthreads();
    }

    int g = lane >> 2, tg = lane & 3;
    int m1 = wm * 16 + g;
    float bsA = __ldg(bred + m1), bsB = __ldg(bred + m1 + 8);
#pragma unroll
    for (int nf = 0; nf < 8; nf++) {
        int p = wn * 64 + nf * 8 + tg * 2;
        float v0 = acc[nf][0] + bsA, v1 = acc[nf][1] + bsA;
        float v2 = acc[nf][2] + bsB, v3 = acc[nf][3] + bsB;
        *(float2*)&redT[m1 * 132 + p]       = make_float2(v0, v1);
        *(float2*)&redT[(m1 + 8) * 132 + p] = make_float2(v2, v3);
        size_t off0 = ((size_t)b * CR + m1) * P + p0 + p;
        size_t off1 = ((size_t)b * CR + m1 + 8) * P + p0 + p;
        __nv_bfloat16 h0, l0, h1, l1;
        __nv_bfloat162 hh, ll;
        split_bf(v0, h0, l0); split_bf(v1, h1, l1);
        hh.x = h0; hh.y = h1; ll.x = l0; ll.y = l1;
        *(__nv_bfloat162*)(g_red_hi + off0) = hh;
        *(__nv_bfloat162*)(g_red_lo + off0) = ll;
        split_bf(v2, h0, l0); split_bf(v3, h1, l1);
        hh.x = h0; hh.y = h1; ll.x = l0; ll.y = l1;
        *(__nv_bfloat162*)(g_red_hi + off1) = hh;
        *(__nv_bfloat162*)(g_red_lo + off1) = ll;
    }
    __syncthreads();

    if (tid < 128) {
        int w = tid & 63;
        float a0 = bs3[0], a1 = bs3[1], a2 = bs3[2];
#pragma unroll 16
        for (int m = 0; m < 64; m++) {
            float r = redT[m * 132 + tid];
            a0 += ws[m]       * r;
            a1 += ws[64 + m]  * r;
            a2 += ws[128 + m] * r;
        }
        float s0 = 1.f / (1.f + expf(-a0));
        float s1 = 1.f / (1.f + expf(-a1));
        float s2 = 1.f / (1.f + expf(-a2));
        float den = fmaxf(s0 + s1 + s2, 1e-6f);
        float rv = s1;
        if (w >= 1)     rv += s0;
        if (w <= S - 2) rv += s2;
        g_Rv[(size_t)b * P + p0 + tid] = rv / den;
    }
}

// ============================================================
// K2 (tensor): u (m<256) and lam (m>=256). K=64, per-chunk 3-term.
// ============================================================
__global__ __launch_bounds__(256) void k_ul_mma(const float* __restrict__ bu,
                                                const float* __restrict__ bl) {
    __shared__ __align__(16) __nv_bfloat16 As_hi[128 * 40];
    __shared__ __align__(16) __nv_bfloat16 As_lo[128 * 40];
    __shared__ __align__(16) __nv_bfloat16 Bs_hi[32 * 136];
    __shared__ __align__(16) __nv_bfloat16 Bs_lo[32 * 136];
    int b  = blockIdx.z;
    int m0 = blockIdx.y * 128;
    int p0 = blockIdx.x * 128;
    int tid = threadIdx.x;
    int wid = tid >> 5, lane = tid & 31;
    int wm = wid >> 2, wn = wid & 3;
    float acc[4][4][4];
#pragma unroll
    for (int i = 0; i < 4; i++)
#pragma unroll
        for (int j = 0; j < 4; j++)
#pragma unroll
            for (int q = 0; q < 4; q++) acc[i][j][q] = 0.f;

    for (int k0 = 0; k0 < 64; k0 += 32) {
#pragma unroll
        for (int l = 0; l < 2; l++) {
            int cid = tid + l * 256;
            int row = cid >> 2, q = cid & 3;
            *(uint4*)&As_hi[row * 40 + q * 8] =
                *(const uint4*)(g_Wul + (size_t)(m0 + row) * 128 + k0 + q * 8);
            *(uint4*)&As_lo[row * 40 + q * 8] =
                *(const uint4*)(g_Wul + (size_t)(m0 + row) * 128 + 64 + k0 + q * 8);
        }
#pragma unroll
        for (int l = 0; l < 2; l++) {
            int cid = tid + l * 256;
            int kk = cid >> 4, q = cid & 15;
            size_t off = ((size_t)b * CR + k0 + kk) * P + p0 + q * 8;
            *(uint4*)&Bs_hi[kk * 136 + q * 8] = *(const uint4*)(g_red_hi + off);
            *(uint4*)&Bs_lo[kk * 136 + q * 8] = *(const uint4*)(g_red_lo + off);
        }
        __syncthreads();
#pragma unroll
        for (int ks = 0; ks < 2; ks++) {
            int kk = ks * 16;
            u32 bh[2][4], bl2[2][4];
#pragma unroll
            for (int nh = 0; nh < 2; nh++) {
                ldm_x4_t(bh[nh], sptr(&Bs_hi[(kk + (lane & 15)) * 136
                                             + wn * 32 + nh * 16 + (lane >> 4) * 8]));
                ldm_x4_t(bl2[nh], sptr(&Bs_lo[(kk + (lane & 15)) * 136
                                              + wn * 32 + nh * 16 + (lane >> 4) * 8]));
            }
#pragma unroll
            for (int mf = 0; mf < 4; mf++) {
                u32 ah[4], al[4];
                ldm_x4(ah, sptr(&As_hi[(wm * 64 + mf * 16 + (lane & 15)) * 40
                                       + kk + (lane >> 4) * 8]));
                ldm_x4(al, sptr(&As_lo[(wm * 64 + mf * 16 + (lane & 15)) * 40
                                       + kk + (lane >> 4) * 8]));
#pragma unroll
                for (int nf = 0; nf < 4; nf++) {
                    u32 b0h = bh[nf >> 1][(nf & 1) * 2], b1h = bh[nf >> 1][(nf & 1) * 2 + 1];
                    u32 b0l = bl2[nf >> 1][(nf & 1) * 2], b1l = bl2[nf >> 1][(nf & 1) * 2 + 1];
                    mma16816(acc[mf][nf], ah, b0h, b1h);
                    mma16816(acc[mf][nf], al, b0h, b1h);
                    mma16816(acc[mf][nf], ah, b0l, b1l);
                }
            }
        }
        __syncthreads();
    }
    float* outb; const float* biasArr; int mofs;
    if (m0 < 256) { outb = g_u   + (size_t)b * C * P; biasArr = bu; mofs = m0; }
    else          { outb = g_lam + (size_t)b * C * P; biasArr = bl; mofs = m0 - 256; }
    int g = lane >> 2, tg = lane & 3;
#pragma unroll
    for (int mf = 0; mf < 4; mf++) {
        int m1 = mofs + wm * 64 + mf * 16 + g;
#pragma unroll
        for (int nf = 0; nf < 4; nf++) {
            int p = p0 + wn * 32 + nf * 8 + tg * 2;
            float bs1 = biasArr[m1], bs2 = biasArr[m1 + 8];
            *(float2*)(outb + (size_t)m1 * P + p) =
                make_float2(acc[mf][nf][0] + bs1, acc[mf][nf][1] + bs1);
            *(float2*)(outb + (size_t)(m1 + 8) * P + p) =
                make_float2(acc[mf][nf][2] + bs2, acc[mf][nf][3] + bs2);
        }
    }
}

// ============================================================
// K4: fused dual scan along w; outputs bf16 hi/lo Kmat planes.
// ============================================================
__global__ __launch_bounds__(512) void k_scan(const float* __restrict__ x) {
    __shared__ float ls[64 * 65];
    int b = blockIdx.y, c = blockIdx.x;
    size_t base = ((size_t)b * C + c) * P;
    const float* xp = x + base;
    const float* up = g_u + base;
    const float* lp = g_lam + base;
    const float* rv = g_Rv + (size_t)b * P;
    __nv_bfloat16* AhiP = g_Khi + ((size_t)b * 512 + c) * P;
    __nv_bfloat16* AloP = g_Klo + ((size_t)b * 512 + c) * P;
    __nv_bfloat16* BhiP = g_Khi + ((size_t)b * 512 + 256 + c) * P;
    __nv_bfloat16* BloP = g_Klo + ((size_t)b * 512 + 256 + c) * P;
    int tid = threadIdx.x;

#pragma unroll
    for (int l = 0; l < 2; l++) {
        int fid = tid + l * 512;
        int row = fid >> 4, q = fid & 15;
        float4 v = *(const float4*)(lp + row * 64 + q * 4);
        ls[row * 65 + q * 4 + 0] = v.x;
        ls[row * 65 + q * 4 + 1] = v.y;
        ls[row * 65 + q * 4 + 2] = v.z;
        ls[row * 65 + q * 4 + 3] = v.w;
    }
    __syncthreads();

    int wid = tid >> 5, lane = tid & 31;
#pragma unroll
    for (int r = 0; r < 4; r++) {
        int h = wid + r * 16;
        int hb = 63 - h;
        int w0 = lane * 2, w1 = w0 + 1;
        float2 av = *(const float2*)(rv + h * 64 + w0);
        float a0 = av.x, a1 = av.y;
        float2 xv = *(const float2*)(xp + h * 64 + w0);
        float bA0 = ls[w0 * 65 + h] * xv.x;
        float bA1 = ls[w1 * 65 + h] * xv.y;
        float bB0 = ls[(63 - w0) * 65 + hb] * xv.x;
        float bB1 = ls[(63 - w1) * 65 + hb] * xv.y;
        float ca  = a0 * a1;
        float cbA = a1 * bA0 + bA1;
        float cbB = a1 * bB0 + bB1;
#pragma unroll
        for (int d = 1; d < 32; d <<= 1) {
            float pa  = __shfl_up_sync(0xffffffffu, ca,  d);
            float pbA = __shfl_up_sync(0xffffffffu, cbA, d);
            float pbB = __shfl_up_sync(0xffffffffu, cbB, d);
            if (lane >= d) {
                cbA = ca * pbA + cbA;
                cbB = ca * pbB + cbB;
                ca  = ca * pa;
            }
        }
        float eA = __shfl_up_sync(0xffffffffu, cbA, 1);
        float eB = __shfl_up_sync(0xffffffffu, cbB, 1);
        if (lane == 0) { eA = 0.f; eB = 0.f; }
        float hA0 = a0 * eA + bA0;
        float hA1 = a1 * hA0 + bA1;
        float hB0 = a0 * eB + bB0;
        float hB1 = a1 * hB0 + bB1;
        float2 uv  = *(const float2*)(up + h  * 64 + w0);
        float2 uvb = *(const float2*)(up + hb * 64 + w0);
        float oA0 = hA0 * uv.x,  oA1 = hA1 * uv.y;
        float oB0 = hB0 * uvb.x, oB1 = hB1 * uvb.y;
        __nv_bfloat16 h0, l0, h1, l1;
        __nv_bfloat162 hh, ll;
        split_bf(oA0, h0, l0); split_bf(oA1, h1, l1);
        hh.x = h0; hh.y = h1; ll.x = l0; ll.y = l1;
        *(__nv_bfloat162*)(AhiP + h * 64 + w0) = hh;
        *(__nv_bfloat162*)(AloP + h * 64 + w0) = ll;
        split_bf(oB0, h0, l0); split_bf(oB1, h1, l1);
        hh.x = h0; hh.y = h1; ll.x = l0; ll.y = l1;
        *(__nv_bfloat162*)(BhiP + h * 64 + w0) = hh;
        *(__nv_bfloat162*)(BloP + h * 64 + w0) = ll;
    }
}

// ============================================================
// K5 (tensor): out = Wf @ Kmat + bias. K=512.
// CTA tile M=256 (full) x N=128, 512 threads (16 warps, 4x4),
// warp tile 64x32, cp.async double-buffered hi/lo stages.
// Dynamic smem: 2 x (A hi+lo 40KB) + 2 x (B hi+lo 17KB) = 116736 B.
// ============================================================
#define MG_A_BUF 40960              // bytes per A buffer (hi 20480 + lo 20480)
#define MG_B_BASE 81920
#define MG_B_BUF 17408              // bytes per B buffer (hi 8704 + lo 8704)
#define MG_SMEM 116736

__global__ __launch_bounds__(512) void k_merge_mma(float* __restrict__ out,
                                                   const float* __restrict__ bm) {
    extern __shared__ __align__(16) char dsm[];
    int b  = blockIdx.z;
    int p0 = blockIdx.x * 128;
    int tid = threadIdx.x;
    int wid = tid >> 5, lane = tid & 31;
    int wm = wid >> 2, wn = wid & 3;        // 4 m-slots x 4 n-slots

    float acc[4][4][4];
#pragma unroll
    for (int i = 0; i < 4; i++)
#pragma unroll
        for (int j = 0; j < 4; j++)
#pragma unroll
            for (int q = 0; q < 4; q++) acc[i][j][q] = 0.f;

    // per-thread load coords
    int a_row0 = tid >> 2, a_q = tid & 3;               // + l*128 rows
    int b_kk = tid >> 4, b_q = tid & 15;

    // prologue: chunk 0
    {
        char* Abuf = dsm;
        char* Bbuf = dsm + MG_B_BASE;
#pragma unroll
        for (int l = 0; l < 2; l++) {
            int row = a_row0 + l * 128;
            cp16(sptr(Abuf + (row * 40 + a_q * 8) * 2),
                 g_Wf + (size_t)row * 1024 + a_q * 8);
            cp16(sptr(Abuf + 20480 + (row * 40 + a_q * 8) * 2),
                 g_Wf + (size_t)row * 1024 + 512 + a_q * 8);
        }
        size_t off = ((size_t)b * 512 + b_kk) * P + p0 + b_q * 8;
        cp16(sptr(Bbuf + (b_kk * 136 + b_q * 8) * 2), g_Khi + off);
        cp16(sptr(Bbuf + 8704 + (b_kk * 136 + b_q * 8) * 2), g_Klo + off);
        asm volatile("cp.async.commit_group;");
    }

    for (int i = 0; i < 16; i++) {
        if (i + 1 < 16) {
            int k0 = (i + 1) * 32;
            char* Abuf = dsm + ((i + 1) & 1) * MG_A_BUF;
            char* Bbuf = dsm + MG_B_BASE + ((i + 1) & 1) * MG_B_BUF;
#pragma unroll
            for (int l = 0; l < 2; l++) {
                int row = a_row0 + l * 128;
                cp16(sptr(Abuf + (row * 40 + a_q * 8) * 2),
                     g_Wf + (size_t)row * 1024 + k0 + a_q * 8);
                cp16(sptr(Abuf + 20480 + (row * 40 + a_q * 8) * 2),
                     g_Wf + (size_t)row * 1024 + 512 + k0 + a_q * 8);
            }
            size_t off = ((size_t)b * 512 + k0 + b_kk) * P + p0 + b_q * 8;
            cp16(sptr(Bbuf + (b_kk * 136 + b_q * 8) * 2), g_Khi + off);
            cp16(sptr(Bbuf + 8704 + (b_kk * 136 + b_q * 8) * 2), g_Klo + off);
            asm volatile("cp.async.commit_group;");
            asm volatile("cp.async.wait_group 1;");
        } else {
            asm volatile("cp.async.wait_group 0;");
        }
        __syncthreads();

        const __nv_bfloat16* Ah = (const __nv_bfloat16*)(dsm + (i & 1) * MG_A_BUF);
        const __nv_bfloat16* Al = (const __nv_bfloat16*)(dsm + (i & 1) * MG_A_BUF + 20480);
        const __nv_bfloat16* Bh = (const __nv_bfloat16*)(dsm + MG_B_BASE + (i & 1) * MG_B_BUF);
        const __nv_bfloat16* Bl = (const __nv_bfloat16*)(dsm + MG_B_BASE + (i & 1) * MG_B_BUF + 8704);
#pragma unroll
        for (int ks = 0; ks < 2; ks++) {
            int kk = ks * 16;
            u32 bh[2][4], bl2[2][4];
#pragma unroll
            for (int nh = 0; nh < 2; nh++) {
                ldm_x4_t(bh[nh], sptr(&Bh[(kk + (lane & 15)) * 136
                                          + wn * 32 + nh * 16 + (lane >> 4) * 8]));
                ldm_x4_t(bl2[nh], sptr(&Bl[(kk + (lane & 15)) * 136
                                           + wn * 32 + nh * 16 + (lane >> 4) * 8]));
            }
#pragma unroll
            for (int mf = 0; mf < 4; mf++) {
                u32 ah[4], al[4];
                ldm_x4(ah, sptr(&Ah[(wm * 64 + mf * 16 + (lane & 15)) * 40
                                    + kk + (lane >> 4) * 8]));
                ldm_x4(al, sptr(&Al[(wm * 64 + mf * 16 + (lane & 15)) * 40
                                    + kk + (lane >> 4) * 8]));
#pragma unroll
                for (int nf = 0; nf < 4; nf++) {
                    u32 b0h = bh[nf >> 1][(nf & 1) * 2], b1h = bh[nf >> 1][(nf & 1) * 2 + 1];
                    u32 b0l = bl2[nf >> 1][(nf & 1) * 2], b1l = bl2[nf >> 1][(nf & 1) * 2 + 1];
                    mma16816(acc[mf][nf], ah, b0h, b1h);
                    mma16816(acc[mf][nf], al, b0h, b1h);
                    mma16816(acc[mf][nf], ah, b0l, b1l);
                }
            }
        }
        __syncthreads();
    }

    int g = lane >> 2, tg = lane & 3;
#pragma unroll
    for (int mf = 0; mf < 4; mf++) {
        int m1 = wm * 64 + mf * 16 + g;
#pragma unroll
        for (int nf = 0; nf < 4; nf++) {
            int p = p0 + wn * 32 + nf * 8 + tg * 2;
            float bs1 = bm[m1], bs2 = bm[m1 + 8];
            *(float2*)(out + ((size_t)b * C + m1) * P + p) =
                make_float2(acc[mf][nf][0] + bs1, acc[mf][nf][1] + bs1);
            *(float2*)(out + ((size_t)b * C + m1 + 8) * P + p) =
                make_float2(acc[mf][nf][2] + bs2, acc[mf][nf][3] + bs2);
        }
    }
}

// ============================================================
extern "C" void kernel_launch(void* const* d_in, const int* in_sizes, int n_in,
                              void* d_out, int out_size) {
    const float* x       = (const float*)d_in[0];
    const float* w_red   = (const float*)d_in[1];
    const float* b_red   = (const float*)d_in[2];
    const float* w_u     = (const float*)d_in[3];
    const float* b_u     = (const float*)d_in[4];
    const float* w_lam   = (const float*)d_in[5];
    const float* b_lam   = (const float*)d_in[6];
    const float* w_wt    = (const float*)d_in[7];
    const float* b_wt    = (const float*)d_in[8];
    const float* w_merge = (const float*)d_in[9];
    const float* b_merge = (const float*)d_in[10];
    float* out = (float*)d_out;

    cudaFuncSetAttribute(k_merge_mma,
                         cudaFuncAttributeMaxDynamicSharedMemorySize, MG_SMEM);

    k_prep<<<704, 256>>>(w_merge, w_u, w_lam, w_red);
    k_red_mma<<<dim3(32, 1, NB), 256>>>(x, b_red, w_wt, b_wt);
    k_ul_mma<<<dim3(32, 4, NB), 256>>>(b_u, b_lam);
    k_scan<<<dim3(256, NB), 512>>>(x);
    k_merge_mma<<<dim3(32, 1, NB), 512, MG_SMEM>>>(out, b_merge);
}

// round 9
// speedup vs baseline: 2.9179x; 1.1716x over previous
#include <cuda_runtime.h>
#include <cuda_bf16.h>
#include <cuda_fp16.h>

#define S 64
#define NB 8
#define C 256
#define CR 64
#define P 4096   // S*S per plane

typedef unsigned int u32;

// ---- scratch (device globals; no runtime allocation allowed) ----
__device__ __nv_bfloat16 g_red_hi[NB * CR * P];      // 4 MB
__device__ __nv_bfloat16 g_red_lo[NB * CR * P];      // 4 MB
__device__ float g_u  [NB * C * P];                  // 32 MB
__device__ float g_lam[NB * C * P];                  // 32 MB
__device__ float g_Rv [NB * P];                      // 128 KB
__device__ __half g_K [NB * 512 * P];                // 32 MB fp16 (0..255 = A dir, 256..511 = B dir)
__device__ __half g_Wf[256 * 1024];                  // merge W fp16: row = [hi(512) | lo(512)]
__device__ __nv_bfloat16 g_Wul [512 * 128];          // u/lam W: row = [hi(64) | lo(64)]
__device__ __nv_bfloat16 g_Wred[64 * 512];           // red  W: row = [hi(256) | lo(256)]

// ---- helpers ----
__device__ __forceinline__ u32 sptr(const void* p) {
    return (u32)__cvta_generic_to_shared(p);
}
__device__ __forceinline__ void ldm_x4(u32* r, u32 addr) {
    asm volatile("ldmatrix.sync.aligned.m8n8.x4.shared.b16 {%0,%1,%2,%3}, [%4];"
                 : "=r"(r[0]), "=r"(r[1]), "=r"(r[2]), "=r"(r[3]) : "r"(addr));
}
__device__ __forceinline__ void ldm_x4_t(u32* r, u32 addr) {
    asm volatile("ldmatrix.sync.aligned.m8n8.x4.trans.shared.b16 {%0,%1,%2,%3}, [%4];"
                 : "=r"(r[0]), "=r"(r[1]), "=r"(r[2]), "=r"(r[3]) : "r"(addr));
}
__device__ __forceinline__ void mma16816(float* d, const u32* a, u32 b0, u32 b1) {
    asm volatile("mma.sync.aligned.m16n8k16.row.col.f32.bf16.bf16.f32 "
                 "{%0,%1,%2,%3}, {%4,%5,%6,%7}, {%8,%9}, {%0,%1,%2,%3};"
                 : "+f"(d[0]), "+f"(d[1]), "+f"(d[2]), "+f"(d[3])
                 : "r"(a[0]), "r"(a[1]), "r"(a[2]), "r"(a[3]), "r"(b0), "r"(b1));
}
__device__ __forceinline__ void mma16816h(float* d, const u32* a, u32 b0, u32 b1) {
    asm volatile("mma.sync.aligned.m16n8k16.row.col.f32.f16.f16.f32 "
                 "{%0,%1,%2,%3}, {%4,%5,%6,%7}, {%8,%9}, {%0,%1,%2,%3};"
                 : "+f"(d[0]), "+f"(d[1]), "+f"(d[2]), "+f"(d[3])
                 : "r"(a[0]), "r"(a[1]), "r"(a[2]), "r"(a[3]), "r"(b0), "r"(b1));
}
__device__ __forceinline__ void split_bf(float v, __nv_bfloat16& hi, __nv_bfloat16& lo) {
    hi = __float2bfloat16(v);
    lo = __float2bfloat16(v - __bfloat162float(hi));
}
__device__ __forceinline__ void split_h(float v, __half& hi, __half& lo) {
    hi = __float2half(v);
    lo = __float2half(v - __half2float(hi));
}
__device__ __forceinline__ void cp16(u32 dst, const void* src) {
    asm volatile("cp.async.cg.shared.global [%0], [%1], 16;" :: "r"(dst), "l"(src));
}

// ============================================================
// Prep: fold merge weights (fp16 hi/lo); bf16-split red/ul weights.
// ============================================================
__global__ void k_prep(const float* __restrict__ wm,
                       const float* __restrict__ wu,
                       const float* __restrict__ wl,
                       const float* __restrict__ wr) {
    int i = blockIdx.x * 256 + threadIdx.x;
    if (i < 131072) {
        int o = i >> 9, k = i & 511;
        float v = wm[o * 1024 + k] + wm[o * 1024 + k + 512];
        __half hi, lo; split_h(v, hi, lo);
        g_Wf[o * 1024 + k]       = hi;
        g_Wf[o * 1024 + 512 + k] = lo;
    } else if (i < 163840) {
        int j = i - 131072;
        int m = j >> 6, k = j & 63;
        float v = (m < 256) ? wu[m * 64 + k] : wl[(m - 256) * 64 + k];
        __nv_bfloat16 hi, lo; split_bf(v, hi, lo);
        g_Wul[m * 128 + k]      = hi;
        g_Wul[m * 128 + 64 + k] = lo;
    } else if (i < 180224) {
        int j = i - 163840;
        int m = j >> 8, k = j & 255;
        float v = wr[m * 256 + k];
        __nv_bfloat16 hi, lo; split_bf(v, hi, lo);
        g_Wred[m * 512 + k]       = hi;
        g_Wred[m * 512 + 256 + k] = lo;
    }
}

// ============================================================
// K1 (tensor mma.sync bf16 3-term): reduced = w_red @ x + b_red.
// Fused epilogue: emits g_red_hi/lo AND Rv.
// ============================================================
__global__ __launch_bounds__(256) void k_red_mma(const float* __restrict__ x,
                                                 const float* __restrict__ bred,
                                                 const float* __restrict__ wwt,
                                                 const float* __restrict__ bwt) {
    __shared__ __align__(16) char arena[33792];
    __nv_bfloat16* As_hi = (__nv_bfloat16*)(arena);
    __nv_bfloat16* As_lo = (__nv_bfloat16*)(arena + 5120);
    __nv_bfloat16* Bs_hi = (__nv_bfloat16*)(arena + 10240);
    __nv_bfloat16* Bs_lo = (__nv_bfloat16*)(arena + 18944);
    float* redT = (float*)arena;
    __shared__ float ws[192];
    __shared__ float bs3[3];

    int b  = blockIdx.z;
    int p0 = blockIdx.x * 128;
    int tid = threadIdx.x;
    int wid = tid >> 5, lane = tid & 31;
    int wm = wid & 3;
    int wn = wid >> 2;
    for (int i = tid; i < 192; i += 256) ws[i] = wwt[i];
    if (tid < 3) bs3[tid] = bwt[tid];

    float acc[8][4];
#pragma unroll
    for (int i = 0; i < 8; i++)
#pragma unroll
        for (int q = 0; q < 4; q++) acc[i][q] = 0.f;

    const float* xb = x + (size_t)b * C * P;
    for (int k0 = 0; k0 < 256; k0 += 32) {
        {
            int row = tid >> 2, q = tid & 3;
            *(uint4*)&As_hi[row * 40 + q * 8] =
                *(const uint4*)(g_Wred + row * 512 + k0 + q * 8);
            *(uint4*)&As_lo[row * 40 + q * 8] =
                *(const uint4*)(g_Wred + row * 512 + 256 + k0 + q * 8);
        }
#pragma unroll
        for (int l = 0; l < 4; l++) {
            int cid = tid + l * 256;
            int kk = cid >> 5, pq = cid & 31;
            float4 v = *(const float4*)(xb + (size_t)(k0 + kk) * P + p0 + pq * 4);
            __nv_bfloat162 h0, h1, l0, l1;
            h0.x = __float2bfloat16(v.x); h0.y = __float2bfloat16(v.y);
            h1.x = __float2bfloat16(v.z); h1.y = __float2bfloat16(v.w);
            l0.x = __float2bfloat16(v.x - __bfloat162float(h0.x));
            l0.y = __float2bfloat16(v.y - __bfloat162float(h0.y));
            l1.x = __float2bfloat16(v.z - __bfloat162float(h1.x));
            l1.y = __float2bfloat16(v.w - __bfloat162float(h1.y));
            *(__nv_bfloat162*)&Bs_hi[kk * 136 + pq * 4]     = h0;
            *(__nv_bfloat162*)&Bs_hi[kk * 136 + pq * 4 + 2] = h1;
            *(__nv_bfloat162*)&Bs_lo[kk * 136 + pq * 4]     = l0;
            *(__nv_bfloat162*)&Bs_lo[kk * 136 + pq * 4 + 2] = l1;
        }
        __syncthreads();
#pragma unroll
        for (int ks = 0; ks < 2; ks++) {
            int kk = ks * 16;
            u32 ah[4], al[4], bh[4][4], bl[4][4];
            ldm_x4(ah, sptr(&As_hi[(wm * 16 + (lane & 15)) * 40 + kk + (lane >> 4) * 8]));
            ldm_x4(al, sptr(&As_lo[(wm * 16 + (lane & 15)) * 40 + kk + (lane >> 4) * 8]));
#pragma unroll
            for (int nh = 0; nh < 4; nh++) {
                ldm_x4_t(bh[nh], sptr(&Bs_hi[(kk + (lane & 15)) * 136
                                             + wn * 64 + nh * 16 + (lane >> 4) * 8]));
                ldm_x4_t(bl[nh], sptr(&Bs_lo[(kk + (lane & 15)) * 136
                                             + wn * 64 + nh * 16 + (lane >> 4) * 8]));
            }
#pragma unroll
            for (int nf = 0; nf < 8; nf++) {
                u32 b0h = bh[nf >> 1][(nf & 1) * 2], b1h = bh[nf >> 1][(nf & 1) * 2 + 1];
                u32 b0l = bl[nf >> 1][(nf & 1) * 2], b1l = bl[nf >> 1][(nf & 1) * 2 + 1];
                mma16816(acc[nf], ah, b0h, b1h);
                mma16816(acc[nf], al, b0h, b1h);
                mma16816(acc[nf], ah, b0l, b1l);
            }
        }
        __syncthreads();
    }

    int g = lane >> 2, tg = lane & 3;
    int m1 = wm * 16 + g;
    float bsA = __ldg(bred + m1), bsB = __ldg(bred + m1 + 8);
#pragma unroll
    for (int nf = 0; nf < 8; nf++) {
        int p = wn * 64 + nf * 8 + tg * 2;
        float v0 = acc[nf][0] + bsA, v1 = acc[nf][1] + bsA;
        float v2 = acc[nf][2] + bsB, v3 = acc[nf][3] + bsB;
        *(float2*)&redT[m1 * 132 + p]       = make_float2(v0, v1);
        *(float2*)&redT[(m1 + 8) * 132 + p] = make_float2(v2, v3);
        size_t off0 = ((size_t)b * CR + m1) * P + p0 + p;
        size_t off1 = ((size_t)b * CR + m1 + 8) * P + p0 + p;
        __nv_bfloat16 h0, l0, h1, l1;
        __nv_bfloat162 hh, ll;
        split_bf(v0, h0, l0); split_bf(v1, h1, l1);
        hh.x = h0; hh.y = h1; ll.x = l0; ll.y = l1;
        *(__nv_bfloat162*)(g_red_hi + off0) = hh;
        *(__nv_bfloat162*)(g_red_lo + off0) = ll;
        split_bf(v2, h0, l0); split_bf(v3, h1, l1);
        hh.x = h0; hh.y = h1; ll.x = l0; ll.y = l1;
        *(__nv_bfloat162*)(g_red_hi + off1) = hh;
        *(__nv_bfloat162*)(g_red_lo + off1) = ll;
    }
    __syncthreads();

    if (tid < 128) {
        int w = tid & 63;
        float a0 = bs3[0], a1 = bs3[1], a2 = bs3[2];
#pragma unroll 16
        for (int m = 0; m < 64; m++) {
            float r = redT[m * 132 + tid];
            a0 += ws[m]       * r;
            a1 += ws[64 + m]  * r;
            a2 += ws[128 + m] * r;
        }
        float s0 = 1.f / (1.f + expf(-a0));
        float s1 = 1.f / (1.f + expf(-a1));
        float s2 = 1.f / (1.f + expf(-a2));
        float den = fmaxf(s0 + s1 + s2, 1e-6f);
        float rv = s1;
        if (w >= 1)     rv += s0;
        if (w <= S - 2) rv += s2;
        g_Rv[(size_t)b * P + p0 + tid] = rv / den;
    }
}

// ============================================================
// K2 (tensor mma.sync bf16 3-term): u (m<256) and lam (m>=256). K=64.
// ============================================================
__global__ __launch_bounds__(256) void k_ul_mma(const float* __restrict__ bu,
                                                const float* __restrict__ bl) {
    __shared__ __align__(16) __nv_bfloat16 As_hi[128 * 40];
    __shared__ __align__(16) __nv_bfloat16 As_lo[128 * 40];
    __shared__ __align__(16) __nv_bfloat16 Bs_hi[32 * 136];
    __shared__ __align__(16) __nv_bfloat16 Bs_lo[32 * 136];
    int b  = blockIdx.z;
    int m0 = blockIdx.y * 128;
    int p0 = blockIdx.x * 128;
    int tid = threadIdx.x;
    int wid = tid >> 5, lane = tid & 31;
    int wm = wid >> 2, wn = wid & 3;
    float acc[4][4][4];
#pragma unroll
    for (int i = 0; i < 4; i++)
#pragma unroll
        for (int j = 0; j < 4; j++)
#pragma unroll
            for (int q = 0; q < 4; q++) acc[i][j][q] = 0.f;

    for (int k0 = 0; k0 < 64; k0 += 32) {
#pragma unroll
        for (int l = 0; l < 2; l++) {
            int cid = tid + l * 256;
            int row = cid >> 2, q = cid & 3;
            *(uint4*)&As_hi[row * 40 + q * 8] =
                *(const uint4*)(g_Wul + (size_t)(m0 + row) * 128 + k0 + q * 8);
            *(uint4*)&As_lo[row * 40 + q * 8] =
                *(const uint4*)(g_Wul + (size_t)(m0 + row) * 128 + 64 + k0 + q * 8);
        }
#pragma unroll
        for (int l = 0; l < 2; l++) {
            int cid = tid + l * 256;
            int kk = cid >> 4, q = cid & 15;
            size_t off = ((size_t)b * CR + k0 + kk) * P + p0 + q * 8;
            *(uint4*)&Bs_hi[kk * 136 + q * 8] = *(const uint4*)(g_red_hi + off);
            *(uint4*)&Bs_lo[kk * 136 + q * 8] = *(const uint4*)(g_red_lo + off);
        }
        __syncthreads();
#pragma unroll
        for (int ks = 0; ks < 2; ks++) {
            int kk = ks * 16;
            u32 bh[2][4], bl2[2][4];
#pragma unroll
            for (int nh = 0; nh < 2; nh++) {
                ldm_x4_t(bh[nh], sptr(&Bs_hi[(kk + (lane & 15)) * 136
                                             + wn * 32 + nh * 16 + (lane >> 4) * 8]));
                ldm_x4_t(bl2[nh], sptr(&Bs_lo[(kk + (lane & 15)) * 136
                                              + wn * 32 + nh * 16 + (lane >> 4) * 8]));
            }
#pragma unroll
            for (int mf = 0; mf < 4; mf++) {
                u32 ah[4], al[4];
                ldm_x4(ah, sptr(&As_hi[(wm * 64 + mf * 16 + (lane & 15)) * 40
                                       + kk + (lane >> 4) * 8]));
                ldm_x4(al, sptr(&As_lo[(wm * 64 + mf * 16 + (lane & 15)) * 40
                                       + kk + (lane >> 4) * 8]));
#pragma unroll
                for (int nf = 0; nf < 4; nf++) {
                    u32 b0h = bh[nf >> 1][(nf & 1) * 2], b1h = bh[nf >> 1][(nf & 1) * 2 + 1];
                    u32 b0l = bl2[nf >> 1][(nf & 1) * 2], b1l = bl2[nf >> 1][(nf & 1) * 2 + 1];
                    mma16816(acc[mf][nf], ah, b0h, b1h);
                    mma16816(acc[mf][nf], al, b0h, b1h);
                    mma16816(acc[mf][nf], ah, b0l, b1l);
                }
            }
        }
        __syncthreads();
    }
    float* outb; const float* biasArr; int mofs;
    if (m0 < 256) { outb = g_u   + (size_t)b * C * P; biasArr = bu; mofs = m0; }
    else          { outb = g_lam + (size_t)b * C * P; biasArr = bl; mofs = m0 - 256; }
    int g = lane >> 2, tg = lane & 3;
#pragma unroll
    for (int mf = 0; mf < 4; mf++) {
        int m1 = mofs + wm * 64 + mf * 16 + g;
#pragma unroll
        for (int nf = 0; nf < 4; nf++) {
            int p = p0 + wn * 32 + nf * 8 + tg * 2;
            float bs1 = biasArr[m1], bs2 = biasArr[m1 + 8];
            *(float2*)(outb + (size_t)m1 * P + p) =
                make_float2(acc[mf][nf][0] + bs1, acc[mf][nf][1] + bs1);
            *(float2*)(outb + (size_t)(m1 + 8) * P + p) =
                make_float2(acc[mf][nf][2] + bs2, acc[mf][nf][3] + bs2);
        }
    }
}

// ============================================================
// K4: fused dual scan along w; outputs single fp16 Kmat planes.
// ============================================================
__global__ __launch_bounds__(512) void k_scan(const float* __restrict__ x) {
    __shared__ float ls[64 * 65];
    int b = blockIdx.y, c = blockIdx.x;
    size_t base = ((size_t)b * C + c) * P;
    const float* xp = x + base;
    const float* up = g_u + base;
    const float* lp = g_lam + base;
    const float* rv = g_Rv + (size_t)b * P;
    __half* AP = g_K + ((size_t)b * 512 + c) * P;
    __half* BP = g_K + ((size_t)b * 512 + 256 + c) * P;
    int tid = threadIdx.x;

#pragma unroll
    for (int l = 0; l < 2; l++) {
        int fid = tid + l * 512;
        int row = fid >> 4, q = fid & 15;
        float4 v = *(const float4*)(lp + row * 64 + q * 4);
        ls[row * 65 + q * 4 + 0] = v.x;
        ls[row * 65 + q * 4 + 1] = v.y;
        ls[row * 65 + q * 4 + 2] = v.z;
        ls[row * 65 + q * 4 + 3] = v.w;
    }
    __syncthreads();

    int wid = tid >> 5, lane = tid & 31;
#pragma unroll
    for (int r = 0; r < 4; r++) {
        int h = wid + r * 16;
        int hb = 63 - h;
        int w0 = lane * 2, w1 = w0 + 1;
        float2 av = *(const float2*)(rv + h * 64 + w0);
        float a0 = av.x, a1 = av.y;
        float2 xv = *(const float2*)(xp + h * 64 + w0);
        float bA0 = ls[w0 * 65 + h] * xv.x;
        float bA1 = ls[w1 * 65 + h] * xv.y;
        float bB0 = ls[(63 - w0) * 65 + hb] * xv.x;
        float bB1 = ls[(63 - w1) * 65 + hb] * xv.y;
        float ca  = a0 * a1;
        float cbA = a1 * bA0 + bA1;
        float cbB = a1 * bB0 + bB1;
#pragma unroll
        for (int d = 1; d < 32; d <<= 1) {
            float pa  = __shfl_up_sync(0xffffffffu, ca,  d);
            float pbA = __shfl_up_sync(0xffffffffu, cbA, d);
            float pbB = __shfl_up_sync(0xffffffffu, cbB, d);
            if (lane >= d) {
                cbA = ca * pbA + cbA;
                cbB = ca * pbB + cbB;
                ca  = ca * pa;
            }
        }
        float eA = __shfl_up_sync(0xffffffffu, cbA, 1);
        float eB = __shfl_up_sync(0xffffffffu, cbB, 1);
        if (lane == 0) { eA = 0.f; eB = 0.f; }
        float hA0 = a0 * eA + bA0;
        float hA1 = a1 * hA0 + bA1;
        float hB0 = a0 * eB + bB0;
        float hB1 = a1 * hB0 + bB1;
        float2 uv  = *(const float2*)(up + h  * 64 + w0);
        float2 uvb = *(const float2*)(up + hb * 64 + w0);
        float oA0 = hA0 * uv.x,  oA1 = hA1 * uv.y;
        float oB0 = hB0 * uvb.x, oB1 = hB1 * uvb.y;
        *(__half2*)(AP + h * 64 + w0) = __floats2half2_rn(oA0, oA1);
        *(__half2*)(BP + h * 64 + w0) = __floats2half2_rn(oB0, oB1);
    }
}

// ============================================================
// K5 (tensor mma.sync fp16 2-term): out = Wf @ Kmat + bias. K=512.
// CTA tile M=256 (full) x N=128, 512 threads (16 warps, 4x4),
// warp tile 64x32, cp.async double-buffered.
// A = fp16 weight hi/lo (exact split); B = single fp16 Kmat.
// Dynamic smem: 2 x (A hi+lo 40KB) + 2 x (B 8.5KB) = 99328 B.
// ============================================================
#define MG_A_BUF 40960              // bytes per A buffer (hi 20480 + lo 20480)
#define MG_B_BASE 81920
#define MG_B_BUF 8704               // bytes per B buffer (single)
#define MG_SMEM 99328

__global__ __launch_bounds__(512) void k_merge_mma(float* __restrict__ out,
                                                   const float* __restrict__ bm) {
    extern __shared__ __align__(16) char dsm[];
    int b  = blockIdx.z;
    int p0 = blockIdx.x * 128;
    int tid = threadIdx.x;
    int wid = tid >> 5, lane = tid & 31;
    int wm = wid >> 2, wn = wid & 3;        // 4 m-slots x 4 n-slots

    float acc[4][4][4];
#pragma unroll
    for (int i = 0; i < 4; i++)
#pragma unroll
        for (int j = 0; j < 4; j++)
#pragma unroll
            for (int q = 0; q < 4; q++) acc[i][j][q] = 0.f;

    // per-thread load coords
    int a_row0 = tid >> 2, a_q = tid & 3;               // + l*128 rows
    int b_kk = tid >> 4, b_q = tid & 15;

    // prologue: chunk 0
    {
        char* Abuf = dsm;
        char* Bbuf = dsm + MG_B_BASE;
#pragma unroll
        for (int l = 0; l < 2; l++) {
            int row = a_row0 + l * 128;
            cp16(sptr(Abuf + (row * 40 + a_q * 8) * 2),
                 g_Wf + (size_t)row * 1024 + a_q * 8);
            cp16(sptr(Abuf + 20480 + (row * 40 + a_q * 8) * 2),
                 g_Wf + (size_t)row * 1024 + 512 + a_q * 8);
        }
        size_t off = ((size_t)b * 512 + b_kk) * P + p0 + b_q * 8;
        cp16(sptr(Bbuf + (b_kk * 136 + b_q * 8) * 2), g_K + off);
        asm volatile("cp.async.commit_group;");
    }

    for (int i = 0; i < 16; i++) {
        if (i + 1 < 16) {
            int k0 = (i + 1) * 32;
            char* Abuf = dsm + ((i + 1) & 1) * MG_A_BUF;
            char* Bbuf = dsm + MG_B_BASE + ((i + 1) & 1) * MG_B_BUF;
#pragma unroll
            for (int l = 0; l < 2; l++) {
                int row = a_row0 + l * 128;
                cp16(sptr(Abuf + (row * 40 + a_q * 8) * 2),
                     g_Wf + (size_t)row * 1024 + k0 + a_q * 8);
                cp16(sptr(Abuf + 20480 + (row * 40 + a_q * 8) * 2),
                     g_Wf + (size_t)row * 1024 + 512 + k0 + a_q * 8);
            }
            size_t off = ((size_t)b * 512 + k0 + b_kk) * P + p0 + b_q * 8;
            cp16(sptr(Bbuf + (b_kk * 136 + b_q * 8) * 2), g_K + off);
            asm volatile("cp.async.commit_group;");
            asm volatile("cp.async.wait_group 1;");
        } else {
            asm volatile("cp.async.wait_group 0;");
        }
        __syncthreads();

        const __half* Ah = (const __half*)(dsm + (i & 1) * MG_A_BUF);
        const __half* Al = (const __half*)(dsm + (i & 1) * MG_A_BUF + 20480);
        const __half* Bh = (const __half*)(dsm + MG_B_BASE + (i & 1) * MG_B_BUF);
#pragma unroll
        for (int ks = 0; ks < 2; ks++) {
            int kk = ks * 16;
            u32 bh[2][4];
#pragma unroll
            for (int nh = 0; nh < 2; nh++)
                ldm_x4_t(bh[nh], sptr(&Bh[(kk + (lane & 15)) * 136
                                          + wn * 32 + nh * 16 + (lane >> 4) * 8]));
#pragma unroll
            for (int mf = 0; mf < 4; mf++) {
                u32 ah[4], al[4];
                ldm_x4(ah, sptr(&Ah[(wm * 64 + mf * 16 + (lane & 15)) * 40
                                    + kk + (lane >> 4) * 8]));
                ldm_x4(al, sptr(&Al[(wm * 64 + mf * 16 + (lane & 15)) * 40
                                    + kk + (lane >> 4) * 8]));
#pragma unroll
                for (int nf = 0; nf < 4; nf++) {
                    u32 b0 = bh[nf >> 1][(nf & 1) * 2], b1 = bh[nf >> 1][(nf & 1) * 2 + 1];
                    mma16816h(acc[mf][nf], ah, b0, b1);
                    mma16816h(acc[mf][nf], al, b0, b1);
                }
            }
        }
        __syncthreads();
    }

    int g = lane >> 2, tg = lane & 3;
#pragma unroll
    for (int mf = 0; mf < 4; mf++) {
        int m1 = wm * 64 + mf * 16 + g;
#pragma unroll
        for (int nf = 0; nf < 4; nf++) {
            int p = p0 + wn * 32 + nf * 8 + tg * 2;
            float bs1 = bm[m1], bs2 = bm[m1 + 8];
            *(float2*)(out + ((size_t)b * C + m1) * P + p) =
                make_float2(acc[mf][nf][0] + bs1, acc[mf][nf][1] + bs1);
            *(float2*)(out + ((size_t)b * C + m1 + 8) * P + p) =
                make_float2(acc[mf][nf][2] + bs2, acc[mf][nf][3] + bs2);
        }
    }
}

// ============================================================
extern "C" void kernel_launch(void* const* d_in, const int* in_sizes, int n_in,
                              void* d_out, int out_size) {
    const float* x       = (const float*)d_in[0];
    const float* w_red   = (const float*)d_in[1];
    const float* b_red   = (const float*)d_in[2];
    const float* w_u     = (const float*)d_in[3];
    const float* b_u     = (const float*)d_in[4];
    const float* w_lam   = (const float*)d_in[5];
    const float* b_lam   = (const float*)d_in[6];
    const float* w_wt    = (const float*)d_in[7];
    const float* b_wt    = (const float*)d_in[8];
    const float* w_merge = (const float*)d_in[9];
    const float* b_merge = (const float*)d_in[10];
    float* out = (float*)d_out;

    cudaFuncSetAttribute(k_merge_mma,
                         cudaFuncAttributeMaxDynamicSharedMemorySize, MG_SMEM);

    k_prep<<<704, 256>>>(w_merge, w_u, w_lam, w_red);
    k_red_mma<<<dim3(32, 1, NB), 256>>>(x, b_red, w_wt, b_wt);
    k_ul_mma<<<dim3(32, 4, NB), 256>>>(b_u, b_lam);
    k_scan<<<dim3(256, NB), 512>>>(x);
    k_merge_mma<<<dim3(32, 1, NB), 512, MG_SMEM>>>(out, b_merge);
}

// round 10
// speedup vs baseline: 3.2489x; 1.1134x over previous
#include <cuda_runtime.h>
#include <cuda_fp16.h>

#define S 64
#define NB 8
#define C 256
#define CR 64
#define P 4096   // S*S per plane

typedef unsigned int u32;

// ---- scratch (device globals; no runtime allocation allowed) ----
__device__ __half g_red[NB * CR * P];                // 4 MB fp16
__device__ __half g_u  [NB * C * P];                 // 16 MB fp16
__device__ __half g_lam[NB * C * P];                 // 16 MB fp16
__device__ float  g_Rv [NB * P];                     // 128 KB fp32
__device__ __half g_K  [NB * 512 * P];               // 32 MB fp16 (0..255 = A dir, 256..511 = B dir)
__device__ __half g_Wf [256 * 1024];                 // merge W fp16: row = [hi(512) | lo(512)]
__device__ __half g_Wul[512 * 128];                  // u/lam W fp16: row = [hi(64) | lo(64)]
__device__ __half g_Wred[64 * 512];                  // red  W fp16: row = [hi(256) | lo(256)]

// ---- helpers ----
__device__ __forceinline__ u32 sptr(const void* p) {
    return (u32)__cvta_generic_to_shared(p);
}
__device__ __forceinline__ void ldm_x4(u32* r, u32 addr) {
    asm volatile("ldmatrix.sync.aligned.m8n8.x4.shared.b16 {%0,%1,%2,%3}, [%4];"
                 : "=r"(r[0]), "=r"(r[1]), "=r"(r[2]), "=r"(r[3]) : "r"(addr));
}
__device__ __forceinline__ void ldm_x4_t(u32* r, u32 addr) {
    asm volatile("ldmatrix.sync.aligned.m8n8.x4.trans.shared.b16 {%0,%1,%2,%3}, [%4];"
                 : "=r"(r[0]), "=r"(r[1]), "=r"(r[2]), "=r"(r[3]) : "r"(addr));
}
__device__ __forceinline__ void mma16816h(float* d, const u32* a, u32 b0, u32 b1) {
    asm volatile("mma.sync.aligned.m16n8k16.row.col.f32.f16.f16.f32 "
                 "{%0,%1,%2,%3}, {%4,%5,%6,%7}, {%8,%9}, {%0,%1,%2,%3};"
                 : "+f"(d[0]), "+f"(d[1]), "+f"(d[2]), "+f"(d[3])
                 : "r"(a[0]), "r"(a[1]), "r"(a[2]), "r"(a[3]), "r"(b0), "r"(b1));
}
__device__ __forceinline__ void split_h(float v, __half& hi, __half& lo) {
    hi = __float2half(v);
    lo = __float2half(v - __half2float(hi));
}
__device__ __forceinline__ void cp16(u32 dst, const void* src) {
    asm volatile("cp.async.cg.shared.global [%0], [%1], 16;" :: "r"(dst), "l"(src));
}

// ============================================================
// Prep: fold merge weights; fp16 hi/lo split all weight matrices.
// ============================================================
__global__ void k_prep(const float* __restrict__ wm,
                       const float* __restrict__ wu,
                       const float* __restrict__ wl,
                       const float* __restrict__ wr) {
    int i = blockIdx.x * 256 + threadIdx.x;
    if (i < 131072) {
        int o = i >> 9, k = i & 511;
        float v = wm[o * 1024 + k] + wm[o * 1024 + k + 512];
        __half hi, lo; split_h(v, hi, lo);
        g_Wf[o * 1024 + k]       = hi;
        g_Wf[o * 1024 + 512 + k] = lo;
    } else if (i < 163840) {
        int j = i - 131072;
        int m = j >> 6, k = j & 63;
        float v = (m < 256) ? wu[m * 64 + k] : wl[(m - 256) * 64 + k];
        __half hi, lo; split_h(v, hi, lo);
        g_Wul[m * 128 + k]      = hi;
        g_Wul[m * 128 + 64 + k] = lo;
    } else if (i < 180224) {
        int j = i - 163840;
        int m = j >> 8, k = j & 255;
        float v = wr[m * 256 + k];
        __half hi, lo; split_h(v, hi, lo);
        g_Wred[m * 512 + k]       = hi;
        g_Wred[m * 512 + 256 + k] = lo;
    }
}

// ============================================================
// K1 (fp16 2-term): reduced = w_red @ x + b_red.
// A = fp16 hi/lo weights (exact), B = single fp16 x (quantized in-kernel).
// Fused epilogue: writes g_red fp16; computes Rv from fp32 accumulators.
// ============================================================
__global__ __launch_bounds__(256) void k_red_mma(const float* __restrict__ x,
                                                 const float* __restrict__ bred,
                                                 const float* __restrict__ wwt,
                                                 const float* __restrict__ bwt) {
    // arena: main loop tiles (18944B) / fp32 red transpose (33792B)
    __shared__ __align__(16) char arena[33792];
    __half* As_hi = (__half*)(arena);            // 64x40 = 5120B
    __half* As_lo = (__half*)(arena + 5120);
    __half* Bs    = (__half*)(arena + 10240);    // 32x136 = 8704B
    float* redT = (float*)arena;                 // 64x132 fp32
    __shared__ float ws[192];
    __shared__ float bs3[3];

    int b  = blockIdx.z;
    int p0 = blockIdx.x * 128;
    int tid = threadIdx.x;
    int wid = tid >> 5, lane = tid & 31;
    int wm = wid & 3;       // 4 m-slots x 16 rows
    int wn = wid >> 2;      // 2 n-slots x 64 cols
    for (int i = tid; i < 192; i += 256) ws[i] = wwt[i];
    if (tid < 3) bs3[tid] = bwt[tid];

    float acc[8][4];
#pragma unroll
    for (int i = 0; i < 8; i++)
#pragma unroll
        for (int q = 0; q < 4; q++) acc[i][q] = 0.f;

    const float* xb = x + (size_t)b * C * P;
    for (int k0 = 0; k0 < 256; k0 += 32) {
        {   // A chunk: 64 rows x 32 k, hi & lo
            int row = tid >> 2, q = tid & 3;
            *(uint4*)&As_hi[row * 40 + q * 8] =
                *(const uint4*)(g_Wred + row * 512 + k0 + q * 8);
            *(uint4*)&As_lo[row * 40 + q * 8] =
                *(const uint4*)(g_Wred + row * 512 + 256 + k0 + q * 8);
        }
#pragma unroll
        for (int l = 0; l < 2; l++) {   // x chunk 32k x 128p -> fp16
            int cid = tid + l * 256;
            int kk = cid >> 4, pq = cid & 15;
            const float* src = xb + (size_t)(k0 + kk) * P + p0 + pq * 8;
            float4 v0 = *(const float4*)(src);
            float4 v1 = *(const float4*)(src + 4);
            __half2 h[4];
            h[0] = __floats2half2_rn(v0.x, v0.y);
            h[1] = __floats2half2_rn(v0.z, v0.w);
            h[2] = __floats2half2_rn(v1.x, v1.y);
            h[3] = __floats2half2_rn(v1.z, v1.w);
            *(uint4*)&Bs[kk * 136 + pq * 8] = *(uint4*)h;
        }
        __syncthreads();
#pragma unroll
        for (int ks = 0; ks < 2; ks++) {
            int kk = ks * 16;
            u32 ah[4], al[4], bh[4][4];
            ldm_x4(ah, sptr(&As_hi[(wm * 16 + (lane & 15)) * 40 + kk + (lane >> 4) * 8]));
            ldm_x4(al, sptr(&As_lo[(wm * 16 + (lane & 15)) * 40 + kk + (lane >> 4) * 8]));
#pragma unroll
            for (int nh = 0; nh < 4; nh++)
                ldm_x4_t(bh[nh], sptr(&Bs[(kk + (lane & 15)) * 136
                                          + wn * 64 + nh * 16 + (lane >> 4) * 8]));
#pragma unroll
            for (int nf = 0; nf < 8; nf++) {
                u32 b0 = bh[nf >> 1][(nf & 1) * 2], b1 = bh[nf >> 1][(nf & 1) * 2 + 1];
                mma16816h(acc[nf], ah, b0, b1);
                mma16816h(acc[nf], al, b0, b1);
            }
        }
        __syncthreads();
    }

    // ---- epilogue: bias, write fp16 red, stage fp32 tile for Rv ----
    int g = lane >> 2, tg = lane & 3;
    int m1 = wm * 16 + g;
    float bsA = __ldg(bred + m1), bsB = __ldg(bred + m1 + 8);
#pragma unroll
    for (int nf = 0; nf < 8; nf++) {
        int p = wn * 64 + nf * 8 + tg * 2;
        float v0 = acc[nf][0] + bsA, v1 = acc[nf][1] + bsA;
        float v2 = acc[nf][2] + bsB, v3 = acc[nf][3] + bsB;
        *(float2*)&redT[m1 * 132 + p]       = make_float2(v0, v1);
        *(float2*)&redT[(m1 + 8) * 132 + p] = make_float2(v2, v3);
        size_t off0 = ((size_t)b * CR + m1) * P + p0 + p;
        size_t off1 = ((size_t)b * CR + m1 + 8) * P + p0 + p;
        *(__half2*)(g_red + off0) = __floats2half2_rn(v0, v1);
        *(__half2*)(g_red + off1) = __floats2half2_rn(v2, v3);
    }
    __syncthreads();

    // ---- fused Rv ----
    if (tid < 128) {
        int w = tid & 63;
        float a0 = bs3[0], a1 = bs3[1], a2 = bs3[2];
#pragma unroll 16
        for (int m = 0; m < 64; m++) {
            float r = redT[m * 132 + tid];
            a0 += ws[m]       * r;
            a1 += ws[64 + m]  * r;
            a2 += ws[128 + m] * r;
        }
        float s0 = 1.f / (1.f + expf(-a0));
        float s1 = 1.f / (1.f + expf(-a1));
        float s2 = 1.f / (1.f + expf(-a2));
        float den = fmaxf(s0 + s1 + s2, 1e-6f);
        float rv = s1;
        if (w >= 1)     rv += s0;
        if (w <= S - 2) rv += s2;
        g_Rv[(size_t)b * P + p0 + tid] = rv / den;
    }
}

// ============================================================
// K2 (fp16 2-term): u (m<256) and lam (m>=256). K=64.
// Outputs fp16.
// ============================================================
__global__ __launch_bounds__(256) void k_ul_mma(const float* __restrict__ bu,
                                                const float* __restrict__ bl) {
    __shared__ __align__(16) __half As_hi[128 * 40];
    __shared__ __align__(16) __half As_lo[128 * 40];
    __shared__ __align__(16) __half Bs   [32 * 136];
    int b  = blockIdx.z;
    int m0 = blockIdx.y * 128;
    int p0 = blockIdx.x * 128;
    int tid = threadIdx.x;
    int wid = tid >> 5, lane = tid & 31;
    int wm = wid >> 2, wn = wid & 3;
    float acc[4][4][4];
#pragma unroll
    for (int i = 0; i < 4; i++)
#pragma unroll
        for (int j = 0; j < 4; j++)
#pragma unroll
            for (int q = 0; q < 4; q++) acc[i][j][q] = 0.f;

    for (int k0 = 0; k0 < 64; k0 += 32) {
#pragma unroll
        for (int l = 0; l < 2; l++) {   // A: 128 rows x 32 k, hi & lo
            int cid = tid + l * 256;
            int row = cid >> 2, q = cid & 3;
            *(uint4*)&As_hi[row * 40 + q * 8] =
                *(const uint4*)(g_Wul + (size_t)(m0 + row) * 128 + k0 + q * 8);
            *(uint4*)&As_lo[row * 40 + q * 8] =
                *(const uint4*)(g_Wul + (size_t)(m0 + row) * 128 + 64 + k0 + q * 8);
        }
#pragma unroll
        for (int l = 0; l < 2; l++) {   // B: 32 k x 128 p, single fp16
            int cid = tid + l * 256;
            int kk = cid >> 4, q = cid & 15;
            size_t off = ((size_t)b * CR + k0 + kk) * P + p0 + q * 8;
            *(uint4*)&Bs[kk * 136 + q * 8] = *(const uint4*)(g_red + off);
        }
        __syncthreads();
#pragma unroll
        for (int ks = 0; ks < 2; ks++) {
            int kk = ks * 16;
            u32 bh[2][4];
#pragma unroll
            for (int nh = 0; nh < 2; nh++)
                ldm_x4_t(bh[nh], sptr(&Bs[(kk + (lane & 15)) * 136
                                          + wn * 32 + nh * 16 + (lane >> 4) * 8]));
#pragma unroll
            for (int mf = 0; mf < 4; mf++) {
                u32 ah[4], al[4];
                ldm_x4(ah, sptr(&As_hi[(wm * 64 + mf * 16 + (lane & 15)) * 40
                                       + kk + (lane >> 4) * 8]));
                ldm_x4(al, sptr(&As_lo[(wm * 64 + mf * 16 + (lane & 15)) * 40
                                       + kk + (lane >> 4) * 8]));
#pragma unroll
                for (int nf = 0; nf < 4; nf++) {
                    u32 b0 = bh[nf >> 1][(nf & 1) * 2], b1 = bh[nf >> 1][(nf & 1) * 2 + 1];
                    mma16816h(acc[mf][nf], ah, b0, b1);
                    mma16816h(acc[mf][nf], al, b0, b1);
                }
            }
        }
        __syncthreads();
    }
    __half* outb; const float* biasArr; int mofs;
    if (m0 < 256) { outb = g_u   + (size_t)b * C * P; biasArr = bu; mofs = m0; }
    else          { outb = g_lam + (size_t)b * C * P; biasArr = bl; mofs = m0 - 256; }
    int g = lane >> 2, tg = lane & 3;
#pragma unroll
    for (int mf = 0; mf < 4; mf++) {
        int m1 = mofs + wm * 64 + mf * 16 + g;
#pragma unroll
        for (int nf = 0; nf < 4; nf++) {
            int p = p0 + wn * 32 + nf * 8 + tg * 2;
            float bs1 = biasArr[m1], bs2 = biasArr[m1 + 8];
            *(__half2*)(outb + (size_t)m1 * P + p) =
                __floats2half2_rn(acc[mf][nf][0] + bs1, acc[mf][nf][1] + bs1);
            *(__half2*)(outb + (size_t)(m1 + 8) * P + p) =
                __floats2half2_rn(acc[mf][nf][2] + bs2, acc[mf][nf][3] + bs2);
        }
    }
}

// ============================================================
// K4: fused dual scan along w; u/lam fp16 in, fp16 Kmat planes out.
// ============================================================
__global__ __launch_bounds__(512) void k_scan(const float* __restrict__ x) {
    __shared__ float ls[64 * 65];
    int b = blockIdx.y, c = blockIdx.x;
    size_t base = ((size_t)b * C + c) * P;
    const float*  xp = x + base;
    const __half* up = g_u + base;
    const __half* lp = g_lam + base;
    const float*  rv = g_Rv + (size_t)b * P;
    __half* AP = g_K + ((size_t)b * 512 + c) * P;
    __half* BP = g_K + ((size_t)b * 512 + 256 + c) * P;
    int tid = threadIdx.x;

    {   // stage lam plane (4096 fp16) into padded fp32 smem
        int row = tid >> 3, q = tid & 7;
        uint4 raw = *(const uint4*)(lp + row * 64 + q * 8);
        __half2* hp = (__half2*)&raw;
#pragma unroll
        for (int j = 0; j < 4; j++) {
            float2 f = __half22float2(hp[j]);
            ls[row * 65 + q * 8 + j * 2]     = f.x;
            ls[row * 65 + q * 8 + j * 2 + 1] = f.y;
        }
    }
    __syncthreads();

    int wid = tid >> 5, lane = tid & 31;
#pragma unroll
    for (int r = 0; r < 4; r++) {
        int h = wid + r * 16;
        int hb = 63 - h;
        int w0 = lane * 2, w1 = w0 + 1;
        float2 av = *(const float2*)(rv + h * 64 + w0);
        float a0 = av.x, a1 = av.y;
        float2 xv = *(const float2*)(xp + h * 64 + w0);
        float bA0 = ls[w0 * 65 + h] * xv.x;
        float bA1 = ls[w1 * 65 + h] * xv.y;
        float bB0 = ls[(63 - w0) * 65 + hb] * xv.x;
        float bB1 = ls[(63 - w1) * 65 + hb] * xv.y;
        float ca  = a0 * a1;
        float cbA = a1 * bA0 + bA1;
        float cbB = a1 * bB0 + bB1;
#pragma unroll
        for (int d = 1; d < 32; d <<= 1) {
            float pa  = __shfl_up_sync(0xffffffffu, ca,  d);
            float pbA = __shfl_up_sync(0xffffffffu, cbA, d);
            float pbB = __shfl_up_sync(0xffffffffu, cbB, d);
            if (lane >= d) {
                cbA = ca * pbA + cbA;
                cbB = ca * pbB + cbB;
                ca  = ca * pa;
            }
        }
        float eA = __shfl_up_sync(0xffffffffu, cbA, 1);
        float eB = __shfl_up_sync(0xffffffffu, cbB, 1);
        if (lane == 0) { eA = 0.f; eB = 0.f; }
        float hA0 = a0 * eA + bA0;
        float hA1 = a1 * hA0 + bA1;
        float hB0 = a0 * eB + bB0;
        float hB1 = a1 * hB0 + bB1;
        float2 uv  = __half22float2(*(const __half2*)(up + h  * 64 + w0));
        float2 uvb = __half22float2(*(const __half2*)(up + hb * 64 + w0));
        *(__half2*)(AP + h * 64 + w0) = __floats2half2_rn(hA0 * uv.x,  hA1 * uv.y);
        *(__half2*)(BP + h * 64 + w0) = __floats2half2_rn(hB0 * uvb.x, hB1 * uvb.y);
    }
}

// ============================================================
// K5 (fp16 2-term): out = Wf @ Kmat + bias. K=512.
// CTA tile M=256 (full) x N=128, 512 threads (16 warps, 4x4),
// warp tile 64x32, cp.async double-buffered.
// ============================================================
#define MG_A_BUF 40960              // bytes per A buffer (hi 20480 + lo 20480)
#define MG_B_BASE 81920
#define MG_B_BUF 8704               // bytes per B buffer (single)
#define MG_SMEM 99328

__global__ __launch_bounds__(512) void k_merge_mma(float* __restrict__ out,
                                                   const float* __restrict__ bm) {
    extern __shared__ __align__(16) char dsm[];
    int b  = blockIdx.z;
    int p0 = blockIdx.x * 128;
    int tid = threadIdx.x;
    int wid = tid >> 5, lane = tid & 31;
    int wm = wid >> 2, wn = wid & 3;

    float acc[4][4][4];
#pragma unroll
    for (int i = 0; i < 4; i++)
#pragma unroll
        for (int j = 0; j < 4; j++)
#pragma unroll
            for (int q = 0; q < 4; q++) acc[i][j][q] = 0.f;

    int a_row0 = tid >> 2, a_q = tid & 3;
    int b_kk = tid >> 4, b_q = tid & 15;

    {
        char* Abuf = dsm;
        char* Bbuf = dsm + MG_B_BASE;
#pragma unroll
        for (int l = 0; l < 2; l++) {
            int row = a_row0 + l * 128;
            cp16(sptr(Abuf + (row * 40 + a_q * 8) * 2),
                 g_Wf + (size_t)row * 1024 + a_q * 8);
            cp16(sptr(Abuf + 20480 + (row * 40 + a_q * 8) * 2),
                 g_Wf + (size_t)row * 1024 + 512 + a_q * 8);
        }
        size_t off = ((size_t)b * 512 + b_kk) * P + p0 + b_q * 8;
        cp16(sptr(Bbuf + (b_kk * 136 + b_q * 8) * 2), g_K + off);
        asm volatile("cp.async.commit_group;");
    }

    for (int i = 0; i < 16; i++) {
        if (i + 1 < 16) {
            int k0 = (i + 1) * 32;
            char* Abuf = dsm + ((i + 1) & 1) * MG_A_BUF;
            char* Bbuf = dsm + MG_B_BASE + ((i + 1) & 1) * MG_B_BUF;
#pragma unroll
            for (int l = 0; l < 2; l++) {
                int row = a_row0 + l * 128;
                cp16(sptr(Abuf + (row * 40 + a_q * 8) * 2),
                     g_Wf + (size_t)row * 1024 + k0 + a_q * 8);
                cp16(sptr(Abuf + 20480 + (row * 40 + a_q * 8) * 2),
                     g_Wf + (size_t)row * 1024 + 512 + k0 + a_q * 8);
            }
            size_t off = ((size_t)b * 512 + k0 + b_kk) * P + p0 + b_q * 8;
            cp16(sptr(Bbuf + (b_kk * 136 + b_q * 8) * 2), g_K + off);
            asm volatile("cp.async.commit_group;");
            asm volatile("cp.async.wait_group 1;");
        } else {
            asm volatile("cp.async.wait_group 0;");
        }
        __syncthreads();

        const __half* Ah = (const __half*)(dsm + (i & 1) * MG_A_BUF);
        const __half* Al = (const __half*)(dsm + (i & 1) * MG_A_BUF + 20480);
        const __half* Bh = (const __half*)(dsm + MG_B_BASE + (i & 1) * MG_B_BUF);
#pragma unroll
        for (int ks = 0; ks < 2; ks++) {
            int kk = ks * 16;
            u32 bh[2][4];
#pragma unroll
            for (int nh = 0; nh < 2; nh++)
                ldm_x4_t(bh[nh], sptr(&Bh[(kk + (lane & 15)) * 136
                                          + wn * 32 + nh * 16 + (lane >> 4) * 8]));
#pragma unroll
            for (int mf = 0; mf < 4; mf++) {
                u32 ah[4], al[4];
                ldm_x4(ah, sptr(&Ah[(wm * 64 + mf * 16 + (lane & 15)) * 40
                                    + kk + (lane >> 4) * 8]));
                ldm_x4(al, sptr(&Al[(wm * 64 + mf * 16 + (lane & 15)) * 40
                                    + kk + (lane >> 4) * 8]));
#pragma unroll
                for (int nf = 0; nf < 4; nf++) {
                    u32 b0 = bh[nf >> 1][(nf & 1) * 2], b1 = bh[nf >> 1][(nf & 1) * 2 + 1];
                    mma16816h(acc[mf][nf], ah, b0, b1);
                    mma16816h(acc[mf][nf], al, b0, b1);
                }
            }
        }
        __syncthreads();
    }

    int g = lane >> 2, tg = lane & 3;
#pragma unroll
    for (int mf = 0; mf < 4; mf++) {
        int m1 = wm * 64 + mf * 16 + g;
#pragma unroll
        for (int nf = 0; nf < 4; nf++) {
            int p = p0 + wn * 32 + nf * 8 + tg * 2;
            float bs1 = bm[m1], bs2 = bm[m1 + 8];
            *(float2*)(out + ((size_t)b * C + m1) * P + p) =
                make_float2(acc[mf][nf][0] + bs1, acc[mf][nf][1] + bs1);
            *(float2*)(out + ((size_t)b * C + m1 + 8) * P + p) =
                make_float2(acc[mf][nf][2] + bs2, acc[mf][nf][3] + bs2);
        }
    }
}

// ============================================================
extern "C" void kernel_launch(void* const* d_in, const int* in_sizes, int n_in,
                              void* d_out, int out_size) {
    const float* x       = (const float*)d_in[0];
    const float* w_red   = (const float*)d_in[1];
    const float* b_red   = (const float*)d_in[2];
    const float* w_u     = (const float*)d_in[3];
    const float* b_u     = (const float*)d_in[4];
    const float* w_lam   = (const float*)d_in[5];
    const float* b_lam   = (const float*)d_in[6];
    const float* w_wt    = (const float*)d_in[7];
    const float* b_wt    = (const float*)d_in[8];
    const float* w_merge = (const float*)d_in[9];
    const float* b_merge = (const float*)d_in[10];
    float* out = (float*)d_out;

    cudaFuncSetAttribute(k_merge_mma,
                         cudaFuncAttributeMaxDynamicSharedMemorySize, MG_SMEM);

    k_prep<<<704, 256>>>(w_merge, w_u, w_lam, w_red);
    k_red_mma<<<dim3(32, 1, NB), 256>>>(x, b_red, w_wt, b_wt);
    k_ul_mma<<<dim3(32, 4, NB), 256>>>(b_u, b_lam);
    k_scan<<<dim3(256, NB), 512>>>(x);
    k_merge_mma<<<dim3(32, 1, NB), 512, MG_SMEM>>>(out, b_merge);
}

// round 11
// speedup vs baseline: 4.1713x; 1.2839x over previous
#include <cuda_runtime.h>
#include <cuda_fp16.h>

#define S 64
#define NB 8
#define C 256
#define CR 64
#define P 4096   // S*S per plane

typedef unsigned int u32;

// ---- scratch (device globals; no runtime allocation allowed) ----
__device__ __half g_red[NB * CR * P];                // 4 MB fp16
__device__ __half g_u  [NB * C * P];                 // 16 MB fp16
__device__ __half g_lam[NB * C * P];                 // 16 MB fp16
__device__ float  g_Rv [NB * P];                     // 128 KB fp32
__device__ __half g_K  [NB * 512 * P];               // 32 MB fp16 (0..255 = A dir, 256..511 = B dir)
__device__ __half g_Wf [256 * 512];                  // merge W fp16 (folded)
__device__ __half g_Wul[512 * 64];                   // u/lam W fp16
__device__ __half g_Wred[64 * 256];                  // red  W fp16

// ---- helpers ----
__device__ __forceinline__ u32 sptr(const void* p) {
    return (u32)__cvta_generic_to_shared(p);
}
__device__ __forceinline__ void ldm_x4(u32* r, u32 addr) {
    asm volatile("ldmatrix.sync.aligned.m8n8.x4.shared.b16 {%0,%1,%2,%3}, [%4];"
                 : "=r"(r[0]), "=r"(r[1]), "=r"(r[2]), "=r"(r[3]) : "r"(addr));
}
__device__ __forceinline__ void ldm_x4_t(u32* r, u32 addr) {
    asm volatile("ldmatrix.sync.aligned.m8n8.x4.trans.shared.b16 {%0,%1,%2,%3}, [%4];"
                 : "=r"(r[0]), "=r"(r[1]), "=r"(r[2]), "=r"(r[3]) : "r"(addr));
}
__device__ __forceinline__ void mma16816h(float* d, const u32* a, u32 b0, u32 b1) {
    asm volatile("mma.sync.aligned.m16n8k16.row.col.f32.f16.f16.f32 "
                 "{%0,%1,%2,%3}, {%4,%5,%6,%7}, {%8,%9}, {%0,%1,%2,%3};"
                 : "+f"(d[0]), "+f"(d[1]), "+f"(d[2]), "+f"(d[3])
                 : "r"(a[0]), "r"(a[1]), "r"(a[2]), "r"(a[3]), "r"(b0), "r"(b1));
}
__device__ __forceinline__ void cp16(u32 dst, const void* src) {
    asm volatile("cp.async.cg.shared.global [%0], [%1], 16;" :: "r"(dst), "l"(src));
}

// ============================================================
// Prep: fold merge weights; all weights -> single fp16.
// ============================================================
__global__ void k_prep(const float* __restrict__ wm,
                       const float* __restrict__ wu,
                       const float* __restrict__ wl,
                       const float* __restrict__ wr) {
    int i = blockIdx.x * 256 + threadIdx.x;
    if (i < 131072) {
        int o = i >> 9, k = i & 511;
        float v = wm[o * 1024 + k] + wm[o * 1024 + k + 512];
        g_Wf[o * 512 + k] = __float2half(v);
    } else if (i < 163840) {
        int j = i - 131072;
        int m = j >> 6, k = j & 63;
        float v = (m < 256) ? wu[m * 64 + k] : wl[(m - 256) * 64 + k];
        g_Wul[m * 64 + k] = __float2half(v);
    } else if (i < 180224) {
        int j = i - 163840;
        int m = j >> 8, k = j & 255;
        g_Wred[m * 256 + k] = __float2half(wr[m * 256 + k]);
    }
}

// ============================================================
// K1 (fp16 1-term): reduced = w_red @ x + b_red.
// Fused epilogue: writes g_red fp16; computes Rv from fp32 accumulators.
// ============================================================
__global__ __launch_bounds__(256) void k_red_mma(const float* __restrict__ x,
                                                 const float* __restrict__ bred,
                                                 const float* __restrict__ wwt,
                                                 const float* __restrict__ bwt) {
    // arena: main loop tiles (13824B) / fp32 red transpose (33792B)
    __shared__ __align__(16) char arena[33792];
    __half* As = (__half*)(arena);               // 64x40 = 5120B
    __half* Bs = (__half*)(arena + 5120);        // 32x136 = 8704B
    float* redT = (float*)arena;                 // 64x132 fp32
    __shared__ float ws[192];
    __shared__ float bs3[3];

    int b  = blockIdx.z;
    int p0 = blockIdx.x * 128;
    int tid = threadIdx.x;
    int wid = tid >> 5, lane = tid & 31;
    int wm = wid & 3;       // 4 m-slots x 16 rows
    int wn = wid >> 2;      // 2 n-slots x 64 cols
    for (int i = tid; i < 192; i += 256) ws[i] = wwt[i];
    if (tid < 3) bs3[tid] = bwt[tid];

    float acc[8][4];
#pragma unroll
    for (int i = 0; i < 8; i++)
#pragma unroll
        for (int q = 0; q < 4; q++) acc[i][q] = 0.f;

    const float* xb = x + (size_t)b * C * P;
    for (int k0 = 0; k0 < 256; k0 += 32) {
        {   // A chunk: 64 rows x 32 k
            int row = tid >> 2, q = tid & 3;
            *(uint4*)&As[row * 40 + q * 8] =
                *(const uint4*)(g_Wred + row * 256 + k0 + q * 8);
        }
#pragma unroll
        for (int l = 0; l < 2; l++) {   // x chunk 32k x 128p -> fp16
            int cid = tid + l * 256;
            int kk = cid >> 4, pq = cid & 15;
            const float* src = xb + (size_t)(k0 + kk) * P + p0 + pq * 8;
            float4 v0 = *(const float4*)(src);
            float4 v1 = *(const float4*)(src + 4);
            __half2 h[4];
            h[0] = __floats2half2_rn(v0.x, v0.y);
            h[1] = __floats2half2_rn(v0.z, v0.w);
            h[2] = __floats2half2_rn(v1.x, v1.y);
            h[3] = __floats2half2_rn(v1.z, v1.w);
            *(uint4*)&Bs[kk * 136 + pq * 8] = *(uint4*)h;
        }
        __syncthreads();
#pragma unroll
        for (int ks = 0; ks < 2; ks++) {
            int kk = ks * 16;
            u32 ah[4], bh[4][4];
            ldm_x4(ah, sptr(&As[(wm * 16 + (lane & 15)) * 40 + kk + (lane >> 4) * 8]));
#pragma unroll
            for (int nh = 0; nh < 4; nh++)
                ldm_x4_t(bh[nh], sptr(&Bs[(kk + (lane & 15)) * 136
                                          + wn * 64 + nh * 16 + (lane >> 4) * 8]));
#pragma unroll
            for (int nf = 0; nf < 8; nf++) {
                u32 b0 = bh[nf >> 1][(nf & 1) * 2], b1 = bh[nf >> 1][(nf & 1) * 2 + 1];
                mma16816h(acc[nf], ah, b0, b1);
            }
        }
        __syncthreads();
    }

    // ---- epilogue: bias, write fp16 red, stage fp32 tile for Rv ----
    int g = lane >> 2, tg = lane & 3;
    int m1 = wm * 16 + g;
    float bsA = __ldg(bred + m1), bsB = __ldg(bred + m1 + 8);
#pragma unroll
    for (int nf = 0; nf < 8; nf++) {
        int p = wn * 64 + nf * 8 + tg * 2;
        float v0 = acc[nf][0] + bsA, v1 = acc[nf][1] + bsA;
        float v2 = acc[nf][2] + bsB, v3 = acc[nf][3] + bsB;
        *(float2*)&redT[m1 * 132 + p]       = make_float2(v0, v1);
        *(float2*)&redT[(m1 + 8) * 132 + p] = make_float2(v2, v3);
        size_t off0 = ((size_t)b * CR + m1) * P + p0 + p;
        size_t off1 = ((size_t)b * CR + m1 + 8) * P + p0 + p;
        *(__half2*)(g_red + off0) = __floats2half2_rn(v0, v1);
        *(__half2*)(g_red + off1) = __floats2half2_rn(v2, v3);
    }
    __syncthreads();

    // ---- fused Rv ----
    if (tid < 128) {
        int w = tid & 63;
        float a0 = bs3[0], a1 = bs3[1], a2 = bs3[2];
#pragma unroll 16
        for (int m = 0; m < 64; m++) {
            float r = redT[m * 132 + tid];
            a0 += ws[m]       * r;
            a1 += ws[64 + m]  * r;
            a2 += ws[128 + m] * r;
        }
        float s0 = 1.f / (1.f + expf(-a0));
        float s1 = 1.f / (1.f + expf(-a1));
        float s2 = 1.f / (1.f + expf(-a2));
        float den = fmaxf(s0 + s1 + s2, 1e-6f);
        float rv = s1;
        if (w >= 1)     rv += s0;
        if (w <= S - 2) rv += s2;
        g_Rv[(size_t)b * P + p0 + tid] = rv / den;
    }
}

// ============================================================
// K2 (fp16 1-term): u (m<256) and lam (m>=256). K=64. Outputs fp16.
// ============================================================
__global__ __launch_bounds__(256) void k_ul_mma(const float* __restrict__ bu,
                                                const float* __restrict__ bl) {
    __shared__ __align__(16) __half As[128 * 40];
    __shared__ __align__(16) __half Bs[32 * 136];
    int b  = blockIdx.z;
    int m0 = blockIdx.y * 128;
    int p0 = blockIdx.x * 128;
    int tid = threadIdx.x;
    int wid = tid >> 5, lane = tid & 31;
    int wm = wid >> 2, wn = wid & 3;
    float acc[4][4][4];
#pragma unroll
    for (int i = 0; i < 4; i++)
#pragma unroll
        for (int j = 0; j < 4; j++)
#pragma unroll
            for (int q = 0; q < 4; q++) acc[i][j][q] = 0.f;

    for (int k0 = 0; k0 < 64; k0 += 32) {
#pragma unroll
        for (int l = 0; l < 2; l++) {   // A: 128 rows x 32 k
            int cid = tid + l * 256;
            int row = cid >> 2, q = cid & 3;
            *(uint4*)&As[row * 40 + q * 8] =
                *(const uint4*)(g_Wul + (size_t)(m0 + row) * 64 + k0 + q * 8);
        }
#pragma unroll
        for (int l = 0; l < 2; l++) {   // B: 32 k x 128 p
            int cid = tid + l * 256;
            int kk = cid >> 4, q = cid & 15;
            size_t off = ((size_t)b * CR + k0 + kk) * P + p0 + q * 8;
            *(uint4*)&Bs[kk * 136 + q * 8] = *(const uint4*)(g_red + off);
        }
        __syncthreads();
#pragma unroll
        for (int ks = 0; ks < 2; ks++) {
            int kk = ks * 16;
            u32 bh[2][4];
#pragma unroll
            for (int nh = 0; nh < 2; nh++)
                ldm_x4_t(bh[nh], sptr(&Bs[(kk + (lane & 15)) * 136
                                          + wn * 32 + nh * 16 + (lane >> 4) * 8]));
#pragma unroll
            for (int mf = 0; mf < 4; mf++) {
                u32 ah[4];
                ldm_x4(ah, sptr(&As[(wm * 64 + mf * 16 + (lane & 15)) * 40
                                    + kk + (lane >> 4) * 8]));
#pragma unroll
                for (int nf = 0; nf < 4; nf++) {
                    u32 b0 = bh[nf >> 1][(nf & 1) * 2], b1 = bh[nf >> 1][(nf & 1) * 2 + 1];
                    mma16816h(acc[mf][nf], ah, b0, b1);
                }
            }
        }
        __syncthreads();
    }
    __half* outb; const float* biasArr; int mofs;
    if (m0 < 256) { outb = g_u   + (size_t)b * C * P; biasArr = bu; mofs = m0; }
    else          { outb = g_lam + (size_t)b * C * P; biasArr = bl; mofs = m0 - 256; }
    int g = lane >> 2, tg = lane & 3;
#pragma unroll
    for (int mf = 0; mf < 4; mf++) {
        int m1 = mofs + wm * 64 + mf * 16 + g;
#pragma unroll
        for (int nf = 0; nf < 4; nf++) {
            int p = p0 + wn * 32 + nf * 8 + tg * 2;
            float bs1 = biasArr[m1], bs2 = biasArr[m1 + 8];
            *(__half2*)(outb + (size_t)m1 * P + p) =
                __floats2half2_rn(acc[mf][nf][0] + bs1, acc[mf][nf][1] + bs1);
            *(__half2*)(outb + (size_t)(m1 + 8) * P + p) =
                __floats2half2_rn(acc[mf][nf][2] + bs2, acc[mf][nf][3] + bs2);
        }
    }
}

// ============================================================
// K4: fused dual scan along w; u/lam fp16 in, fp16 Kmat planes out.
// ============================================================
__global__ __launch_bounds__(512) void k_scan(const float* __restrict__ x) {
    __shared__ float ls[64 * 65];
    int b = blockIdx.y, c = blockIdx.x;
    size_t base = ((size_t)b * C + c) * P;
    const float*  xp = x + base;
    const __half* up = g_u + base;
    const __half* lp = g_lam + base;
    const float*  rv = g_Rv + (size_t)b * P;
    __half* AP = g_K + ((size_t)b * 512 + c) * P;
    __half* BP = g_K + ((size_t)b * 512 + 256 + c) * P;
    int tid = threadIdx.x;

    {   // stage lam plane (4096 fp16) into padded fp32 smem
        int row = tid >> 3, q = tid & 7;
        uint4 raw = *(const uint4*)(lp + row * 64 + q * 8);
        __half2* hp = (__half2*)&raw;
#pragma unroll
        for (int j = 0; j < 4; j++) {
            float2 f = __half22float2(hp[j]);
            ls[row * 65 + q * 8 + j * 2]     = f.x;
            ls[row * 65 + q * 8 + j * 2 + 1] = f.y;
        }
    }
    __syncthreads();

    int wid = tid >> 5, lane = tid & 31;
#pragma unroll
    for (int r = 0; r < 4; r++) {
        int h = wid + r * 16;
        int hb = 63 - h;
        int w0 = lane * 2, w1 = w0 + 1;
        float2 av = *(const float2*)(rv + h * 64 + w0);
        float a0 = av.x, a1 = av.y;
        float2 xv = *(const float2*)(xp + h * 64 + w0);
        float bA0 = ls[w0 * 65 + h] * xv.x;
        float bA1 = ls[w1 * 65 + h] * xv.y;
        float bB0 = ls[(63 - w0) * 65 + hb] * xv.x;
        float bB1 = ls[(63 - w1) * 65 + hb] * xv.y;
        float ca  = a0 * a1;
        float cbA = a1 * bA0 + bA1;
        float cbB = a1 * bB0 + bB1;
#pragma unroll
        for (int d = 1; d < 32; d <<= 1) {
            float pa  = __shfl_up_sync(0xffffffffu, ca,  d);
            float pbA = __shfl_up_sync(0xffffffffu, cbA, d);
            float pbB = __shfl_up_sync(0xffffffffu, cbB, d);
            if (lane >= d) {
                cbA = ca * pbA + cbA;
                cbB = ca * pbB + cbB;
                ca  = ca * pa;
            }
        }
        float eA = __shfl_up_sync(0xffffffffu, cbA, 1);
        float eB = __shfl_up_sync(0xffffffffu, cbB, 1);
        if (lane == 0) { eA = 0.f; eB = 0.f; }
        float hA0 = a0 * eA + bA0;
        float hA1 = a1 * hA0 + bA1;
        float hB0 = a0 * eB + bB0;
        float hB1 = a1 * hB0 + bB1;
        float2 uv  = __half22float2(*(const __half2*)(up + h  * 64 + w0));
        float2 uvb = __half22float2(*(const __half2*)(up + hb * 64 + w0));
        *(__half2*)(AP + h * 64 + w0) = __floats2half2_rn(hA0 * uv.x,  hA1 * uv.y);
        *(__half2*)(BP + h * 64 + w0) = __floats2half2_rn(hB0 * uvb.x, hB1 * uvb.y);
    }
}

// ============================================================
// K5 (fp16 1-term): out = Wf @ Kmat + bias. K=512.
// CTA tile M=256 (full) x N=128, 512 threads (16 warps, 4x4),
// warp tile 64x32, cp.async double-buffered.
// Dynamic smem: 2 x (A 20KB) + 2 x (B 8.5KB) = 58368 B.
// ============================================================
#define MG_A_BUF 20480              // bytes per A buffer
#define MG_B_BASE 40960
#define MG_B_BUF 8704               // bytes per B buffer
#define MG_SMEM 58368

__global__ __launch_bounds__(512) void k_merge_mma(float* __restrict__ out,
                                                   const float* __restrict__ bm) {
    extern __shared__ __align__(16) char dsm[];
    int b  = blockIdx.z;
    int p0 = blockIdx.x * 128;
    int tid = threadIdx.x;
    int wid = tid >> 5, lane = tid & 31;
    int wm = wid >> 2, wn = wid & 3;

    float acc[4][4][4];
#pragma unroll
    for (int i = 0; i < 4; i++)
#pragma unroll
        for (int j = 0; j < 4; j++)
#pragma unroll
            for (int q = 0; q < 4; q++) acc[i][j][q] = 0.f;

    int a_row0 = tid >> 2, a_q = tid & 3;
    int b_kk = tid >> 4, b_q = tid & 15;

    {
        char* Abuf = dsm;
        char* Bbuf = dsm + MG_B_BASE;
#pragma unroll
        for (int l = 0; l < 2; l++) {
            int row = a_row0 + l * 128;
            cp16(sptr(Abuf + (row * 40 + a_q * 8) * 2),
                 g_Wf + (size_t)row * 512 + a_q * 8);
        }
        size_t off = ((size_t)b * 512 + b_kk) * P + p0 + b_q * 8;
        cp16(sptr(Bbuf + (b_kk * 136 + b_q * 8) * 2), g_K + off);
        asm volatile("cp.async.commit_group;");
    }

    for (int i = 0; i < 16; i++) {
        if (i + 1 < 16) {
            int k0 = (i + 1) * 32;
            char* Abuf = dsm + ((i + 1) & 1) * MG_A_BUF;
            char* Bbuf = dsm + MG_B_BASE + ((i + 1) & 1) * MG_B_BUF;
#pragma unroll
            for (int l = 0; l < 2; l++) {
                int row = a_row0 + l * 128;
                cp16(sptr(Abuf + (row * 40 + a_q * 8) * 2),
                     g_Wf + (size_t)row * 512 + k0 + a_q * 8);
            }
            size_t off = ((size_t)b * 512 + k0 + b_kk) * P + p0 + b_q * 8;
            cp16(sptr(Bbuf + (b_kk * 136 + b_q * 8) * 2), g_K + off);
            asm volatile("cp.async.commit_group;");
            asm volatile("cp.async.wait_group 1;");
        } else {
            asm volatile("cp.async.wait_group 0;");
        }
        __syncthreads();

        const __half* Ah = (const __half*)(dsm + (i & 1) * MG_A_BUF);
        const __half* Bh = (const __half*)(dsm + MG_B_BASE + (i & 1) * MG_B_BUF);
#pragma unroll
        for (int ks = 0; ks < 2; ks++) {
            int kk = ks * 16;
            u32 bh[2][4];
#pragma unroll
            for (int nh = 0; nh < 2; nh++)
                ldm_x4_t(bh[nh], sptr(&Bh[(kk + (lane & 15)) * 136
                                          + wn * 32 + nh * 16 + (lane >> 4) * 8]));
#pragma unroll
            for (int mf = 0; mf < 4; mf++) {
                u32 ah[4];
                ldm_x4(ah, sptr(&Ah[(wm * 64 + mf * 16 + (lane & 15)) * 40
                                    + kk + (lane >> 4) * 8]));
#pragma unroll
                for (int nf = 0; nf < 4; nf++) {
                    u32 b0 = bh[nf >> 1][(nf & 1) * 2], b1 = bh[nf >> 1][(nf & 1) * 2 + 1];
                    mma16816h(acc[mf][nf], ah, b0, b1);
                }
            }
        }
        __syncthreads();
    }

    int g = lane >> 2, tg = lane & 3;
#pragma unroll
    for (int mf = 0; mf < 4; mf++) {
        int m1 = wm * 64 + mf * 16 + g;
#pragma unroll
        for (int nf = 0; nf < 4; nf++) {
            int p = p0 + wn * 32 + nf * 8 + tg * 2;
            float bs1 = bm[m1], bs2 = bm[m1 + 8];
            *(float2*)(out + ((size_t)b * C + m1) * P + p) =
                make_float2(acc[mf][nf][0] + bs1, acc[mf][nf][1] + bs1);
            *(float2*)(out + ((size_t)b * C + m1 + 8) * P + p) =
                make_float2(acc[mf][nf][2] + bs2, acc[mf][nf][3] + bs2);
        }
    }
}

// ============================================================
extern "C" void kernel_launch(void* const* d_in, const int* in_sizes, int n_in,
                              void* d_out, int out_size) {
    const float* x       = (const float*)d_in[0];
    const float* w_red   = (const float*)d_in[1];
    const float* b_red   = (const float*)d_in[2];
    const float* w_u     = (const float*)d_in[3];
    const float* b_u     = (const float*)d_in[4];
    const float* w_lam   = (const float*)d_in[5];
    const float* b_lam   = (const float*)d_in[6];
    const float* w_wt    = (const float*)d_in[7];
    const float* b_wt    = (const float*)d_in[8];
    const float* w_merge = (const float*)d_in[9];
    const float* b_merge = (const float*)d_in[10];
    float* out = (float*)d_out;

    cudaFuncSetAttribute(k_merge_mma,
                         cudaFuncAttributeMaxDynamicSharedMemorySize, MG_SMEM);

    k_prep<<<704, 256>>>(w_merge, w_u, w_lam, w_red);
    k_red_mma<<<dim3(32, 1, NB), 256>>>(x, b_red, w_wt, b_wt);
    k_ul_mma<<<dim3(32, 4, NB), 256>>>(b_u, b_lam);
    k_scan<<<dim3(256, NB), 512>>>(x);
    k_merge_mma<<<dim3(32, 1, NB), 512, MG_SMEM>>>(out, b_merge);
}

// round 12
// speedup vs baseline: 4.6073x; 1.1045x over previous
#include <cuda_runtime.h>
#include <cuda_fp16.h>

#define S 64
#define NB 8
#define C 256
#define CR 64
#define P 4096   // S*S per plane

typedef unsigned int u32;

// ---- scratch (device globals; no runtime allocation allowed) ----
__device__ __half g_u  [NB * C * P];                 // 16 MB fp16
__device__ __half g_lam[NB * C * P];                 // 16 MB fp16
__device__ float  g_Rv [NB * P];                     // 128 KB fp32
__device__ __half g_K  [NB * 512 * P];               // 32 MB fp16 (0..255 = A dir, 256..511 = B dir)
__device__ __half g_Wf [256 * 512];                  // merge W fp16 (folded)
__device__ __half g_Wul[512 * 64];                   // u/lam W fp16
__device__ __half g_Wred[64 * 256];                  // red  W fp16

// ---- helpers ----
__device__ __forceinline__ u32 sptr(const void* p) {
    return (u32)__cvta_generic_to_shared(p);
}
__device__ __forceinline__ void ldm_x4(u32* r, u32 addr) {
    asm volatile("ldmatrix.sync.aligned.m8n8.x4.shared.b16 {%0,%1,%2,%3}, [%4];"
                 : "=r"(r[0]), "=r"(r[1]), "=r"(r[2]), "=r"(r[3]) : "r"(addr));
}
__device__ __forceinline__ void ldm_x4_t(u32* r, u32 addr) {
    asm volatile("ldmatrix.sync.aligned.m8n8.x4.trans.shared.b16 {%0,%1,%2,%3}, [%4];"
                 : "=r"(r[0]), "=r"(r[1]), "=r"(r[2]), "=r"(r[3]) : "r"(addr));
}
__device__ __forceinline__ void mma16816h(float* d, const u32* a, u32 b0, u32 b1) {
    asm volatile("mma.sync.aligned.m16n8k16.row.col.f32.f16.f16.f32 "
                 "{%0,%1,%2,%3}, {%4,%5,%6,%7}, {%8,%9}, {%0,%1,%2,%3};"
                 : "+f"(d[0]), "+f"(d[1]), "+f"(d[2]), "+f"(d[3])
                 : "r"(a[0]), "r"(a[1]), "r"(a[2]), "r"(a[3]), "r"(b0), "r"(b1));
}
__device__ __forceinline__ void cp16(u32 dst, const void* src) {
    asm volatile("cp.async.cg.shared.global [%0], [%1], 16;" :: "r"(dst), "l"(src));
}

// ============================================================
// Prep: fold merge weights; all weights -> single fp16.
// ============================================================
__global__ void k_prep(const float* __restrict__ wm,
                       const float* __restrict__ wu,
                       const float* __restrict__ wl,
                       const float* __restrict__ wr) {
    int i = blockIdx.x * 256 + threadIdx.x;
    if (i < 131072) {
        int o = i >> 9, k = i & 511;
        float v = wm[o * 1024 + k] + wm[o * 1024 + k + 512];
        g_Wf[o * 512 + k] = __float2half(v);
    } else if (i < 163840) {
        int j = i - 131072;
        int m = j >> 6, k = j & 63;
        float v = (m < 256) ? wu[m * 64 + k] : wl[(m - 256) * 64 + k];
        g_Wul[m * 64 + k] = __float2half(v);
    } else if (i < 180224) {
        int j = i - 163840;
        int m = j >> 8, k = j & 255;
        g_Wred[m * 256 + k] = __float2half(wr[m * 256 + k]);
    }
}

// ============================================================
// K1 (fused red + Rv + u/lam): one CTA owns one (b, 128-p tile).
// Phase 1: red[64, 128] = Wred @ x  (fp16 MMA, fp32 acc)
//   -> smem Bs2 fp16 (B operand for phase 2) + redT fp32 (for Rv)
// Rv: sigmoid tri-band rowsum from redT.
// Phase 2: 4 m-chunks of 128: u/lam[mchunk] = Wul[mchunk] @ Bs2.
// Dynamic smem: arena 33792 (phase1 tiles / redT / phase2 A) + Bs2 17408.
// ============================================================
#define RU_BS2   33792
#define RU_SMEM  51200

__global__ __launch_bounds__(256) void k_rul(const float* __restrict__ x,
                                             const float* __restrict__ bred,
                                             const float* __restrict__ wwt,
                                             const float* __restrict__ bwt,
                                             const float* __restrict__ bu,
                                             const float* __restrict__ bl) {
    extern __shared__ __align__(16) char dsm[];
    __half* As   = (__half*)(dsm);               // phase1 A: 64x40 = 5120B
    __half* Bsx  = (__half*)(dsm + 5120);        // phase1 B: 32x136 = 8704B
    float*  redT = (float*)(dsm);                // 64x132 fp32 = 33792B
    __half* Aul  = (__half*)(dsm);               // phase2 A: 128x72 = 18432B
    __half* Bs2  = (__half*)(dsm + RU_BS2);      // red fp16 [64k][136p]
    __shared__ float ws[192];
    __shared__ float bs3[3];

    int b  = blockIdx.y;
    int p0 = blockIdx.x * 128;
    int tid = threadIdx.x;
    int wid = tid >> 5, lane = tid & 31;
    for (int i = tid; i < 192; i += 256) ws[i] = wwt[i];
    if (tid < 3) bs3[tid] = bwt[tid];

    // ================= Phase 1: red GEMM =================
    {
        int wm = wid & 3;       // 4 m-slots x 16 rows
        int wn = wid >> 2;      // 2 n-slots x 64 cols
        float acc[8][4];
#pragma unroll
        for (int i = 0; i < 8; i++)
#pragma unroll
            for (int q = 0; q < 4; q++) acc[i][q] = 0.f;

        const float* xb = x + (size_t)b * C * P;
        for (int k0 = 0; k0 < 256; k0 += 32) {
            {   // A chunk: 64 rows x 32 k
                int row = tid >> 2, q = tid & 3;
                *(uint4*)&As[row * 40 + q * 8] =
                    *(const uint4*)(g_Wred + row * 256 + k0 + q * 8);
            }
#pragma unroll
            for (int l = 0; l < 2; l++) {   // x chunk 32k x 128p -> fp16
                int cid = tid + l * 256;
                int kk = cid >> 4, pq = cid & 15;
                const float* src = xb + (size_t)(k0 + kk) * P + p0 + pq * 8;
                float4 v0 = *(const float4*)(src);
                float4 v1 = *(const float4*)(src + 4);
                __half2 h[4];
                h[0] = __floats2half2_rn(v0.x, v0.y);
                h[1] = __floats2half2_rn(v0.z, v0.w);
                h[2] = __floats2half2_rn(v1.x, v1.y);
                h[3] = __floats2half2_rn(v1.z, v1.w);
                *(uint4*)&Bsx[kk * 136 + pq * 8] = *(uint4*)h;
            }
            __syncthreads();
#pragma unroll
            for (int ks = 0; ks < 2; ks++) {
                int kk = ks * 16;
                u32 ah[4], bh[4][4];
                ldm_x4(ah, sptr(&As[(wm * 16 + (lane & 15)) * 40 + kk + (lane >> 4) * 8]));
#pragma unroll
                for (int nh = 0; nh < 4; nh++)
                    ldm_x4_t(bh[nh], sptr(&Bsx[(kk + (lane & 15)) * 136
                                               + wn * 64 + nh * 16 + (lane >> 4) * 8]));
#pragma unroll
                for (int nf = 0; nf < 8; nf++) {
                    u32 b0 = bh[nf >> 1][(nf & 1) * 2], b1 = bh[nf >> 1][(nf & 1) * 2 + 1];
                    mma16816h(acc[nf], ah, b0, b1);
                }
            }
            __syncthreads();
        }

        // epilogue: bias; stage redT fp32 (Rv) + Bs2 fp16 (phase-2 B)
        int g = lane >> 2, tg = lane & 3;
        int m1 = wm * 16 + g;
        float bsA = __ldg(bred + m1), bsB = __ldg(bred + m1 + 8);
#pragma unroll
        for (int nf = 0; nf < 8; nf++) {
            int p = wn * 64 + nf * 8 + tg * 2;
            float v0 = acc[nf][0] + bsA, v1 = acc[nf][1] + bsA;
            float v2 = acc[nf][2] + bsB, v3 = acc[nf][3] + bsB;
            *(float2*)&redT[m1 * 132 + p]       = make_float2(v0, v1);
            *(float2*)&redT[(m1 + 8) * 132 + p] = make_float2(v2, v3);
            *(__half2*)&Bs2[m1 * 136 + p]       = __floats2half2_rn(v0, v1);
            *(__half2*)&Bs2[(m1 + 8) * 136 + p] = __floats2half2_rn(v2, v3);
        }
    }
    __syncthreads();

    // ================= Rv =================
    if (tid < 128) {
        int w = tid & 63;
        float a0 = bs3[0], a1 = bs3[1], a2 = bs3[2];
#pragma unroll 16
        for (int m = 0; m < 64; m++) {
            float r = redT[m * 132 + tid];
            a0 += ws[m]       * r;
            a1 += ws[64 + m]  * r;
            a2 += ws[128 + m] * r;
        }
        float s0 = 1.f / (1.f + expf(-a0));
        float s1 = 1.f / (1.f + expf(-a1));
        float s2 = 1.f / (1.f + expf(-a2));
        float den = fmaxf(s0 + s1 + s2, 1e-6f);
        float rv = s1;
        if (w >= 1)     rv += s0;
        if (w <= S - 2) rv += s2;
        g_Rv[(size_t)b * P + p0 + tid] = rv / den;
    }
    __syncthreads();

    // ================= Phase 2: u/lam, 4 m-chunks of 128 =================
    {
        int wm = wid >> 2, wn = wid & 3;    // 2 m-slots x 4 n-slots, warp 64x32
        for (int mc = 0; mc < 4; mc++) {
            // load A: 128 rows x 64 k -> Aul[128x72]
#pragma unroll
            for (int l = 0; l < 4; l++) {
                int cid = tid + l * 256;
                int row = cid >> 3, q = cid & 7;
                *(uint4*)&Aul[row * 72 + q * 8] =
                    *(const uint4*)(g_Wul + (size_t)(mc * 128 + row) * 64 + q * 8);
            }
            __syncthreads();

            float acc[4][4][4];
#pragma unroll
            for (int i = 0; i < 4; i++)
#pragma unroll
                for (int j = 0; j < 4; j++)
#pragma unroll
                    for (int q = 0; q < 4; q++) acc[i][j][q] = 0.f;

#pragma unroll
            for (int ks = 0; ks < 4; ks++) {
                int kk = ks * 16;
                u32 bh[2][4];
#pragma unroll
                for (int nh = 0; nh < 2; nh++)
                    ldm_x4_t(bh[nh], sptr(&Bs2[(kk + (lane & 15)) * 136
                                               + wn * 32 + nh * 16 + (lane >> 4) * 8]));
#pragma unroll
                for (int mf = 0; mf < 4; mf++) {
                    u32 ah[4];
                    ldm_x4(ah, sptr(&Aul[(wm * 64 + mf * 16 + (lane & 15)) * 72
                                         + kk + (lane >> 4) * 8]));
#pragma unroll
                    for (int nf = 0; nf < 4; nf++) {
                        u32 b0 = bh[nf >> 1][(nf & 1) * 2], b1 = bh[nf >> 1][(nf & 1) * 2 + 1];
                        mma16816h(acc[mf][nf], ah, b0, b1);
                    }
                }
            }

            int mg0 = mc * 128;
            __half* outb; const float* biasArr; int mofs;
            if (mg0 < 256) { outb = g_u   + (size_t)b * C * P; biasArr = bu; mofs = mg0; }
            else           { outb = g_lam + (size_t)b * C * P; biasArr = bl; mofs = mg0 - 256; }
            int g = lane >> 2, tg = lane & 3;
#pragma unroll
            for (int mf = 0; mf < 4; mf++) {
                int m1 = mofs + wm * 64 + mf * 16 + g;
#pragma unroll
                for (int nf = 0; nf < 4; nf++) {
                    int p = p0 + wn * 32 + nf * 8 + tg * 2;
                    float bs1 = biasArr[m1], bs2v = biasArr[m1 + 8];
                    *(__half2*)(outb + (size_t)m1 * P + p) =
                        __floats2half2_rn(acc[mf][nf][0] + bs1, acc[mf][nf][1] + bs1);
                    *(__half2*)(outb + (size_t)(m1 + 8) * P + p) =
                        __floats2half2_rn(acc[mf][nf][2] + bs2v, acc[mf][nf][3] + bs2v);
                }
            }
            __syncthreads();    // Aul reuse
        }
    }
}

// ============================================================
// K4: fused dual scan along w; u/lam fp16 in, fp16 Kmat planes out.
// ============================================================
__global__ __launch_bounds__(512) void k_scan(const float* __restrict__ x) {
    __shared__ float ls[64 * 65];
    int b = blockIdx.y, c = blockIdx.x;
    size_t base = ((size_t)b * C + c) * P;
    const float*  xp = x + base;
    const __half* up = g_u + base;
    const __half* lp = g_lam + base;
    const float*  rv = g_Rv + (size_t)b * P;
    __half* AP = g_K + ((size_t)b * 512 + c) * P;
    __half* BP = g_K + ((size_t)b * 512 + 256 + c) * P;
    int tid = threadIdx.x;

    {   // stage lam plane (4096 fp16) into padded fp32 smem
        int row = tid >> 3, q = tid & 7;
        uint4 raw = *(const uint4*)(lp + row * 64 + q * 8);
        __half2* hp = (__half2*)&raw;
#pragma unroll
        for (int j = 0; j < 4; j++) {
            float2 f = __half22float2(hp[j]);
            ls[row * 65 + q * 8 + j * 2]     = f.x;
            ls[row * 65 + q * 8 + j * 2 + 1] = f.y;
        }
    }
    __syncthreads();

    int wid = tid >> 5, lane = tid & 31;
#pragma unroll
    for (int r = 0; r < 4; r++) {
        int h = wid + r * 16;
        int hb = 63 - h;
        int w0 = lane * 2, w1 = w0 + 1;
        float2 av = *(const float2*)(rv + h * 64 + w0);
        float a0 = av.x, a1 = av.y;
        float2 xv = *(const float2*)(xp + h * 64 + w0);
        float bA0 = ls[w0 * 65 + h] * xv.x;
        float bA1 = ls[w1 * 65 + h] * xv.y;
        float bB0 = ls[(63 - w0) * 65 + hb] * xv.x;
        float bB1 = ls[(63 - w1) * 65 + hb] * xv.y;
        float ca  = a0 * a1;
        float cbA = a1 * bA0 + bA1;
        float cbB = a1 * bB0 + bB1;
#pragma unroll
        for (int d = 1; d < 32; d <<= 1) {
            float pa  = __shfl_up_sync(0xffffffffu, ca,  d);
            float pbA = __shfl_up_sync(0xffffffffu, cbA, d);
            float pbB = __shfl_up_sync(0xffffffffu, cbB, d);
            if (lane >= d) {
                cbA = ca * pbA + cbA;
                cbB = ca * pbB + cbB;
                ca  = ca * pa;
            }
        }
        float eA = __shfl_up_sync(0xffffffffu, cbA, 1);
        float eB = __shfl_up_sync(0xffffffffu, cbB, 1);
        if (lane == 0) { eA = 0.f; eB = 0.f; }
        float hA0 = a0 * eA + bA0;
        float hA1 = a1 * hA0 + bA1;
        float hB0 = a0 * eB + bB0;
        float hB1 = a1 * hB0 + bB1;
        float2 uv  = __half22float2(*(const __half2*)(up + h  * 64 + w0));
        float2 uvb = __half22float2(*(const __half2*)(up + hb * 64 + w0));
        *(__half2*)(AP + h * 64 + w0) = __floats2half2_rn(hA0 * uv.x,  hA1 * uv.y);
        *(__half2*)(BP + h * 64 + w0) = __floats2half2_rn(hB0 * uvb.x, hB1 * uvb.y);
    }
}

// ============================================================
// K5 (fp16 1-term): out = Wf @ Kmat + bias. K=512, BK=64 (8 chunks).
// CTA tile M=256 (full) x N=128, 512 threads (16 warps, 4x4),
// warp tile 64x32, cp.async double-buffered.
// Dynamic smem: 2 x (A 36KB) + 2 x (B 17KB) = 108544 B.
// ============================================================
#define MG_A_BUF 36864              // 256 x 72 halves
#define MG_B_BASE 73728
#define MG_B_BUF 17408              // 64 x 136 halves
#define MG_SMEM 108544

__global__ __launch_bounds__(512) void k_merge_mma(float* __restrict__ out,
                                                   const float* __restrict__ bm) {
    extern __shared__ __align__(16) char dsm[];
    int b  = blockIdx.z;
    int p0 = blockIdx.x * 128;
    int tid = threadIdx.x;
    int wid = tid >> 5, lane = tid & 31;
    int wm = wid >> 2, wn = wid & 3;

    float acc[4][4][4];
#pragma unroll
    for (int i = 0; i < 4; i++)
#pragma unroll
        for (int j = 0; j < 4; j++)
#pragma unroll
            for (int q = 0; q < 4; q++) acc[i][j][q] = 0.f;

#define MG_LOAD(chunk, buf) do {                                                     \
    char* Abuf = dsm + (buf) * MG_A_BUF;                                             \
    char* Bbuf = dsm + MG_B_BASE + (buf) * MG_B_BUF;                                 \
    int k0 = (chunk) * 64;                                                           \
    _Pragma("unroll")                                                                \
    for (int l = 0; l < 4; l++) {    /* A: 256 rows x 64 k = 2048 uint4 */           \
        int cid = tid + l * 512;                                                     \
        int row = cid >> 3, q = cid & 7;                                             \
        cp16(sptr(Abuf + (row * 72 + q * 8) * 2),                                    \
             g_Wf + (size_t)row * 512 + k0 + q * 8);                                 \
    }                                                                                \
    _Pragma("unroll")                                                                \
    for (int l = 0; l < 2; l++) {    /* B: 64 k x 128 p = 1024 uint4 */              \
        int cid = tid + l * 512;                                                     \
        int kk = cid >> 4, q = cid & 15;                                             \
        size_t off = ((size_t)b * 512 + k0 + kk) * P + p0 + q * 8;                   \
        cp16(sptr(Bbuf + (kk * 136 + q * 8) * 2), g_K + off);                        \
    }                                                                                \
    asm volatile("cp.async.commit_group;");                                          \
} while (0)

    MG_LOAD(0, 0);

    for (int i = 0; i < 8; i++) {
        if (i + 1 < 8) {
            MG_LOAD(i + 1, (i + 1) & 1);
            asm volatile("cp.async.wait_group 1;");
        } else {
            asm volatile("cp.async.wait_group 0;");
        }
        __syncthreads();

        const __half* Ah = (const __half*)(dsm + (i & 1) * MG_A_BUF);
        const __half* Bh = (const __half*)(dsm + MG_B_BASE + (i & 1) * MG_B_BUF);
#pragma unroll
        for (int ks = 0; ks < 4; ks++) {
            int kk = ks * 16;
            u32 bh[2][4];
#pragma unroll
            for (int nh = 0; nh < 2; nh++)
                ldm_x4_t(bh[nh], sptr(&Bh[(kk + (lane & 15)) * 136
                                          + wn * 32 + nh * 16 + (lane >> 4) * 8]));
#pragma unroll
            for (int mf = 0; mf < 4; mf++) {
                u32 ah[4];
                ldm_x4(ah, sptr(&Ah[(wm * 64 + mf * 16 + (lane & 15)) * 72
                                    + kk + (lane >> 4) * 8]));
#pragma unroll
                for (int nf = 0; nf < 4; nf++) {
                    u32 b0 = bh[nf >> 1][(nf & 1) * 2], b1 = bh[nf >> 1][(nf & 1) * 2 + 1];
                    mma16816h(acc[mf][nf], ah, b0, b1);
                }
            }
        }
        __syncthreads();
    }

    int g = lane >> 2, tg = lane & 3;
#pragma unroll
    for (int mf = 0; mf < 4; mf++) {
        int m1 = wm * 64 + mf * 16 + g;
#pragma unroll
        for (int nf = 0; nf < 4; nf++) {
            int p = p0 + wn * 32 + nf * 8 + tg * 2;
            float bs1 = bm[m1], bs2 = bm[m1 + 8];
            *(float2*)(out + ((size_t)b * C + m1) * P + p) =
                make_float2(acc[mf][nf][0] + bs1, acc[mf][nf][1] + bs1);
            *(float2*)(out + ((size_t)b * C + m1 + 8) * P + p) =
                make_float2(acc[mf][nf][2] + bs2, acc[mf][nf][3] + bs2);
        }
    }
}

// ============================================================
extern "C" void kernel_launch(void* const* d_in, const int* in_sizes, int n_in,
                              void* d_out, int out_size) {
    const float* x       = (const float*)d_in[0];
    const float* w_red   = (const float*)d_in[1];
    const float* b_red   = (const float*)d_in[2];
    const float* w_u     = (const float*)d_in[3];
    const float* b_u     = (const float*)d_in[4];
    const float* w_lam   = (const float*)d_in[5];
    const float* b_lam   = (const float*)d_in[6];
    const float* w_wt    = (const float*)d_in[7];
    const float* b_wt    = (const float*)d_in[8];
    const float* w_merge = (const float*)d_in[9];
    const float* b_merge = (const float*)d_in[10];
    float* out = (float*)d_out;

    cudaFuncSetAttribute(k_rul,
                         cudaFuncAttributeMaxDynamicSharedMemorySize, RU_SMEM);
    cudaFuncSetAttribute(k_merge_mma,
                         cudaFuncAttributeMaxDynamicSharedMemorySize, MG_SMEM);

    k_prep<<<704, 256>>>(w_merge, w_u, w_lam, w_red);
    k_rul<<<dim3(32, NB), 256, RU_SMEM>>>(x, b_red, w_wt, b_wt, b_u, b_lam);
    k_scan<<<dim3(256, NB), 512>>>(x);
    k_merge_mma<<<dim3(32, 1, NB), 512, MG_SMEM>>>(out, b_merge);
}

// round 13
// speedup vs baseline: 4.7038x; 1.0209x over previous
#include <cuda_runtime.h>
#include <cuda_fp16.h>

#define S 64
#define NB 8
#define C 256
#define CR 64
#define P 4096   // S*S per plane

typedef unsigned int u32;

// ---- scratch (device globals; no runtime allocation allowed) ----
__device__ __half g_u  [NB * C * P];                 // 16 MB fp16
__device__ __half g_lam[NB * C * P];                 // 16 MB fp16
__device__ float  g_Rv [NB * P];                     // 128 KB fp32
__device__ __half g_K  [NB * 512 * P];               // 32 MB fp16 (0..255 = A dir, 256..511 = B dir)
__device__ __half g_Wf [256 * 512];                  // merge W fp16 (folded)
__device__ __half g_Wul[512 * 64];                   // u/lam W fp16
__device__ __half g_Wred[64 * 256];                  // red  W fp16

// ---- helpers ----
__device__ __forceinline__ u32 sptr(const void* p) {
    return (u32)__cvta_generic_to_shared(p);
}
__device__ __forceinline__ void ldm_x4(u32* r, u32 addr) {
    asm volatile("ldmatrix.sync.aligned.m8n8.x4.shared.b16 {%0,%1,%2,%3}, [%4];"
                 : "=r"(r[0]), "=r"(r[1]), "=r"(r[2]), "=r"(r[3]) : "r"(addr));
}
__device__ __forceinline__ void ldm_x4_t(u32* r, u32 addr) {
    asm volatile("ldmatrix.sync.aligned.m8n8.x4.trans.shared.b16 {%0,%1,%2,%3}, [%4];"
                 : "=r"(r[0]), "=r"(r[1]), "=r"(r[2]), "=r"(r[3]) : "r"(addr));
}
__device__ __forceinline__ void mma16816h(float* d, const u32* a, u32 b0, u32 b1) {
    asm volatile("mma.sync.aligned.m16n8k16.row.col.f32.f16.f16.f32 "
                 "{%0,%1,%2,%3}, {%4,%5,%6,%7}, {%8,%9}, {%0,%1,%2,%3};"
                 : "+f"(d[0]), "+f"(d[1]), "+f"(d[2]), "+f"(d[3])
                 : "r"(a[0]), "r"(a[1]), "r"(a[2]), "r"(a[3]), "r"(b0), "r"(b1));
}
__device__ __forceinline__ void cp16(u32 dst, const void* src) {
    asm volatile("cp.async.cg.shared.global [%0], [%1], 16;" :: "r"(dst), "l"(src));
}

// ============================================================
// Prep: fold merge weights; all weights -> single fp16.
// ============================================================
__global__ void k_prep(const float* __restrict__ wm,
                       const float* __restrict__ wu,
                       const float* __restrict__ wl,
                       const float* __restrict__ wr) {
    int i = blockIdx.x * 256 + threadIdx.x;
    if (i < 131072) {
        int o = i >> 9, k = i & 511;
        float v = wm[o * 1024 + k] + wm[o * 1024 + k + 512];
        g_Wf[o * 512 + k] = __float2half(v);
    } else if (i < 163840) {
        int j = i - 131072;
        int m = j >> 6, k = j & 63;
        float v = (m < 256) ? wu[m * 64 + k] : wl[(m - 256) * 64 + k];
        g_Wul[m * 64 + k] = __float2half(v);
    } else if (i < 180224) {
        int j = i - 163840;
        int m = j >> 8, k = j & 255;
        g_Wred[m * 256 + k] = __float2half(wr[m * 256 + k]);
    }
}

// ============================================================
// K1 (fused red + Rv + u/lam): one CTA owns one (b, 128-p tile).
// ============================================================
#define RU_BS2   33792
#define RU_SMEM  51200

__global__ __launch_bounds__(256) void k_rul(const float* __restrict__ x,
                                             const float* __restrict__ bred,
                                             const float* __restrict__ wwt,
                                             const float* __restrict__ bwt,
                                             const float* __restrict__ bu,
                                             const float* __restrict__ bl) {
    extern __shared__ __align__(16) char dsm[];
    __half* As   = (__half*)(dsm);               // phase1 A: 64x40 = 5120B
    __half* Bsx  = (__half*)(dsm + 5120);        // phase1 B: 32x136 = 8704B
    float*  redT = (float*)(dsm);                // 64x132 fp32 = 33792B
    __half* Aul  = (__half*)(dsm);               // phase2 A: 128x72 = 18432B
    __half* Bs2  = (__half*)(dsm + RU_BS2);      // red fp16 [64k][136p]
    __shared__ float ws[192];
    __shared__ float bs3[3];

    int b  = blockIdx.y;
    int p0 = blockIdx.x * 128;
    int tid = threadIdx.x;
    int wid = tid >> 5, lane = tid & 31;
    for (int i = tid; i < 192; i += 256) ws[i] = wwt[i];
    if (tid < 3) bs3[tid] = bwt[tid];

    // ================= Phase 1: red GEMM =================
    {
        int wm = wid & 3;       // 4 m-slots x 16 rows
        int wn = wid >> 2;      // 2 n-slots x 64 cols
        float acc[8][4];
#pragma unroll
        for (int i = 0; i < 8; i++)
#pragma unroll
            for (int q = 0; q < 4; q++) acc[i][q] = 0.f;

        const float* xb = x + (size_t)b * C * P;
        for (int k0 = 0; k0 < 256; k0 += 32) {
            {   // A chunk: 64 rows x 32 k
                int row = tid >> 2, q = tid & 3;
                *(uint4*)&As[row * 40 + q * 8] =
                    *(const uint4*)(g_Wred + row * 256 + k0 + q * 8);
            }
#pragma unroll
            for (int l = 0; l < 2; l++) {   // x chunk 32k x 128p -> fp16
                int cid = tid + l * 256;
                int kk = cid >> 4, pq = cid & 15;
                const float* src = xb + (size_t)(k0 + kk) * P + p0 + pq * 8;
                float4 v0 = *(const float4*)(src);
                float4 v1 = *(const float4*)(src + 4);
                __half2 h[4];
                h[0] = __floats2half2_rn(v0.x, v0.y);
                h[1] = __floats2half2_rn(v0.z, v0.w);
                h[2] = __floats2half2_rn(v1.x, v1.y);
                h[3] = __floats2half2_rn(v1.z, v1.w);
                *(uint4*)&Bsx[kk * 136 + pq * 8] = *(uint4*)h;
            }
            __syncthreads();
#pragma unroll
            for (int ks = 0; ks < 2; ks++) {
                int kk = ks * 16;
                u32 ah[4], bh[4][4];
                ldm_x4(ah, sptr(&As[(wm * 16 + (lane & 15)) * 40 + kk + (lane >> 4) * 8]));
#pragma unroll
                for (int nh = 0; nh < 4; nh++)
                    ldm_x4_t(bh[nh], sptr(&Bsx[(kk + (lane & 15)) * 136
                                               + wn * 64 + nh * 16 + (lane >> 4) * 8]));
#pragma unroll
                for (int nf = 0; nf < 8; nf++) {
                    u32 b0 = bh[nf >> 1][(nf & 1) * 2], b1 = bh[nf >> 1][(nf & 1) * 2 + 1];
                    mma16816h(acc[nf], ah, b0, b1);
                }
            }
            __syncthreads();
        }

        // epilogue: bias; stage redT fp32 (Rv) + Bs2 fp16 (phase-2 B)
        int g = lane >> 2, tg = lane & 3;
        int m1 = wm * 16 + g;
        float bsA = __ldg(bred + m1), bsB = __ldg(bred + m1 + 8);
#pragma unroll
        for (int nf = 0; nf < 8; nf++) {
            int p = wn * 64 + nf * 8 + tg * 2;
            float v0 = acc[nf][0] + bsA, v1 = acc[nf][1] + bsA;
            float v2 = acc[nf][2] + bsB, v3 = acc[nf][3] + bsB;
            *(float2*)&redT[m1 * 132 + p]       = make_float2(v0, v1);
            *(float2*)&redT[(m1 + 8) * 132 + p] = make_float2(v2, v3);
            *(__half2*)&Bs2[m1 * 136 + p]       = __floats2half2_rn(v0, v1);
            *(__half2*)&Bs2[(m1 + 8) * 136 + p] = __floats2half2_rn(v2, v3);
        }
    }
    __syncthreads();

    // ================= Rv =================
    if (tid < 128) {
        int w = tid & 63;
        float a0 = bs3[0], a1 = bs3[1], a2 = bs3[2];
#pragma unroll 16
        for (int m = 0; m < 64; m++) {
            float r = redT[m * 132 + tid];
            a0 += ws[m]       * r;
            a1 += ws[64 + m]  * r;
            a2 += ws[128 + m] * r;
        }
        float s0 = 1.f / (1.f + expf(-a0));
        float s1 = 1.f / (1.f + expf(-a1));
        float s2 = 1.f / (1.f + expf(-a2));
        float den = fmaxf(s0 + s1 + s2, 1e-6f);
        float rv = s1;
        if (w >= 1)     rv += s0;
        if (w <= S - 2) rv += s2;
        g_Rv[(size_t)b * P + p0 + tid] = rv / den;
    }
    __syncthreads();

    // ================= Phase 2: u/lam, 4 m-chunks of 128 =================
    {
        int wm = wid >> 2, wn = wid & 3;    // 2 m-slots x 4 n-slots, warp 64x32
        for (int mc = 0; mc < 4; mc++) {
#pragma unroll
            for (int l = 0; l < 4; l++) {
                int cid = tid + l * 256;
                int row = cid >> 3, q = cid & 7;
                *(uint4*)&Aul[row * 72 + q * 8] =
                    *(const uint4*)(g_Wul + (size_t)(mc * 128 + row) * 64 + q * 8);
            }
            __syncthreads();

            float acc[4][4][4];
#pragma unroll
            for (int i = 0; i < 4; i++)
#pragma unroll
                for (int j = 0; j < 4; j++)
#pragma unroll
                    for (int q = 0; q < 4; q++) acc[i][j][q] = 0.f;

#pragma unroll
            for (int ks = 0; ks < 4; ks++) {
                int kk = ks * 16;
                u32 bh[2][4];
#pragma unroll
                for (int nh = 0; nh < 2; nh++)
                    ldm_x4_t(bh[nh], sptr(&Bs2[(kk + (lane & 15)) * 136
                                               + wn * 32 + nh * 16 + (lane >> 4) * 8]));
#pragma unroll
                for (int mf = 0; mf < 4; mf++) {
                    u32 ah[4];
                    ldm_x4(ah, sptr(&Aul[(wm * 64 + mf * 16 + (lane & 15)) * 72
                                         + kk + (lane >> 4) * 8]));
#pragma unroll
                    for (int nf = 0; nf < 4; nf++) {
                        u32 b0 = bh[nf >> 1][(nf & 1) * 2], b1 = bh[nf >> 1][(nf & 1) * 2 + 1];
                        mma16816h(acc[mf][nf], ah, b0, b1);
                    }
                }
            }

            int mg0 = mc * 128;
            __half* outb; const float* biasArr; int mofs;
            if (mg0 < 256) { outb = g_u   + (size_t)b * C * P; biasArr = bu; mofs = mg0; }
            else           { outb = g_lam + (size_t)b * C * P; biasArr = bl; mofs = mg0 - 256; }
            int g = lane >> 2, tg = lane & 3;
#pragma unroll
            for (int mf = 0; mf < 4; mf++) {
                int m1 = mofs + wm * 64 + mf * 16 + g;
#pragma unroll
                for (int nf = 0; nf < 4; nf++) {
                    int p = p0 + wn * 32 + nf * 8 + tg * 2;
                    float bs1 = biasArr[m1], bs2v = biasArr[m1 + 8];
                    *(__half2*)(outb + (size_t)m1 * P + p) =
                        __floats2half2_rn(acc[mf][nf][0] + bs1, acc[mf][nf][1] + bs1);
                    *(__half2*)(outb + (size_t)(m1 + 8) * P + p) =
                        __floats2half2_rn(acc[mf][nf][2] + bs2v, acc[mf][nf][3] + bs2v);
                }
            }
            __syncthreads();    // Aul reuse
        }
    }
}

// ============================================================
// K4: fused dual scan along w; u/lam fp16 in, fp16 Kmat planes out.
// ============================================================
__global__ __launch_bounds__(512) void k_scan(const float* __restrict__ x) {
    __shared__ float ls[64 * 65];
    int b = blockIdx.y, c = blockIdx.x;
    size_t base = ((size_t)b * C + c) * P;
    const float*  xp = x + base;
    const __half* up = g_u + base;
    const __half* lp = g_lam + base;
    const float*  rv = g_Rv + (size_t)b * P;
    __half* AP = g_K + ((size_t)b * 512 + c) * P;
    __half* BP = g_K + ((size_t)b * 512 + 256 + c) * P;
    int tid = threadIdx.x;

    {   // stage lam plane (4096 fp16) into padded fp32 smem
        int row = tid >> 3, q = tid & 7;
        uint4 raw = *(const uint4*)(lp + row * 64 + q * 8);
        __half2* hp = (__half2*)&raw;
#pragma unroll
        for (int j = 0; j < 4; j++) {
            float2 f = __half22float2(hp[j]);
            ls[row * 65 + q * 8 + j * 2]     = f.x;
            ls[row * 65 + q * 8 + j * 2 + 1] = f.y;
        }
    }
    __syncthreads();

    int wid = tid >> 5, lane = tid & 31;
#pragma unroll
    for (int r = 0; r < 4; r++) {
        int h = wid + r * 16;
        int hb = 63 - h;
        int w0 = lane * 2, w1 = w0 + 1;
        float2 av = *(const float2*)(rv + h * 64 + w0);
        float a0 = av.x, a1 = av.y;
        float2 xv = *(const float2*)(xp + h * 64 + w0);
        float bA0 = ls[w0 * 65 + h] * xv.x;
        float bA1 = ls[w1 * 65 + h] * xv.y;
        float bB0 = ls[(63 - w0) * 65 + hb] * xv.x;
        float bB1 = ls[(63 - w1) * 65 + hb] * xv.y;
        float ca  = a0 * a1;
        float cbA = a1 * bA0 + bA1;
        float cbB = a1 * bB0 + bB1;
#pragma unroll
        for (int d = 1; d < 32; d <<= 1) {
            float pa  = __shfl_up_sync(0xffffffffu, ca,  d);
            float pbA = __shfl_up_sync(0xffffffffu, cbA, d);
            float pbB = __shfl_up_sync(0xffffffffu, cbB, d);
            if (lane >= d) {
                cbA = ca * pbA + cbA;
                cbB = ca * pbB + cbB;
                ca  = ca * pa;
            }
        }
        float eA = __shfl_up_sync(0xffffffffu, cbA, 1);
        float eB = __shfl_up_sync(0xffffffffu, cbB, 1);
        if (lane == 0) { eA = 0.f; eB = 0.f; }
        float hA0 = a0 * eA + bA0;
        float hA1 = a1 * hA0 + bA1;
        float hB0 = a0 * eB + bB0;
        float hB1 = a1 * hB0 + bB1;
        float2 uv  = __half22float2(*(const __half2*)(up + h  * 64 + w0));
        float2 uvb = __half22float2(*(const __half2*)(up + hb * 64 + w0));
        *(__half2*)(AP + h * 64 + w0) = __floats2half2_rn(hA0 * uv.x,  hA1 * uv.y);
        *(__half2*)(BP + h * 64 + w0) = __floats2half2_rn(hB0 * uvb.x, hB1 * uvb.y);
    }
}

// ============================================================
// K5 (fp16 1-term): out = Wf @ Kmat + bias. K=512, BK=64 (8 chunks).
// CTA tile M=128 x N=128, 256 threads (8 warps, 2x4), warp 64x32.
// 3-stage cp.async pipeline; 2 CTAs/SM co-resident (24.5K regs/CTA).
// Dynamic smem: 3 x (A 18KB + B 17KB) = 107520 B.
// ============================================================
#define MG3_A 18432                 // 128 x 72 halves
#define MG3_B 17408                 // 64 x 136 halves
#define MG3_STAGE (MG3_A + MG3_B)   // 35840
#define MG3_SMEM (3 * MG3_STAGE)    // 107520

__global__ __launch_bounds__(256, 2) void k_merge_mma(float* __restrict__ out,
                                                      const float* __restrict__ bm) {
    extern __shared__ __align__(16) char dsm[];
    int b  = blockIdx.z;
    int m0 = blockIdx.y * 128;
    int p0 = blockIdx.x * 128;
    int tid = threadIdx.x;
    int wid = tid >> 5, lane = tid & 31;
    int wm = wid >> 2, wn = wid & 3;    // 2 m-slots x 4 n-slots

    float acc[4][4][4];
#pragma unroll
    for (int i = 0; i < 4; i++)
#pragma unroll
        for (int j = 0; j < 4; j++)
#pragma unroll
            for (int q = 0; q < 4; q++) acc[i][j][q] = 0.f;

#define MG_LOAD(chunk, buf) do {                                                     \
    char* Abuf = dsm + (buf) * MG3_STAGE;                                            \
    char* Bbuf = Abuf + MG3_A;                                                       \
    int k0 = (chunk) * 64;                                                           \
    _Pragma("unroll")                                                                \
    for (int l = 0; l < 4; l++) {    /* A: 128 rows x 64 k = 1024 uint4 */           \
        int cid = tid + l * 256;                                                     \
        int row = cid >> 3, q = cid & 7;                                             \
        cp16(sptr(Abuf + (row * 72 + q * 8) * 2),                                    \
             g_Wf + (size_t)(m0 + row) * 512 + k0 + q * 8);                          \
    }                                                                                \
    _Pragma("unroll")                                                                \
    for (int l = 0; l < 4; l++) {    /* B: 64 k x 128 p = 1024 uint4 */              \
        int cid = tid + l * 256;                                                     \
        int kk = cid >> 4, q = cid & 15;                                             \
        size_t off = ((size_t)b * 512 + k0 + kk) * P + p0 + q * 8;                   \
        cp16(sptr(Bbuf + (kk * 136 + q * 8) * 2), g_K + off);                        \
    }                                                                                \
    asm volatile("cp.async.commit_group;");                                          \
} while (0)

    MG_LOAD(0, 0);
    MG_LOAD(1, 1);

    for (int i = 0; i < 8; i++) {
        if (i + 2 < 8) {
            MG_LOAD(i + 2, (i + 2) % 3);
            asm volatile("cp.async.wait_group 2;");
        } else if (i + 1 < 8) {
            asm volatile("cp.async.wait_group 1;");
        } else {
            asm volatile("cp.async.wait_group 0;");
        }
        __syncthreads();

        const __half* Ah = (const __half*)(dsm + (i % 3) * MG3_STAGE);
        const __half* Bh = (const __half*)((const char*)Ah + MG3_A);
#pragma unroll
        for (int ks = 0; ks < 4; ks++) {
            int kk = ks * 16;
            u32 bh[2][4];
#pragma unroll
            for (int nh = 0; nh < 2; nh++)
                ldm_x4_t(bh[nh], sptr(&Bh[(kk + (lane & 15)) * 136
                                          + wn * 32 + nh * 16 + (lane >> 4) * 8]));
#pragma unroll
            for (int mf = 0; mf < 4; mf++) {
                u32 ah[4];
                ldm_x4(ah, sptr(&Ah[(wm * 64 + mf * 16 + (lane & 15)) * 72
                                    + kk + (lane >> 4) * 8]));
#pragma unroll
                for (int nf = 0; nf < 4; nf++) {
                    u32 b0 = bh[nf >> 1][(nf & 1) * 2], b1 = bh[nf >> 1][(nf & 1) * 2 + 1];
                    mma16816h(acc[mf][nf], ah, b0, b1);
                }
            }
        }
        __syncthreads();
    }

    int g = lane >> 2, tg = lane & 3;
#pragma unroll
    for (int mf = 0; mf < 4; mf++) {
        int m1 = m0 + wm * 64 + mf * 16 + g;
#pragma unroll
        for (int nf = 0; nf < 4; nf++) {
            int p = p0 + wn * 32 + nf * 8 + tg * 2;
            float bs1 = bm[m1], bs2 = bm[m1 + 8];
            *(float2*)(out + ((size_t)b * C + m1) * P + p) =
                make_float2(acc[mf][nf][0] + bs1, acc[mf][nf][1] + bs1);
            *(float2*)(out + ((size_t)b * C + m1 + 8) * P + p) =
                make_float2(acc[mf][nf][2] + bs2, acc[mf][nf][3] + bs2);
        }
    }
}

// ============================================================
extern "C" void kernel_launch(void* const* d_in, const int* in_sizes, int n_in,
                              void* d_out, int out_size) {
    const float* x       = (const float*)d_in[0];
    const float* w_red   = (const float*)d_in[1];
    const float* b_red   = (const float*)d_in[2];
    const float* w_u     = (const float*)d_in[3];
    const float* b_u     = (const float*)d_in[4];
    const float* w_lam   = (const float*)d_in[5];
    const float* b_lam   = (const float*)d_in[6];
    const float* w_wt    = (const float*)d_in[7];
    const float* b_wt    = (const float*)d_in[8];
    const float* w_merge = (const float*)d_in[9];
    const float* b_merge = (const float*)d_in[10];
    float* out = (float*)d_out;

    cudaFuncSetAttribute(k_rul,
                         cudaFuncAttributeMaxDynamicSharedMemorySize, RU_SMEM);
    cudaFuncSetAttribute(k_merge_mma,
                         cudaFuncAttributeMaxDynamicSharedMemorySize, MG3_SMEM);

    k_prep<<<704, 256>>>(w_merge, w_u, w_lam, w_red);
    k_rul<<<dim3(32, NB), 256, RU_SMEM>>>(x, b_red, w_wt, b_wt, b_u, b_lam);
    k_scan<<<dim3(256, NB), 512>>>(x);
    k_merge_mma<<<dim3(32, 2, NB), 256, MG3_SMEM>>>(out, b_merge);
}

// round 14
// speedup vs baseline: 4.7054x; 1.0003x over previous
#include <cuda_runtime.h>
#include <cuda_fp16.h>

#define S 64
#define NB 8
#define C 256
#define CR 64
#define P 4096   // S*S per plane

typedef unsigned int u32;

// ---- scratch (device globals; no runtime allocation allowed) ----
__device__ __half g_u  [NB * C * P];                 // 16 MB fp16
__device__ __half g_lam[NB * C * P];                 // 16 MB fp16
__device__ float  g_Rv [NB * P];                     // 128 KB fp32
__device__ __half g_K  [NB * 512 * P];               // 32 MB fp16 (0..255 = A dir, 256..511 = B dir)
__device__ __half g_Wf [256 * 512];                  // merge W fp16 (folded)
__device__ __half g_Wul[512 * 64];                   // u/lam W fp16
__device__ __half g_Wred[64 * 256];                  // red  W fp16

// ---- helpers ----
__device__ __forceinline__ u32 sptr(const void* p) {
    return (u32)__cvta_generic_to_shared(p);
}
__device__ __forceinline__ void ldm_x4(u32* r, u32 addr) {
    asm volatile("ldmatrix.sync.aligned.m8n8.x4.shared.b16 {%0,%1,%2,%3}, [%4];"
                 : "=r"(r[0]), "=r"(r[1]), "=r"(r[2]), "=r"(r[3]) : "r"(addr));
}
__device__ __forceinline__ void ldm_x4_t(u32* r, u32 addr) {
    asm volatile("ldmatrix.sync.aligned.m8n8.x4.trans.shared.b16 {%0,%1,%2,%3}, [%4];"
                 : "=r"(r[0]), "=r"(r[1]), "=r"(r[2]), "=r"(r[3]) : "r"(addr));
}
__device__ __forceinline__ void mma16816h(float* d, const u32* a, u32 b0, u32 b1) {
    asm volatile("mma.sync.aligned.m16n8k16.row.col.f32.f16.f16.f32 "
                 "{%0,%1,%2,%3}, {%4,%5,%6,%7}, {%8,%9}, {%0,%1,%2,%3};"
                 : "+f"(d[0]), "+f"(d[1]), "+f"(d[2]), "+f"(d[3])
                 : "r"(a[0]), "r"(a[1]), "r"(a[2]), "r"(a[3]), "r"(b0), "r"(b1));
}
__device__ __forceinline__ void cp16(u32 dst, const void* src) {
    asm volatile("cp.async.cg.shared.global [%0], [%1], 16;" :: "r"(dst), "l"(src));
}

// ============================================================
// Prep: fold merge weights; all weights -> single fp16.
// ============================================================
__global__ void k_prep(const float* __restrict__ wm,
                       const float* __restrict__ wu,
                       const float* __restrict__ wl,
                       const float* __restrict__ wr) {
    int i = blockIdx.x * 256 + threadIdx.x;
    if (i < 131072) {
        int o = i >> 9, k = i & 511;
        float v = wm[o * 1024 + k] + wm[o * 1024 + k + 512];
        g_Wf[o * 512 + k] = __float2half(v);
    } else if (i < 163840) {
        int j = i - 131072;
        int m = j >> 6, k = j & 63;
        float v = (m < 256) ? wu[m * 64 + k] : wl[(m - 256) * 64 + k];
        g_Wul[m * 64 + k] = __float2half(v);
    } else if (i < 180224) {
        int j = i - 163840;
        int m = j >> 8, k = j & 255;
        g_Wred[m * 256 + k] = __float2half(wr[m * 256 + k]);
    }
}

// ============================================================
// K1 (fused red + Rv + u/lam): one CTA owns one (b, 128-p tile).
// ============================================================
#define RU_BS2   33792
#define RU_SMEM  51200

__global__ __launch_bounds__(256) void k_rul(const float* __restrict__ x,
                                             const float* __restrict__ bred,
                                             const float* __restrict__ wwt,
                                             const float* __restrict__ bwt,
                                             const float* __restrict__ bu,
                                             const float* __restrict__ bl) {
    extern __shared__ __align__(16) char dsm[];
    __half* As   = (__half*)(dsm);               // phase1 A: 64x40 = 5120B
    __half* Bsx  = (__half*)(dsm + 5120);        // phase1 B: 32x136 = 8704B
    float*  redT = (float*)(dsm);                // 64x132 fp32 = 33792B
    __half* Aul  = (__half*)(dsm);               // phase2 A: 128x72 = 18432B
    __half* Bs2  = (__half*)(dsm + RU_BS2);      // red fp16 [64k][136p]
    __shared__ float ws[192];
    __shared__ float bs3[3];

    int b  = blockIdx.y;
    int p0 = blockIdx.x * 128;
    int tid = threadIdx.x;
    int wid = tid >> 5, lane = tid & 31;
    for (int i = tid; i < 192; i += 256) ws[i] = wwt[i];
    if (tid < 3) bs3[tid] = bwt[tid];

    // ================= Phase 1: red GEMM =================
    {
        int wm = wid & 3;       // 4 m-slots x 16 rows
        int wn = wid >> 2;      // 2 n-slots x 64 cols
        float acc[8][4];
#pragma unroll
        for (int i = 0; i < 8; i++)
#pragma unroll
            for (int q = 0; q < 4; q++) acc[i][q] = 0.f;

        const float* xb = x + (size_t)b * C * P;
        for (int k0 = 0; k0 < 256; k0 += 32) {
            {   // A chunk: 64 rows x 32 k
                int row = tid >> 2, q = tid & 3;
                *(uint4*)&As[row * 40 + q * 8] =
                    *(const uint4*)(g_Wred + row * 256 + k0 + q * 8);
            }
#pragma unroll
            for (int l = 0; l < 2; l++) {   // x chunk 32k x 128p -> fp16
                int cid = tid + l * 256;
                int kk = cid >> 4, pq = cid & 15;
                const float* src = xb + (size_t)(k0 + kk) * P + p0 + pq * 8;
                float4 v0 = *(const float4*)(src);
                float4 v1 = *(const float4*)(src + 4);
                __half2 h[4];
                h[0] = __floats2half2_rn(v0.x, v0.y);
                h[1] = __floats2half2_rn(v0.z, v0.w);
                h[2] = __floats2half2_rn(v1.x, v1.y);
                h[3] = __floats2half2_rn(v1.z, v1.w);
                *(uint4*)&Bsx[kk * 136 + pq * 8] = *(uint4*)h;
            }
            __syncthreads();
#pragma unroll
            for (int ks = 0; ks < 2; ks++) {
                int kk = ks * 16;
                u32 ah[4], bh[4][4];
                ldm_x4(ah, sptr(&As[(wm * 16 + (lane & 15)) * 40 + kk + (lane >> 4) * 8]));
#pragma unroll
                for (int nh = 0; nh < 4; nh++)
                    ldm_x4_t(bh[nh], sptr(&Bsx[(kk + (lane & 15)) * 136
                                               + wn * 64 + nh * 16 + (lane >> 4) * 8]));
#pragma unroll
                for (int nf = 0; nf < 8; nf++) {
                    u32 b0 = bh[nf >> 1][(nf & 1) * 2], b1 = bh[nf >> 1][(nf & 1) * 2 + 1];
                    mma16816h(acc[nf], ah, b0, b1);
                }
            }
            __syncthreads();
        }

        // epilogue: bias; stage redT fp32 (Rv) + Bs2 fp16 (phase-2 B)
        int g = lane >> 2, tg = lane & 3;
        int m1 = wm * 16 + g;
        float bsA = __ldg(bred + m1), bsB = __ldg(bred + m1 + 8);
#pragma unroll
        for (int nf = 0; nf < 8; nf++) {
            int p = wn * 64 + nf * 8 + tg * 2;
            float v0 = acc[nf][0] + bsA, v1 = acc[nf][1] + bsA;
            float v2 = acc[nf][2] + bsB, v3 = acc[nf][3] + bsB;
            *(float2*)&redT[m1 * 132 + p]       = make_float2(v0, v1);
            *(float2*)&redT[(m1 + 8) * 132 + p] = make_float2(v2, v3);
            *(__half2*)&Bs2[m1 * 136 + p]       = __floats2half2_rn(v0, v1);
            *(__half2*)&Bs2[(m1 + 8) * 136 + p] = __floats2half2_rn(v2, v3);
        }
    }
    __syncthreads();

    // ================= Rv =================
    if (tid < 128) {
        int w = tid & 63;
        float a0 = bs3[0], a1 = bs3[1], a2 = bs3[2];
#pragma unroll 16
        for (int m = 0; m < 64; m++) {
            float r = redT[m * 132 + tid];
            a0 += ws[m]       * r;
            a1 += ws[64 + m]  * r;
            a2 += ws[128 + m] * r;
        }
        float s0 = 1.f / (1.f + expf(-a0));
        float s1 = 1.f / (1.f + expf(-a1));
        float s2 = 1.f / (1.f + expf(-a2));
        float den = fmaxf(s0 + s1 + s2, 1e-6f);
        float rv = s1;
        if (w >= 1)     rv += s0;
        if (w <= S - 2) rv += s2;
        g_Rv[(size_t)b * P + p0 + tid] = rv / den;
    }
    __syncthreads();

    // ================= Phase 2: u/lam, 4 m-chunks of 128 =================
    {
        int wm = wid >> 2, wn = wid & 3;    // 2 m-slots x 4 n-slots, warp 64x32
        for (int mc = 0; mc < 4; mc++) {
#pragma unroll
            for (int l = 0; l < 4; l++) {
                int cid = tid + l * 256;
                int row = cid >> 3, q = cid & 7;
                *(uint4*)&Aul[row * 72 + q * 8] =
                    *(const uint4*)(g_Wul + (size_t)(mc * 128 + row) * 64 + q * 8);
            }
            __syncthreads();

            float acc[4][4][4];
#pragma unroll
            for (int i = 0; i < 4; i++)
#pragma unroll
                for (int j = 0; j < 4; j++)
#pragma unroll
                    for (int q = 0; q < 4; q++) acc[i][j][q] = 0.f;

#pragma unroll
            for (int ks = 0; ks < 4; ks++) {
                int kk = ks * 16;
                u32 bh[2][4];
#pragma unroll
                for (int nh = 0; nh < 2; nh++)
                    ldm_x4_t(bh[nh], sptr(&Bs2[(kk + (lane & 15)) * 136
                                               + wn * 32 + nh * 16 + (lane >> 4) * 8]));
#pragma unroll
                for (int mf = 0; mf < 4; mf++) {
                    u32 ah[4];
                    ldm_x4(ah, sptr(&Aul[(wm * 64 + mf * 16 + (lane & 15)) * 72
                                         + kk + (lane >> 4) * 8]));
#pragma unroll
                    for (int nf = 0; nf < 4; nf++) {
                        u32 b0 = bh[nf >> 1][(nf & 1) * 2], b1 = bh[nf >> 1][(nf & 1) * 2 + 1];
                        mma16816h(acc[mf][nf], ah, b0, b1);
                    }
                }
            }

            int mg0 = mc * 128;
            __half* outb; const float* biasArr; int mofs;
            if (mg0 < 256) { outb = g_u   + (size_t)b * C * P; biasArr = bu; mofs = mg0; }
            else           { outb = g_lam + (size_t)b * C * P; biasArr = bl; mofs = mg0 - 256; }
            int g = lane >> 2, tg = lane & 3;
#pragma unroll
            for (int mf = 0; mf < 4; mf++) {
                int m1 = mofs + wm * 64 + mf * 16 + g;
#pragma unroll
                for (int nf = 0; nf < 4; nf++) {
                    int p = p0 + wn * 32 + nf * 8 + tg * 2;
                    float bs1 = biasArr[m1], bs2v = biasArr[m1 + 8];
                    *(__half2*)(outb + (size_t)m1 * P + p) =
                        __floats2half2_rn(acc[mf][nf][0] + bs1, acc[mf][nf][1] + bs1);
                    *(__half2*)(outb + (size_t)(m1 + 8) * P + p) =
                        __floats2half2_rn(acc[mf][nf][2] + bs2v, acc[mf][nf][3] + bs2v);
                }
            }
            __syncthreads();    // Aul reuse
        }
    }
}

// ============================================================
// K4: fused dual scan along w; u/lam fp16 in, fp16 Kmat planes out.
// ============================================================
__global__ __launch_bounds__(512) void k_scan(const float* __restrict__ x) {
    __shared__ float ls[64 * 65];
    int b = blockIdx.y, c = blockIdx.x;
    size_t base = ((size_t)b * C + c) * P;
    const float*  xp = x + base;
    const __half* up = g_u + base;
    const __half* lp = g_lam + base;
    const float*  rv = g_Rv + (size_t)b * P;
    __half* AP = g_K + ((size_t)b * 512 + c) * P;
    __half* BP = g_K + ((size_t)b * 512 + 256 + c) * P;
    int tid = threadIdx.x;

    {   // stage lam plane (4096 fp16) into padded fp32 smem
        int row = tid >> 3, q = tid & 7;
        uint4 raw = *(const uint4*)(lp + row * 64 + q * 8);
        __half2* hp = (__half2*)&raw;
#pragma unroll
        for (int j = 0; j < 4; j++) {
            float2 f = __half22float2(hp[j]);
            ls[row * 65 + q * 8 + j * 2]     = f.x;
            ls[row * 65 + q * 8 + j * 2 + 1] = f.y;
        }
    }
    __syncthreads();

    int wid = tid >> 5, lane = tid & 31;
#pragma unroll
    for (int r = 0; r < 4; r++) {
        int h = wid + r * 16;
        int hb = 63 - h;
        int w0 = lane * 2, w1 = w0 + 1;
        float2 av = *(const float2*)(rv + h * 64 + w0);
        float a0 = av.x, a1 = av.y;
        float2 xv = *(const float2*)(xp + h * 64 + w0);
        float bA0 = ls[w0 * 65 + h] * xv.x;
        float bA1 = ls[w1 * 65 + h] * xv.y;
        float bB0 = ls[(63 - w0) * 65 + hb] * xv.x;
        float bB1 = ls[(63 - w1) * 65 + hb] * xv.y;
        float ca  = a0 * a1;
        float cbA = a1 * bA0 + bA1;
        float cbB = a1 * bB0 + bB1;
#pragma unroll
        for (int d = 1; d < 32; d <<= 1) {
            float pa  = __shfl_up_sync(0xffffffffu, ca,  d);
            float pbA = __shfl_up_sync(0xffffffffu, cbA, d);
            float pbB = __shfl_up_sync(0xffffffffu, cbB, d);
            if (lane >= d) {
                cbA = ca * pbA + cbA;
                cbB = ca * pbB + cbB;
                ca  = ca * pa;
            }
        }
        float eA = __shfl_up_sync(0xffffffffu, cbA, 1);
        float eB = __shfl_up_sync(0xffffffffu, cbB, 1);
        if (lane == 0) { eA = 0.f; eB = 0.f; }
        float hA0 = a0 * eA + bA0;
        float hA1 = a1 * hA0 + bA1;
        float hB0 = a0 * eB + bB0;
        float hB1 = a1 * hB0 + bB1;
        float2 uv  = __half22float2(*(const __half2*)(up + h  * 64 + w0));
        float2 uvb = __half22float2(*(const __half2*)(up + hb * 64 + w0));
        *(__half2*)(AP + h * 64 + w0) = __floats2half2_rn(hA0 * uv.x,  hA1 * uv.y);
        *(__half2*)(BP + h * 64 + w0) = __floats2half2_rn(hB0 * uvb.x, hB1 * uvb.y);
    }
}

// ============================================================
// K5 (fp16 1-term): out = Wf @ Kmat + bias. K=512, BK=64 (8 chunks).
// CTA tile M=128 x N=128, 256 threads (8 warps, 2x4), warp 64x32.
// 3-stage cp.async smem pipeline + register fragment double-buffer
// (ldmatrix for ks+1 issued before the 16 MMAs of ks).
// ============================================================
#define MG3_A 18432                 // 128 x 72 halves
#define MG3_B 17408                 // 64 x 136 halves
#define MG3_STAGE (MG3_A + MG3_B)   // 35840
#define MG3_SMEM (3 * MG3_STAGE)    // 107520

__global__ __launch_bounds__(256, 2) void k_merge_mma(float* __restrict__ out,
                                                      const float* __restrict__ bm) {
    extern __shared__ __align__(16) char dsm[];
    int b  = blockIdx.z;
    int m0 = blockIdx.y * 128;
    int p0 = blockIdx.x * 128;
    int tid = threadIdx.x;
    int wid = tid >> 5, lane = tid & 31;
    int wm = wid >> 2, wn = wid & 3;    // 2 m-slots x 4 n-slots

    float acc[4][4][4];
#pragma unroll
    for (int i = 0; i < 4; i++)
#pragma unroll
        for (int j = 0; j < 4; j++)
#pragma unroll
            for (int q = 0; q < 4; q++) acc[i][j][q] = 0.f;

#define MG_LOAD(chunk, buf) do {                                                     \
    char* Abuf = dsm + (buf) * MG3_STAGE;                                            \
    char* Bbuf = Abuf + MG3_A;                                                       \
    int k0 = (chunk) * 64;                                                           \
    _Pragma("unroll")                                                                \
    for (int l = 0; l < 4; l++) {    /* A: 128 rows x 64 k = 1024 uint4 */           \
        int cid = tid + l * 256;                                                     \
        int row = cid >> 3, q = cid & 7;                                             \
        cp16(sptr(Abuf + (row * 72 + q * 8) * 2),                                    \
             g_Wf + (size_t)(m0 + row) * 512 + k0 + q * 8);                          \
    }                                                                                \
    _Pragma("unroll")                                                                \
    for (int l = 0; l < 4; l++) {    /* B: 64 k x 128 p = 1024 uint4 */              \
        int cid = tid + l * 256;                                                     \
        int kk = cid >> 4, q = cid & 15;                                             \
        size_t off = ((size_t)b * 512 + k0 + kk) * P + p0 + q * 8;                   \
        cp16(sptr(Bbuf + (kk * 136 + q * 8) * 2), g_K + off);                        \
    }                                                                                \
    asm volatile("cp.async.commit_group;");                                          \
} while (0)

    MG_LOAD(0, 0);
    MG_LOAD(1, 1);

    // lane-invariant fragment sub-offsets (halves -> bytes via *2)
    u32 a_lane_off = ((lane & 15) * 72 + (lane >> 4) * 8) * 2;
    u32 b_lane_off = ((lane & 15) * 136 + (lane >> 4) * 8) * 2;

    for (int i = 0; i < 8; i++) {
        if (i + 2 < 8) {
            MG_LOAD(i + 2, (i + 2) % 3);
            asm volatile("cp.async.wait_group 2;");
        } else if (i + 1 < 8) {
            asm volatile("cp.async.wait_group 1;");
        } else {
            asm volatile("cp.async.wait_group 0;");
        }
        __syncthreads();

        u32 Abase = sptr(dsm + (i % 3) * MG3_STAGE) + wm * 64 * 72 * 2 + a_lane_off;
        u32 Bbase = sptr(dsm + (i % 3) * MG3_STAGE + MG3_A) + wn * 32 * 2 + b_lane_off;

        u32 bfrag[2][2][4];     // [buf][nh][4]
        u32 afrag[2][4][4];     // [buf][mf][4]

        // prologue: fragments for ks = 0
#pragma unroll
        for (int nh = 0; nh < 2; nh++)
            ldm_x4_t(bfrag[0][nh], Bbase + nh * 16 * 2);
#pragma unroll
        for (int mf = 0; mf < 4; mf++)
            ldm_x4(afrag[0][mf], Abase + mf * 16 * 72 * 2);

#pragma unroll
        for (int ks = 0; ks < 4; ks++) {
            int cur = ks & 1, nxt = cur ^ 1;
            if (ks < 3) {       // prefetch fragments for ks+1
                u32 kb = (u32)((ks + 1) * 16 * 2);
#pragma unroll
                for (int nh = 0; nh < 2; nh++)
                    ldm_x4_t(bfrag[nxt][nh], Bbase + kb * 136 + nh * 16 * 2);
#pragma unroll
                for (int mf = 0; mf < 4; mf++)
                    ldm_x4(afrag[nxt][mf], Abase + mf * 16 * 72 * 2 + kb);
            }
#pragma unroll
            for (int mf = 0; mf < 4; mf++)
#pragma unroll
                for (int nf = 0; nf < 4; nf++) {
                    u32 b0 = bfrag[cur][nf >> 1][(nf & 1) * 2];
                    u32 b1 = bfrag[cur][nf >> 1][(nf & 1) * 2 + 1];
                    mma16816h(acc[mf][nf], afrag[cur][mf], b0, b1);
                }
        }
        __syncthreads();
    }

    int g = lane >> 2, tg = lane & 3;
#pragma unroll
    for (int mf = 0; mf < 4; mf++) {
        int m1 = m0 + wm * 64 + mf * 16 + g;
#pragma unroll
        for (int nf = 0; nf < 4; nf++) {
            int p = p0 + wn * 32 + nf * 8 + tg * 2;
            float bs1 = bm[m1], bs2 = bm[m1 + 8];
            *(float2*)(out + ((size_t)b * C + m1) * P + p) =
                make_float2(acc[mf][nf][0] + bs1, acc[mf][nf][1] + bs1);
            *(float2*)(out + ((size_t)b * C + m1 + 8) * P + p) =
                make_float2(acc[mf][nf][2] + bs2, acc[mf][nf][3] + bs2);
        }
    }
}

// ============================================================
extern "C" void kernel_launch(void* const* d_in, const int* in_sizes, int n_in,
                              void* d_out, int out_size) {
    const float* x       = (const float*)d_in[0];
    const float* w_red   = (const float*)d_in[1];
    const float* b_red   = (const float*)d_in[2];
    const float* w_u     = (const float*)d_in[3];
    const float* b_u     = (const float*)d_in[4];
    const float* w_lam   = (const float*)d_in[5];
    const float* b_lam   = (const float*)d_in[6];
    const float* w_wt    = (const float*)d_in[7];
    const float* b_wt    = (const float*)d_in[8];
    const float* w_merge = (const float*)d_in[9];
    const float* b_merge = (const float*)d_in[10];
    float* out = (float*)d_out;

    cudaFuncSetAttribute(k_rul,
                         cudaFuncAttributeMaxDynamicSharedMemorySize, RU_SMEM);
    cudaFuncSetAttribute(k_merge_mma,
                         cudaFuncAttributeMaxDynamicSharedMemorySize, MG3_SMEM);

    k_prep<<<704, 256>>>(w_merge, w_u, w_lam, w_red);
    k_rul<<<dim3(32, NB), 256, RU_SMEM>>>(x, b_red, w_wt, b_wt, b_u, b_lam);
    k_scan<<<dim3(256, NB), 512>>>(x);
    k_merge_mma<<<dim3(32, 2, NB), 256, MG3_SMEM>>>(out, b_merge);
}

// round 16
// speedup vs baseline: 4.9803x; 1.0584x over previous
#include <cuda_runtime.h>
#include <cuda_fp16.h>

#define S 64
#define NB 8
#define C 256
#define CR 64
#define P 4096   // S*S per plane

typedef unsigned int u32;

// ---- scratch (device globals; no runtime allocation allowed) ----
__device__ __half g_u  [NB * C * P];                 // 16 MB fp16
__device__ __half g_lam[NB * C * P];                 // 16 MB fp16
__device__ float  g_Rv [NB * P];                     // 128 KB fp32
__device__ __half g_K  [NB * 512 * P];               // 32 MB fp16 (0..255 = A dir, 256..511 = B dir)
__device__ __half g_Wf [256 * 512];                  // merge W fp16 (folded)
__device__ __half g_Wul[512 * 64];                   // u/lam W fp16
__device__ __half g_Wred[64 * 256];                  // red  W fp16

// ---- helpers ----
__device__ __forceinline__ u32 sptr(const void* p) {
    return (u32)__cvta_generic_to_shared(p);
}
__device__ __forceinline__ void ldm_x4(u32* r, u32 addr) {
    asm volatile("ldmatrix.sync.aligned.m8n8.x4.shared.b16 {%0,%1,%2,%3}, [%4];"
                 : "=r"(r[0]), "=r"(r[1]), "=r"(r[2]), "=r"(r[3]) : "r"(addr));
}
__device__ __forceinline__ void ldm_x4_t(u32* r, u32 addr) {
    asm volatile("ldmatrix.sync.aligned.m8n8.x4.trans.shared.b16 {%0,%1,%2,%3}, [%4];"
                 : "=r"(r[0]), "=r"(r[1]), "=r"(r[2]), "=r"(r[3]) : "r"(addr));
}
__device__ __forceinline__ void mma16816h(float* d, const u32* a, u32 b0, u32 b1) {
    asm volatile("mma.sync.aligned.m16n8k16.row.col.f32.f16.f16.f32 "
                 "{%0,%1,%2,%3}, {%4,%5,%6,%7}, {%8,%9}, {%0,%1,%2,%3};"
                 : "+f"(d[0]), "+f"(d[1]), "+f"(d[2]), "+f"(d[3])
                 : "r"(a[0]), "r"(a[1]), "r"(a[2]), "r"(a[3]), "r"(b0), "r"(b1));
}
__device__ __forceinline__ void cp16(u32 dst, const void* src) {
    asm volatile("cp.async.cg.shared.global [%0], [%1], 16;" :: "r"(dst), "l"(src));
}

// ============================================================
// Prep: fold merge weights; all weights -> single fp16.
// ============================================================
__global__ void k_prep(const float* __restrict__ wm,
                       const float* __restrict__ wu,
                       const float* __restrict__ wl,
                       const float* __restrict__ wr) {
    int i = blockIdx.x * 256 + threadIdx.x;
    if (i < 131072) {
        int o = i >> 9, k = i & 511;
        float v = wm[o * 1024 + k] + wm[o * 1024 + k + 512];
        g_Wf[o * 512 + k] = __float2half(v);
    } else if (i < 163840) {
        int j = i - 131072;
        int m = j >> 6, k = j & 63;
        float v = (m < 256) ? wu[m * 64 + k] : wl[(m - 256) * 64 + k];
        g_Wul[m * 64 + k] = __float2half(v);
    } else if (i < 180224) {
        int j = i - 163840;
        int m = j >> 8, k = j & 255;
        g_Wred[m * 256 + k] = __float2half(wr[m * 256 + k]);
    }
}

// ============================================================
// K1 (fused red + Rv + u/lam): one CTA owns one (b, 128-p tile).
// ============================================================
#define RU_BS2   33792
#define RU_SMEM  51200

__global__ __launch_bounds__(256) void k_rul(const float* __restrict__ x,
                                             const float* __restrict__ bred,
                                             const float* __restrict__ wwt,
                                             const float* __restrict__ bwt,
                                             const float* __restrict__ bu,
                                             const float* __restrict__ bl) {
    extern __shared__ __align__(16) char dsm[];
    __half* As   = (__half*)(dsm);               // phase1 A: 64x40 = 5120B
    __half* Bsx  = (__half*)(dsm + 5120);        // phase1 B: 32x136 = 8704B
    float*  redT = (float*)(dsm);                // 64x132 fp32 = 33792B
    __half* Aul  = (__half*)(dsm);               // phase2 A: 128x72 = 18432B
    __half* Bs2  = (__half*)(dsm + RU_BS2);      // red fp16 [64k][136p]
    __shared__ float ws[192];
    __shared__ float bs3[3];

    int b  = blockIdx.y;
    int p0 = blockIdx.x * 128;
    int tid = threadIdx.x;
    int wid = tid >> 5, lane = tid & 31;
    for (int i = tid; i < 192; i += 256) ws[i] = wwt[i];
    if (tid < 3) bs3[tid] = bwt[tid];

    // ================= Phase 1: red GEMM =================
    {
        int wm = wid & 3;       // 4 m-slots x 16 rows
        int wn = wid >> 2;      // 2 n-slots x 64 cols
        float acc[8][4];
#pragma unroll
        for (int i = 0; i < 8; i++)
#pragma unroll
            for (int q = 0; q < 4; q++) acc[i][q] = 0.f;

        const float* xb = x + (size_t)b * C * P;
        for (int k0 = 0; k0 < 256; k0 += 32) {
            {   // A chunk: 64 rows x 32 k
                int row = tid >> 2, q = tid & 3;
                *(uint4*)&As[row * 40 + q * 8] =
                    *(const uint4*)(g_Wred + row * 256 + k0 + q * 8);
            }
#pragma unroll
            for (int l = 0; l < 2; l++) {   // x chunk 32k x 128p -> fp16
                int cid = tid + l * 256;
                int kk = cid >> 4, pq = cid & 15;
                const float* src = xb + (size_t)(k0 + kk) * P + p0 + pq * 8;
                float4 v0 = *(const float4*)(src);
                float4 v1 = *(const float4*)(src + 4);
                __half2 h[4];
                h[0] = __floats2half2_rn(v0.x, v0.y);
                h[1] = __floats2half2_rn(v0.z, v0.w);
                h[2] = __floats2half2_rn(v1.x, v1.y);
                h[3] = __floats2half2_rn(v1.z, v1.w);
                *(uint4*)&Bsx[kk * 136 + pq * 8] = *(uint4*)h;
            }
            __syncthreads();
#pragma unroll
            for (int ks = 0; ks < 2; ks++) {
                int kk = ks * 16;
                u32 ah[4], bh[4][4];
                ldm_x4(ah, sptr(&As[(wm * 16 + (lane & 15)) * 40 + kk + (lane >> 4) * 8]));
#pragma unroll
                for (int nh = 0; nh < 4; nh++)
                    ldm_x4_t(bh[nh], sptr(&Bsx[(kk + (lane & 15)) * 136
                                               + wn * 64 + nh * 16 + (lane >> 4) * 8]));
#pragma unroll
                for (int nf = 0; nf < 8; nf++) {
                    u32 b0 = bh[nf >> 1][(nf & 1) * 2], b1 = bh[nf >> 1][(nf & 1) * 2 + 1];
                    mma16816h(acc[nf], ah, b0, b1);
                }
            }
            __syncthreads();
        }

        // epilogue: bias; stage redT fp32 (Rv) + Bs2 fp16 (phase-2 B)
        int g = lane >> 2, tg = lane & 3;
        int m1 = wm * 16 + g;
        float bsA = __ldg(bred + m1), bsB = __ldg(bred + m1 + 8);
#pragma unroll
        for (int nf = 0; nf < 8; nf++) {
            int p = wn * 64 + nf * 8 + tg * 2;
            float v0 = acc[nf][0] + bsA, v1 = acc[nf][1] + bsA;
            float v2 = acc[nf][2] + bsB, v3 = acc[nf][3] + bsB;
            *(float2*)&redT[m1 * 132 + p]       = make_float2(v0, v1);
            *(float2*)&redT[(m1 + 8) * 132 + p] = make_float2(v2, v3);
            *(__half2*)&Bs2[m1 * 136 + p]       = __floats2half2_rn(v0, v1);
            *(__half2*)&Bs2[(m1 + 8) * 136 + p] = __floats2half2_rn(v2, v3);
        }
    }
    __syncthreads();

    // ================= Rv =================
    if (tid < 128) {
        int w = tid & 63;
        float a0 = bs3[0], a1 = bs3[1], a2 = bs3[2];
#pragma unroll 16
        for (int m = 0; m < 64; m++) {
            float r = redT[m * 132 + tid];
            a0 += ws[m]       * r;
            a1 += ws[64 + m]  * r;
            a2 += ws[128 + m] * r;
        }
        float s0 = 1.f / (1.f + expf(-a0));
        float s1 = 1.f / (1.f + expf(-a1));
        float s2 = 1.f / (1.f + expf(-a2));
        float den = fmaxf(s0 + s1 + s2, 1e-6f);
        float rv = s1;
        if (w >= 1)     rv += s0;
        if (w <= S - 2) rv += s2;
        g_Rv[(size_t)b * P + p0 + tid] = rv / den;
    }
    __syncthreads();

    // ================= Phase 2: u/lam, 4 m-chunks of 128 =================
    {
        int wm = wid >> 2, wn = wid & 3;    // 2 m-slots x 4 n-slots, warp 64x32
        for (int mc = 0; mc < 4; mc++) {
#pragma unroll
            for (int l = 0; l < 4; l++) {
                int cid = tid + l * 256;
                int row = cid >> 3, q = cid & 7;
                *(uint4*)&Aul[row * 72 + q * 8] =
                    *(const uint4*)(g_Wul + (size_t)(mc * 128 + row) * 64 + q * 8);
            }
            __syncthreads();

            float acc[4][4][4];
#pragma unroll
            for (int i = 0; i < 4; i++)
#pragma unroll
                for (int j = 0; j < 4; j++)
#pragma unroll
                    for (int q = 0; q < 4; q++) acc[i][j][q] = 0.f;

#pragma unroll
            for (int ks = 0; ks < 4; ks++) {
                int kk = ks * 16;
                u32 bh[2][4];
#pragma unroll
                for (int nh = 0; nh < 2; nh++)
                    ldm_x4_t(bh[nh], sptr(&Bs2[(kk + (lane & 15)) * 136
                                               + wn * 32 + nh * 16 + (lane >> 4) * 8]));
#pragma unroll
                for (int mf = 0; mf < 4; mf++) {
                    u32 ah[4];
                    ldm_x4(ah, sptr(&Aul[(wm * 64 + mf * 16 + (lane & 15)) * 72
                                         + kk + (lane >> 4) * 8]));
#pragma unroll
                    for (int nf = 0; nf < 4; nf++) {
                        u32 b0 = bh[nf >> 1][(nf & 1) * 2], b1 = bh[nf >> 1][(nf & 1) * 2 + 1];
                        mma16816h(acc[mf][nf], ah, b0, b1);
                    }
                }
            }

            int mg0 = mc * 128;
            __half* outb; const float* biasArr; int mofs;
            if (mg0 < 256) { outb = g_u   + (size_t)b * C * P; biasArr = bu; mofs = mg0; }
            else           { outb = g_lam + (size_t)b * C * P; biasArr = bl; mofs = mg0 - 256; }
            int g = lane >> 2, tg = lane & 3;
#pragma unroll
            for (int mf = 0; mf < 4; mf++) {
                int m1 = mofs + wm * 64 + mf * 16 + g;
#pragma unroll
                for (int nf = 0; nf < 4; nf++) {
                    int p = p0 + wn * 32 + nf * 8 + tg * 2;
                    float bs1 = biasArr[m1], bs2v = biasArr[m1 + 8];
                    *(__half2*)(outb + (size_t)m1 * P + p) =
                        __floats2half2_rn(acc[mf][nf][0] + bs1, acc[mf][nf][1] + bs1);
                    *(__half2*)(outb + (size_t)(m1 + 8) * P + p) =
                        __floats2half2_rn(acc[mf][nf][2] + bs2v, acc[mf][nf][3] + bs2v);
                }
            }
            __syncthreads();    // Aul reuse
        }
    }
}

// ============================================================
// K4: fused dual scan along w. Width-16 segmented scan:
// each warp = 2 rows (lanes 0-15 / 16-31), 4 elements per lane.
// Shuffle count per row drops 17 -> 7 vs per-row warp scan.
// ============================================================
__global__ __launch_bounds__(512) void k_scan(const float* __restrict__ x) {
    __shared__ float ls[64 * 65];
    int b = blockIdx.y, c = blockIdx.x;
    size_t base = ((size_t)b * C + c) * P;
    const float*  xp = x + base;
    const __half* up = g_u + base;
    const __half* lp = g_lam + base;
    const float*  rv = g_Rv + (size_t)b * P;
    __half* AP = g_K + ((size_t)b * 512 + c) * P;
    __half* BP = g_K + ((size_t)b * 512 + 256 + c) * P;
    int tid = threadIdx.x;

    {   // stage lam plane (4096 fp16) into padded fp32 smem
        int row = tid >> 3, q = tid & 7;
        uint4 raw = *(const uint4*)(lp + row * 64 + q * 8);
        __half2* hp = (__half2*)&raw;
#pragma unroll
        for (int j = 0; j < 4; j++) {
            float2 f = __half22float2(hp[j]);
            ls[row * 65 + q * 8 + j * 2]     = f.x;
            ls[row * 65 + q * 8 + j * 2 + 1] = f.y;
        }
    }
    __syncthreads();

    int wid = tid >> 5, lane = tid & 31;
    int seg = lane >> 4;        // 0/1: which row of the pair
    int sl  = lane & 15;        // lane within 16-wide segment
    int w0  = sl * 4;

#pragma unroll
    for (int r = 0; r < 2; r++) {
        int h  = r * 32 + wid * 2 + seg;
        int hb = 63 - h;

        float4 xv = *(const float4*)(xp + h * 64 + w0);
        float4 av = *(const float4*)(rv + h * 64 + w0);
        float a[4]  = {av.x, av.y, av.z, av.w};
        float xe[4] = {xv.x, xv.y, xv.z, xv.w};
        float bA[4], bB[4];
#pragma unroll
        for (int i = 0; i < 4; i++) {
            bA[i] = ls[(w0 + i) * 65 + h] * xe[i];
            bB[i] = ls[(63 - (w0 + i)) * 65 + hb] * xe[i];
        }
        // local 4-step composite
        float ca  = a[0] * a[1] * a[2] * a[3];
        float cbA = ((bA[0] * a[1] + bA[1]) * a[2] + bA[2]) * a[3] + bA[3];
        float cbB = ((bB[0] * a[1] + bB[1]) * a[2] + bB[2]) * a[3] + bB[3];
        // width-16 segmented inclusive scan
#pragma unroll
        for (int d = 1; d < 16; d <<= 1) {
            float pa  = __shfl_up_sync(0xffffffffu, ca,  d, 16);
            float pbA = __shfl_up_sync(0xffffffffu, cbA, d, 16);
            float pbB = __shfl_up_sync(0xffffffffu, cbB, d, 16);
            if (sl >= d) {
                cbA = ca * pbA + cbA;
                cbB = ca * pbB + cbB;
                ca  = ca * pa;
            }
        }
        float eA = __shfl_up_sync(0xffffffffu, cbA, 1, 16);
        float eB = __shfl_up_sync(0xffffffffu, cbB, 1, 16);
        if (sl == 0) { eA = 0.f; eB = 0.f; }
        // expand to 4 elements
        float hA[4], hB[4];
        float pA = eA, pB = eB;
#pragma unroll
        for (int i = 0; i < 4; i++) {
            pA = a[i] * pA + bA[i]; hA[i] = pA;
            pB = a[i] * pB + bB[i]; hB[i] = pB;
        }
        // u loads (4 halves = 8B per row)
        uint2 uraw  = *(const uint2*)(up + h  * 64 + w0);
        uint2 ubraw = *(const uint2*)(up + hb * 64 + w0);
        float2 u01  = __half22float2(*(__half2*)&uraw.x);
        float2 u23  = __half22float2(*(__half2*)&uraw.y);
        float2 ub01 = __half22float2(*(__half2*)&ubraw.x);
        float2 ub23 = __half22float2(*(__half2*)&ubraw.y);
        __half2 oA0 = __floats2half2_rn(hA[0] * u01.x, hA[1] * u01.y);
        __half2 oA1 = __floats2half2_rn(hA[2] * u23.x, hA[3] * u23.y);
        __half2 oB0 = __floats2half2_rn(hB[0] * ub01.x, hB[1] * ub01.y);
        __half2 oB1 = __floats2half2_rn(hB[2] * ub23.x, hB[3] * ub23.y);
        *(uint2*)(AP + h * 64 + w0) = make_uint2(*(u32*)&oA0, *(u32*)&oA1);
        *(uint2*)(BP + h * 64 + w0) = make_uint2(*(u32*)&oB0, *(u32*)&oB1);
    }
}

// ============================================================
// K5 (fp16 1-term): out = Wf @ Kmat + bias. K=512, BK=64 (8 chunks).
// CTA tile M=128 x N=128, 256 threads (8 warps, 2x4), warp 64x32.
// 3-stage cp.async smem pipeline + register fragment double-buffer.
// (At the mma.sync issue floor — frozen.)
// ============================================================
#define MG3_A 18432                 // 128 x 72 halves
#define MG3_B 17408                 // 64 x 136 halves
#define MG3_STAGE (MG3_A + MG3_B)   // 35840
#define MG3_SMEM (3 * MG3_STAGE)    // 107520

__global__ __launch_bounds__(256, 2) void k_merge_mma(float* __restrict__ out,
                                                      const float* __restrict__ bm) {
    extern __shared__ __align__(16) char dsm[];
    int b  = blockIdx.z;
    int m0 = blockIdx.y * 128;
    int p0 = blockIdx.x * 128;
    int tid = threadIdx.x;
    int wid = tid >> 5, lane = tid & 31;
    int wm = wid >> 2, wn = wid & 3;    // 2 m-slots x 4 n-slots

    float acc[4][4][4];
#pragma unroll
    for (int i = 0; i < 4; i++)
#pragma unroll
        for (int j = 0; j < 4; j++)
#pragma unroll
            for (int q = 0; q < 4; q++) acc[i][j][q] = 0.f;

#define MG_LOAD(chunk, buf) do {                                                     \
    char* Abuf = dsm + (buf) * MG3_STAGE;                                            \
    char* Bbuf = Abuf + MG3_A;                                                       \
    int k0 = (chunk) * 64;                                                           \
    _Pragma("unroll")                                                                \
    for (int l = 0; l < 4; l++) {    /* A: 128 rows x 64 k = 1024 uint4 */           \
        int cid = tid + l * 256;                                                     \
        int row = cid >> 3, q = cid & 7;                                             \
        cp16(sptr(Abuf + (row * 72 + q * 8) * 2),                                    \
             g_Wf + (size_t)(m0 + row) * 512 + k0 + q * 8);                          \
    }                                                                                \
    _Pragma("unroll")                                                                \
    for (int l = 0; l < 4; l++) {    /* B: 64 k x 128 p = 1024 uint4 */              \
        int cid = tid + l * 256;                                                     \
        int kk = cid >> 4, q = cid & 15;                                             \
        size_t off = ((size_t)b * 512 + k0 + kk) * P + p0 + q * 8;                   \
        cp16(sptr(Bbuf + (kk * 136 + q * 8) * 2), g_K + off);                        \
    }                                                                                \
    asm volatile("cp.async.commit_group;");                                          \
} while (0)

    MG_LOAD(0, 0);
    MG_LOAD(1, 1);

    u32 a_lane_off = ((lane & 15) * 72 + (lane >> 4) * 8) * 2;
    u32 b_lane_off = ((lane & 15) * 136 + (lane >> 4) * 8) * 2;

    for (int i = 0; i < 8; i++) {
        if (i + 2 < 8) {
            MG_LOAD(i + 2, (i + 2) % 3);
            asm volatile("cp.async.wait_group 2;");
        } else if (i + 1 < 8) {
            asm volatile("cp.async.wait_group 1;");
        } else {
            asm volatile("cp.async.wait_group 0;");
        }
        __syncthreads();

        u32 Abase = sptr(dsm + (i % 3) * MG3_STAGE) + wm * 64 * 72 * 2 + a_lane_off;
        u32 Bbase = sptr(dsm + (i % 3) * MG3_STAGE + MG3_A) + wn * 32 * 2 + b_lane_off;

        u32 bfrag[2][2][4];
        u32 afrag[2][4][4];

#pragma unroll
        for (int nh = 0; nh < 2; nh++)
            ldm_x4_t(bfrag[0][nh], Bbase + nh * 16 * 2);
#pragma unroll
        for (int mf = 0; mf < 4; mf++)
            ldm_x4(afrag[0][mf], Abase + mf * 16 * 72 * 2);

#pragma unroll
        for (int ks = 0; ks < 4; ks++) {
            int cur = ks & 1, nxt = cur ^ 1;
            if (ks < 3) {
                u32 kb = (u32)((ks + 1) * 16 * 2);
#pragma unroll
                for (int nh = 0; nh < 2; nh++)
                    ldm_x4_t(bfrag[nxt][nh], Bbase + kb * 136 + nh * 16 * 2);
#pragma unroll
                for (int mf = 0; mf < 4; mf++)
                    ldm_x4(afrag[nxt][mf], Abase + mf * 16 * 72 * 2 + kb);
            }
#pragma unroll
            for (int mf = 0; mf < 4; mf++)
#pragma unroll
                for (int nf = 0; nf < 4; nf++) {
                    u32 b0 = bfrag[cur][nf >> 1][(nf & 1) * 2];
                    u32 b1 = bfrag[cur][nf >> 1][(nf & 1) * 2 + 1];
                    mma16816h(acc[mf][nf], afrag[cur][mf], b0, b1);
                }
        }
        __syncthreads();
    }

    int g = lane >> 2, tg = lane & 3;
#pragma unroll
    for (int mf = 0; mf < 4; mf++) {
        int m1 = m0 + wm * 64 + mf * 16 + g;
#pragma unroll
        for (int nf = 0; nf < 4; nf++) {
            int p = p0 + wn * 32 + nf * 8 + tg * 2;
            float bs1 = bm[m1], bs2 = bm[m1 + 8];
            *(float2*)(out + ((size_t)b * C + m1) * P + p) =
                make_float2(acc[mf][nf][0] + bs1, acc[mf][nf][1] + bs1);
            *(float2*)(out + ((size_t)b * C + m1 + 8) * P + p) =
                make_float2(acc[mf][nf][2] + bs2, acc[mf][nf][3] + bs2);
        }
    }
}

// ============================================================
extern "C" void kernel_launch(void* const* d_in, const int* in_sizes, int n_in,
                              void* d_out, int out_size) {
    const float* x       = (const float*)d_in[0];
    const float* w_red   = (const float*)d_in[1];
    const float* b_red   = (const float*)d_in[2];
    const float* w_u     = (const float*)d_in[3];
    const float* b_u     = (const float*)d_in[4];
    const float* w_lam   = (const float*)d_in[5];
    const float* b_lam   = (const float*)d_in[6];
    const float* w_wt    = (const float*)d_in[7];
    const float* b_wt    = (const float*)d_in[8];
    const float* w_merge = (const float*)d_in[9];
    const float* b_merge = (const float*)d_in[10];
    float* out = (float*)d_out;

    cudaFuncSetAttribute(k_rul,
                         cudaFuncAttributeMaxDynamicSharedMemorySize, RU_SMEM);
    cudaFuncSetAttribute(k_merge_mma,
                         cudaFuncAttributeMaxDynamicSharedMemorySize, MG3_SMEM);

    k_prep<<<704, 256>>>(w_merge, w_u, w_lam, w_red);
    k_rul<<<dim3(32, NB), 256, RU_SMEM>>>(x, b_red, w_wt, b_wt, b_u, b_lam);
    k_scan<<<dim3(256, NB), 512>>>(x);
    k_merge_mma<<<dim3(32, 2, NB), 256, MG3_SMEM>>>(out, b_merge);
}